// round 7
// baseline (speedup 1.0000x reference)
#include <cuda_runtime.h>
#include <cuda_bf16.h>
#include <math.h>

#define BATCH 8
#define DD 24
#define HH 64
#define WW 128
#define HW (HH*WW)

typedef unsigned long long u64;
typedef unsigned int u32;

// ---------------- packed fp32x2 helpers ----------------
__device__ __forceinline__ u64 pk(float lo, float hi) {
    u64 r; asm("mov.b64 %0, {%1,%2};" : "=l"(r) : "f"(lo), "f"(hi)); return r;
}
__device__ __forceinline__ u64 pk1(float v) { return pk(v, v); }
__device__ __forceinline__ void fma2(u64& d, u64 a, u64 b) {
    asm("fma.rn.f32x2 %0, %1, %2, %0;" : "+l"(d) : "l"(a), "l"(b));
}
__device__ __forceinline__ float2 unpk(u64 v) {
    float2 f; asm("mov.b64 {%0,%1}, %2;" : "=f"(f.x), "=f"(f.y) : "l"(v)); return f;
}

// ---------------- mma / ldmatrix helpers ----------------
__device__ __forceinline__ u32 smem_u32(const void* p) {
    u32 a; asm("{ .reg .u64 t; cvta.to.shared.u64 t, %1; cvt.u32.u64 %0, t; }" : "=r"(a) : "l"(p));
    return a;
}
__device__ __forceinline__ void ldsm4(u32 a, u32& r0, u32& r1, u32& r2, u32& r3) {
    asm volatile("ldmatrix.sync.aligned.m8n8.x4.shared.b16 {%0,%1,%2,%3}, [%4];"
                 : "=r"(r0), "=r"(r1), "=r"(r2), "=r"(r3) : "r"(a));
}
__device__ __forceinline__ void mma16816(float* d, u32 a0, u32 a1, u32 a2, u32 a3, u32 b0, u32 b1) {
    asm volatile("mma.sync.aligned.m16n8k16.row.col.f32.bf16.bf16.f32 "
                 "{%0,%1,%2,%3}, {%4,%5,%6,%7}, {%8,%9}, {%0,%1,%2,%3};"
                 : "+f"(d[0]), "+f"(d[1]), "+f"(d[2]), "+f"(d[3])
                 : "r"(a0), "r"(a1), "r"(a2), "r"(a3), "r"(b0), "r"(b1));
}
__device__ __forceinline__ void cp16(u32 dst, const void* src) {
    asm volatile("cp.async.ca.shared.global [%0], [%1], 16;" :: "r"(dst), "l"(src));
}

// ---------------- scratch ----------------
__device__ float g_cv[BATCH*8*DD*HH*WW];
__device__ float g_x1[BATCH*16*DD*HH*WW];
__device__ __align__(16) char g_x1p[(size_t)BATCH*DD*HH*WW*64];  // packed bf16 hi/lo, 64B per voxel
__device__ float g_x2[BATCH*16*DD*HH*WW];
__device__ float g_x2n[BATCH*16*DD*HH*WW];
__device__ float g_logits[BATCH*DD*HH*WW];
__device__ float g_feat[BATCH*16*HH*WW];
__device__ double g_stats[3*BATCH*8*2];
__device__ __align__(16) float g_zerobuf[4];   // zero-initialized

__global__ void k_zero_stats() {
    int i = threadIdx.x;
    if (i < 3*BATCH*8*2) g_stats[i] = 0.0;
}

// ---------------- cost volume (proven) ----------------
__global__ void __launch_bounds__(128) k_costvol(const float* __restrict__ fL,
                                                 const float* __restrict__ fR) {
    __shared__ float sR[16*128];
    int x = blockIdx.x;
    int h = x & 63, g = (x >> 6) & 7, b = x >> 9;
    int tid = threadIdx.x;
    const float* baseL = fL + (((size_t)(b*128 + g*16))*HH + h)*WW;
    const float* baseR = fR + (((size_t)(b*128 + g*16))*HH + h)*WW;
    float l[16];
#pragma unroll
    for (int c = 0; c < 16; c++) {
        l[c] = baseL[(size_t)c*HW + tid];
        sR[c*128 + tid] = baseR[(size_t)c*HW + tid];
    }
    __syncthreads();
    float* ov = g_cv + (((size_t)(b*8 + g)*DD)*HH + h)*WW + tid;
    for (int d = 0; d < DD; d++) {
        float s = 0.f;
        if (tid >= d) {
#pragma unroll
            for (int c = 0; c < 16; c++) s += l[c] * sR[c*128 + tid - d];
            s *= 0.0625f;
        }
        ov[(size_t)d*HW] = s;
    }
}

// ================= tensor-core conv3d, pipelined =================
// grid = B*32*4 (b, h-pair, d-sixth), block = 512 (16 warps)
// warp: hl = wrp>>3, wq = wrp&7 -> 16-pixel tile at w0=wq*16
#define PLANE_B (520*64)
#define W_OFF   (4*PLANE_B)
#define BOUNCE_OFF (W_OFF + 27648)
#define CONV_SMEM (BOUNCE_OFF + 16640)

template<int CIN>
__global__ void __launch_bounds__(512) k_conv_tc(const float* __restrict__ wts) {
    float* out = (CIN == 8) ? g_x1 : g_x2;
    double* stats = g_stats + ((CIN == 8) ? 0 : 1)*128;

    extern __shared__ char smem[];
    __nv_bfloat16* w_sm = (__nv_bfloat16*)(smem + W_OFF);
    float* bounce = (float*)(smem + BOUNCE_OFF);
    __shared__ float sred[16];

    u32 a_base = smem_u32(smem);
    u32 w_base = smem_u32(w_sm);
    int tid = threadIdx.x, lane = tid & 31, wrp = tid >> 5;
    int hl = wrp >> 3, wq = wrp & 7, w0 = wq*16;
    if (tid < 16) sred[tid] = 0.f;

    int x = blockIdx.x;
    int dq = x & 3, hp = (x >> 2) & 31, b = x >> 7;
    int d0 = dq*6, h0 = hp*2;

    // zero all 4 plane slots (halo cols; conv1 upper-channel chunks stay zero)
    for (int i = tid; i < 4*PLANE_B/4; i += 512) ((u32*)smem)[i] = 0u;

    // weights: [split][tap][oc16][ic16] bf16
    for (int i = tid; i < 27*256; i += 512) {
        int ic = i & 15, oc = (i >> 4) & 15, tap = i >> 8;
        float v = (ic < CIN) ? wts[(oc*CIN + ic)*27 + tap] : 0.f;
        __nv_bfloat16 hi = __float2bfloat16(v);
        __nv_bfloat16 lo = __float2bfloat16(v - __bfloat162float(hi));
        w_sm[i] = hi; w_sm[27*256 + i] = lo;
    }
    __syncthreads();

    auto stage = [&](int zd) {
        int slot = (zd - d0 + 1) & 3;
        bool pv = ((unsigned)zd < 24u);
        if (CIN == 8) {
            char* pl = smem + slot*PLANE_B;
            for (int it = tid; it < 4096; it += 512) {
                int w = it & 127, c = (it >> 7) & 7, zhl = it >> 10;
                int zh = h0 - 1 + zhl;
                float v = 0.f;
                if (pv && (unsigned)zh < 64u)
                    v = g_cv[(((size_t)(b*8 + c)*DD + zd)*HH + zh)*WW + w];
                __nv_bfloat16 hi = __float2bfloat16(v);
                __nv_bfloat16 lo = __float2bfloat16(v - __bfloat162float(hi));
                int r = zhl*130 + w + 1;
                char* rowb = pl + r*64;
                *(__nv_bfloat16*)(rowb + (((r & 3))*16) + c*2) = hi;       // chunk 0 ^ (r&3)
                *(__nv_bfloat16*)(rowb + ((2 ^ (r & 3))*16) + c*2) = lo;   // chunk 2 ^ (r&3)
            }
        } else {
            for (int it = tid; it < 2048; it += 512) {
                int ch = it & 3, w = (it >> 2) & 127, zhl = it >> 9;
                int zh = h0 - 1 + zhl;
                int r = zhl*130 + w + 1;
                u32 dst = a_base + slot*PLANE_B + (u32)r*64 + ((ch ^ (r & 3))*16);
                const void* src = (pv && (unsigned)zh < 64u)
                    ? (const void*)(g_x1p + ((((size_t)(b*24 + zd)*64 + zh)*128 + w)*64 + ch*16))
                    : (const void*)g_zerobuf;
                cp16(dst, src);
            }
        }
        asm volatile("cp.async.commit_group;" ::: "memory");
    };

    stage(d0 - 1); stage(d0); stage(d0 + 1);

    float gsum[2] = {0.f, 0.f}, gss[2] = {0.f, 0.f};

    for (int dl = 0; dl < 6; dl++) {
        int d = d0 + dl;
        stage(d + 2);                                        // prefetch, overlaps
        asm volatile("cp.async.wait_group 1;" ::: "memory"); // planes d-1..d+1 ready
        __syncthreads();

        float acc[2][4];
#pragma unroll
        for (int oh = 0; oh < 2; oh++)
#pragma unroll
            for (int r = 0; r < 4; r++) acc[oh][r] = 0.f;

#pragma unroll
        for (int kd = 0; kd < 3; kd++) {
            u32 pbase = a_base + (u32)((dl + kd) & 3)*PLANE_B;
#pragma unroll
            for (int kh = 0; kh < 3; kh++) {
                int zhl = hl + kh;
                u32 bfr[3][2][4];
#pragma unroll
                for (int kw = 0; kw < 3; kw++) {
                    int tap = (kd*3 + kh)*3 + kw;
                    int m = lane >> 3;
#pragma unroll
                    for (int sp = 0; sp < 2; sp++) {
                        u32 ba = w_base + (u32)((sp*27 + tap)*256
                                  + ((m >> 1)*8 + (lane & 7))*16 + (m & 1)*8)*2;
                        ldsm4(ba, bfr[kw][sp][0], bfr[kw][sp][1], bfr[kw][sp][2], bfr[kw][sp][3]);
                    }
                }
#pragma unroll
                for (int kw = 0; kw < 3; kw++) {
                    int r = zhl*130 + w0 + kw + (lane & 15);
                    u32 ah = pbase + (u32)r*64 + (((lane >> 4) ^ (r & 3))*16);
                    u32 al = pbase + (u32)r*64 + ((((lane >> 4) | 2) ^ (r & 3))*16);
                    u32 h0r, h1r, h2r, h3r, l0r, l1r, l2r, l3r;
                    ldsm4(ah, h0r, h1r, h2r, h3r);
                    ldsm4(al, l0r, l1r, l2r, l3r);
#pragma unroll
                    for (int oh = 0; oh < 2; oh++) {
                        mma16816(acc[oh], h0r, h1r, h2r, h3r, bfr[kw][0][oh*2], bfr[kw][0][oh*2+1]);
                        mma16816(acc[oh], h0r, h1r, h2r, h3r, bfr[kw][1][oh*2], bfr[kw][1][oh*2+1]);
                        mma16816(acc[oh], l0r, l1r, l2r, l3r, bfr[kw][0][oh*2], bfr[kw][0][oh*2+1]);
                    }
                }
            }
        }

        // stats
#pragma unroll
        for (int oh = 0; oh < 2; oh++) {
            float s = 0.f, s2 = 0.f;
#pragma unroll
            for (int r = 0; r < 4; r++) { float v = acc[oh][r]; s += v; s2 += v*v; }
            gsum[oh] += s; gss[oh] += s2;
        }

        // bounce (dedicated buffer) + coalesced store
#pragma unroll
        for (int oh = 0; oh < 2; oh++)
#pragma unroll
            for (int r = 0; r < 4; r++) {
                int oc = oh*8 + (lane & 3)*2 + (r & 1);
                int px = w0 + (lane >> 2) + (r >> 1)*8;
                bounce[oc*260 + hl*128 + px] = acc[oh][r];
            }
        __syncthreads();
        float* ob = out + ((size_t)b*16*DD + d)*HW;
        for (int i = tid; i < 1024; i += 512) {
            int oc = i >> 6, rem = i & 63;
            int h2 = rem >> 5, w4 = rem & 31;
            float4 v = *(float4*)&bounce[oc*260 + h2*128 + w4*4];
            *(float4*)&ob[(size_t)oc*DD*HW + (h0 + h2)*WW + w4*4] = v;
        }
    }

    int g0 = lane & 3;
    atomicAdd(&sred[g0*2],         gsum[0]); atomicAdd(&sred[g0*2 + 1],         gss[0]);
    atomicAdd(&sred[(4 + g0)*2],   gsum[1]); atomicAdd(&sred[(4 + g0)*2 + 1],   gss[1]);
    __syncthreads();
    if (tid < 16) atomicAdd(&stats[b*16 + tid], (double)sred[tid]);
}

// ---------------- GN1 finalize + SiLU -> packed bf16 hi/lo channels-last ----------------
// grid = B*24*64 (b,d,h), block 256
__global__ void __launch_bounds__(256) k_norm_pack(const float* __restrict__ gw,
                                                   const float* __restrict__ gb) {
    __shared__ float sA[16], sB[16];
    __shared__ __align__(16) char sbuf[128*64];
    int x = blockIdx.x;
    int h = x & 63, d = (x >> 6) % 24, b = x / 1536;
    int tid = threadIdx.x;
    if (tid < 16) {
        const double* p = g_stats + ((size_t)b*8 + (tid >> 1))*2;
        double mu = p[0] / 393216.0;
        double var = p[1] / 393216.0 - mu*mu;
        float rstd = rsqrtf((float)var + 1e-5f);
        float A = rstd * gw[tid];
        sA[tid] = A; sB[tid] = gb[tid] - (float)mu*A;
    }
    __syncthreads();
    for (int i = tid; i < 512; i += 256) {
        int c = i >> 5, w4 = i & 31;
        float4 v = *(const float4*)&g_x1[(((size_t)(b*16 + c)*24 + d)*64 + h)*128 + w4*4];
        float A = sA[c], Bv = sB[c];
        float vv[4] = {v.x, v.y, v.z, v.w};
#pragma unroll
        for (int j = 0; j < 4; j++) {
            float t = vv[j]*A + Bv;
            t = t / (1.f + __expf(-t));
            __nv_bfloat16 hi = __float2bfloat16(t);
            __nv_bfloat16 lo = __float2bfloat16(t - __bfloat162float(hi));
            int w = w4*4 + j;
            *(__nv_bfloat16*)(sbuf + w*64 + (c >> 3)*16 + (c & 7)*2) = hi;
            *(__nv_bfloat16*)(sbuf + w*64 + 32 + (c >> 3)*16 + (c & 7)*2) = lo;
        }
    }
    __syncthreads();
    float4* outp = (float4*)(g_x1p + (((size_t)(b*24 + d)*64 + h)*128)*64);
    for (int i = tid; i < 512; i += 256) outp[i] = ((float4*)sbuf)[i];
}

// ---------------- GN finalize + apply + SiLU (layers 1,2) ----------------
__global__ void __launch_bounds__(256) k_norm(int which, float* outext,
                                              const float* __restrict__ gw,
                                              const float* __restrict__ gb,
                                              int nslab, float invN) {
    const float* in = (which == 1) ? g_x2 : g_feat;
    float* out = (which == 2) ? outext : g_x2n;
    const double* st = g_stats + which*128;
    __shared__ float sA, sB;
    int x = blockIdx.x;
    int s = x % nslab, c = (x / nslab) & 15, b = x / (nslab*16);
    if (threadIdx.x == 0) {
        const double* p = st + ((size_t)b*8 + (c >> 1))*2;
        double mu = p[0] * (double)invN;
        double var = p[1] * (double)invN - mu*mu;
        float rstd = rsqrtf((float)var + 1e-5f);
        float A = rstd * gw[c];
        sA = A; sB = gb[c] - (float)mu * A;
    }
    __syncthreads();
    float A = sA, Bv = sB;
    size_t base = ((size_t)(b*16 + c)*nslab + s)*8192;
    const float4* ip = (const float4*)(in + base);
    float4* op = (float4*)(out + base);
    for (int i = threadIdx.x; i < 2048; i += 256) {
        float4 v = ip[i];
        v.x = v.x*A + Bv; v.y = v.y*A + Bv; v.z = v.z*A + Bv; v.w = v.w*A + Bv;
        v.x = v.x / (1.f + __expf(-v.x));
        v.y = v.y / (1.f + __expf(-v.y));
        v.z = v.z / (1.f + __expf(-v.z));
        v.w = v.w / (1.f + __expf(-v.w));
        op[i] = v;
    }
}

// ---------------- conv3d oc=1 (FMA2, proven) ----------------
__global__ void __launch_bounds__(128) k_conv3d_oc1(const float* __restrict__ wts,
                                                    const float* __restrict__ bias) {
    __shared__ u64 swt[432];
    int tid = threadIdx.x;
    for (int i = tid; i < 432; i += 128) swt[i] = pk1(wts[i]);
    __syncthreads();
    int x = blockIdx.x;
    int ht = x & 7, d = (x >> 3) % 24, b = x / 192;
    int wt = tid & 15, hr = tid >> 4;
    int w0 = wt << 3, h = ht*8 + hr;
    u64 acc[4];
#pragma unroll
    for (int t = 0; t < 4; t++) acc[t] = 0ull;
    const float* inb = g_x2n + (size_t)b*16*DD*HW;
    for (int ic = 0; ic < 16; ic++) {
        const float* inc = inb + (size_t)ic*DD*HW;
#pragma unroll
        for (int kd = 0; kd < 3; kd++) {
            int zd = d + kd - 1;
            if ((unsigned)zd >= (unsigned)DD) continue;
#pragma unroll
            for (int kh = 0; kh < 3; kh++) {
                int zh = h + kh - 1;
                if ((unsigned)zh >= (unsigned)HH) continue;
                const float* row = inc + ((size_t)zd*HH + zh)*WW + w0;
                float r0 = (w0 == 0) ? 0.f : __ldg(row - 1);
                float4 va = *(const float4*)row;
                float4 vb = *(const float4*)(row + 4);
                float r9 = (w0 == 120) ? 0.f : __ldg(row + 8);
                u64 pe[5], po[4];
                pe[0] = pk(r0, va.x);  pe[1] = pk(va.y, va.z);
                pe[2] = pk(va.w, vb.x); pe[3] = pk(vb.y, vb.z);
                pe[4] = pk(vb.w, r9);
                po[0] = pk(va.x, va.y); po[1] = pk(va.z, va.w);
                po[2] = pk(vb.x, vb.y); po[3] = pk(vb.z, vb.w);
                int tb = (kd*3 + kh)*3;
                u64 wv0 = swt[ic*27 + tb + 0];
                u64 wv1 = swt[ic*27 + tb + 1];
                u64 wv2 = swt[ic*27 + tb + 2];
#pragma unroll
                for (int t = 0; t < 4; t++) {
                    fma2(acc[t], wv0, pe[t]);
                    fma2(acc[t], wv1, po[t]);
                    fma2(acc[t], wv2, pe[t + 1]);
                }
            }
        }
    }
    float bs = bias[0];
    float o[8];
#pragma unroll
    for (int t = 0; t < 4; t++) { float2 f = unpk(acc[t]); o[2*t] = f.x + bs; o[2*t+1] = f.y + bs; }
    float* orow = g_logits + (((size_t)b*DD + d)*HH + h)*WW + w0;
    *(float4*)orow       = make_float4(o[0], o[1], o[2], o[3]);
    *(float4*)(orow + 4) = make_float4(o[4], o[5], o[6], o[7]);
}

// ---------------- softmax (proven) ----------------
__global__ void __launch_bounds__(128) k_softmax(float* __restrict__ out) {
    int x = blockIdx.x;
    int h = x & 63, b = x >> 6;
    int w = threadIdx.x;
    const float* lp = g_logits + ((size_t)b*DD*HH + h)*WW + w;
    float l[DD];
    float m = -1e30f;
#pragma unroll
    for (int d = 0; d < DD; d++) { l[d] = lp[(size_t)d*HW]; m = fmaxf(m, l[d]); }
    float S = 0.f, E = 0.f;
#pragma unroll
    for (int d = 0; d < DD; d++) {
        float e = __expf(l[d] - m);
        S += e; E += e * (float)d;
    }
    float inv = 1.f / S;
    int oi = (b*HH + h)*WW + w;
    out[oi]           = E * inv;
    out[65536 + oi]   = 0.f;
    out[131072 + oi]  = 0.f;
    out[1245184 + oi] = inv;
}

// ---------------- feature head conv2d (FMA2, proven) ----------------
__global__ void __launch_bounds__(128, 3) k_conv2d_feat(const float* __restrict__ fL,
                                                        const float* __restrict__ wts) {
    __shared__ __align__(16) u64 swt[32*9*16];
    __shared__ float sred[16];
    int tid = threadIdx.x;
    if (tid < 16) sred[tid] = 0.f;
    int x = blockIdx.x;
    int wtile = x & 1, ht = (x >> 1) & 15, b = x >> 5;
    int wt = tid & 7, os = (tid >> 3) & 3, hr = tid >> 5;
    int w0 = wtile*64 + wt*8, h = ht*4 + hr, oc0 = os*4;
    u64 acc[4][4];
#pragma unroll
    for (int o = 0; o < 4; o++)
#pragma unroll
        for (int t = 0; t < 4; t++) acc[o][t] = 0ull;
    for (int p = 0; p < 4; p++) {
        __syncthreads();
        for (int i = tid; i < 32*144; i += 128) {
            int icl = i / 144; int r = i - icl*144; int tap = r >> 4; int oc = r & 15;
            swt[i] = pk1(wts[((size_t)oc*128 + p*32 + icl)*9 + tap]);
        }
        __syncthreads();
        for (int icl = 0; icl < 32; icl++) {
            int ic = p*32 + icl;
            const float* rowb = fL + ((size_t)(b*128 + ic)*HH)*WW;
#pragma unroll
            for (int kh = 0; kh < 3; kh++) {
                int zh = h + kh - 1;
                if ((unsigned)zh >= (unsigned)HH) continue;
                const float* row = rowb + (size_t)zh*WW + w0;
                float r0 = (w0 == 0) ? 0.f : __ldg(row - 1);
                float4 va = *(const float4*)row;
                float4 vb = *(const float4*)(row + 4);
                float r9 = (w0 == 120) ? 0.f : __ldg(row + 8);
                u64 pe[5], po[4];
                pe[0] = pk(r0, va.x);  pe[1] = pk(va.y, va.z);
                pe[2] = pk(va.w, vb.x); pe[3] = pk(vb.y, vb.z);
                pe[4] = pk(vb.w, r9);
                po[0] = pk(va.x, va.y); po[1] = pk(va.z, va.w);
                po[2] = pk(vb.x, vb.y); po[3] = pk(vb.z, vb.w);
                const u64* wbase = swt + (icl*9 + kh*3)*16 + oc0;
#pragma unroll
                for (int o = 0; o < 4; o++) {
                    u64 wv0 = wbase[o];
                    fma2(acc[o][0], wv0, pe[0]); fma2(acc[o][1], wv0, pe[1]);
                    fma2(acc[o][2], wv0, pe[2]); fma2(acc[o][3], wv0, pe[3]);
                }
#pragma unroll
                for (int o = 0; o < 4; o++) {
                    u64 wv1 = wbase[16 + o];
                    fma2(acc[o][0], wv1, po[0]); fma2(acc[o][1], wv1, po[1]);
                    fma2(acc[o][2], wv1, po[2]); fma2(acc[o][3], wv1, po[3]);
                }
#pragma unroll
                for (int o = 0; o < 4; o++) {
                    u64 wv2 = wbase[32 + o];
                    fma2(acc[o][0], wv2, pe[1]); fma2(acc[o][1], wv2, pe[2]);
                    fma2(acc[o][2], wv2, pe[3]); fma2(acc[o][3], wv2, pe[4]);
                }
            }
        }
    }
    float gs[2], gs2[2];
    gs[0] = gs[1] = gs2[0] = gs2[1] = 0.f;
#pragma unroll
    for (int o = 0; o < 4; o++) {
        float v[8];
#pragma unroll
        for (int t = 0; t < 4; t++) { float2 f = unpk(acc[o][t]); v[2*t] = f.x; v[2*t+1] = f.y; }
        int oc = oc0 + o;
        float* orow = g_feat + (((size_t)b*16 + oc)*HH + h)*WW + w0;
        *(float4*)orow       = make_float4(v[0], v[1], v[2], v[3]);
        *(float4*)(orow + 4) = make_float4(v[4], v[5], v[6], v[7]);
        float s = 0.f, s2 = 0.f;
#pragma unroll
        for (int j = 0; j < 8; j++) { s += v[j]; s2 += v[j]*v[j]; }
        gs[o >> 1] += s; gs2[o >> 1] += s2;
    }
#pragma unroll
    for (int i = 0; i < 2; i++) {
        int grp = os*2 + i;
        atomicAdd(&sred[grp*2],     gs[i]);
        atomicAdd(&sred[grp*2 + 1], gs2[i]);
    }
    __syncthreads();
    if (tid < 16) atomicAdd(&g_stats[2*128 + b*16 + tid], (double)sred[tid]);
}

// ---------------- launch ----------------
extern "C" void kernel_launch(void* const* d_in, const int* in_sizes, int n_in,
                              void* d_out, int out_size) {
    const float* fL    = (const float*)d_in[0];
    const float* fR    = (const float*)d_in[1];
    const float* w1    = (const float*)d_in[2];
    const float* gn1w  = (const float*)d_in[3];
    const float* gn1b  = (const float*)d_in[4];
    const float* w2    = (const float*)d_in[5];
    const float* gn2w  = (const float*)d_in[6];
    const float* gn2b  = (const float*)d_in[7];
    const float* w3    = (const float*)d_in[8];
    const float* b3    = (const float*)d_in[9];
    const float* fhw   = (const float*)d_in[10];
    const float* fhgnw = (const float*)d_in[11];
    const float* fhgnb = (const float*)d_in[12];
    float* out = (float*)d_out;

    const float invN3d = 1.0f / (2.0f*DD*HH*WW);
    const float invN2d = 1.0f / (2.0f*HH*WW);

    cudaFuncSetAttribute(k_conv_tc<8>,  cudaFuncAttributeMaxDynamicSharedMemorySize, CONV_SMEM);
    cudaFuncSetAttribute(k_conv_tc<16>, cudaFuncAttributeMaxDynamicSharedMemorySize, CONV_SMEM);

    k_zero_stats<<<1, 384>>>();                                  // 0
    k_costvol<<<BATCH*8*HH, 128>>>(fL, fR);                      // 1
    k_conv_tc<8><<<1024, 512, CONV_SMEM>>>(w1);                  // 2
    k_norm_pack<<<BATCH*24*64, 256>>>(gn1w, gn1b);               // 3
    k_zero_stats<<<1, 384>>>();                                  // 4 (dummy: aligns ncu onto conv2)
    k_conv_tc<16><<<1024, 512, CONV_SMEM>>>(w2);                 // 5 <-- ncu -s 5
    k_norm<<<BATCH*16*24, 256>>>(1, nullptr, gn2w, gn2b, 24, invN3d);  // 6
    k_conv3d_oc1<<<BATCH*24*8, 128>>>(w3, b3);                   // 7
    k_softmax<<<BATCH*HH, 128>>>(out);                           // 8
    k_conv2d_feat<<<BATCH*16*2, 128>>>(fL, fhw);                 // 9
    k_norm<<<BATCH*16, 256>>>(2, out + 196608, fhgnw, fhgnb, 1, invN2d); // 10
}

// round 8
// speedup vs baseline: 1.2529x; 1.2529x over previous
#include <cuda_runtime.h>
#include <cuda_bf16.h>
#include <math.h>

#define BATCH 8
#define DD 24
#define HH 64
#define WW 128
#define HW (HH*WW)

typedef unsigned long long u64;
typedef unsigned int u32;
typedef unsigned short u16;

// ---------------- packed fp32x2 helpers ----------------
__device__ __forceinline__ u64 pk(float lo, float hi) {
    u64 r; asm("mov.b64 %0, {%1,%2};" : "=l"(r) : "f"(lo), "f"(hi)); return r;
}
__device__ __forceinline__ u64 pk1(float v) { return pk(v, v); }
__device__ __forceinline__ void fma2(u64& d, u64 a, u64 b) {
    asm("fma.rn.f32x2 %0, %1, %2, %0;" : "+l"(d) : "l"(a), "l"(b));
}
__device__ __forceinline__ float2 unpk(u64 v) {
    float2 f; asm("mov.b64 {%0,%1}, %2;" : "=f"(f.x), "=f"(f.y) : "l"(v)); return f;
}

// ---------------- mma / ldmatrix helpers ----------------
__device__ __forceinline__ u32 smem_u32(const void* p) {
    u32 a; asm("{ .reg .u64 t; cvta.to.shared.u64 t, %1; cvt.u32.u64 %0, t; }" : "=r"(a) : "l"(p));
    return a;
}
__device__ __forceinline__ void ldsm4(u32 a, u32& r0, u32& r1, u32& r2, u32& r3) {
    asm volatile("ldmatrix.sync.aligned.m8n8.x4.shared.b16 {%0,%1,%2,%3}, [%4];"
                 : "=r"(r0), "=r"(r1), "=r"(r2), "=r"(r3) : "r"(a));
}
__device__ __forceinline__ void mma16816(float* d, u32 a0, u32 a1, u32 a2, u32 a3, u32 b0, u32 b1) {
    asm volatile("mma.sync.aligned.m16n8k16.row.col.f32.bf16.bf16.f32 "
                 "{%0,%1,%2,%3}, {%4,%5,%6,%7}, {%8,%9}, {%0,%1,%2,%3};"
                 : "+f"(d[0]), "+f"(d[1]), "+f"(d[2]), "+f"(d[3])
                 : "r"(a0), "r"(a1), "r"(a2), "r"(a3), "r"(b0), "r"(b1));
}
__device__ __forceinline__ void cp16(u32 dst, const void* src) {
    asm volatile("cp.async.ca.shared.global [%0], [%1], 16;" :: "r"(dst), "l"(src));
}
__device__ __forceinline__ u16 bfb(float f) {
    return __bfloat16_as_ushort(__float2bfloat16(f));
}

// ---------------- scratch ----------------
__device__ float g_cv[BATCH*8*DD*HH*WW];
__device__ float g_x1[BATCH*16*DD*HH*WW];
__device__ __align__(16) char g_x1p[(size_t)BATCH*DD*HH*WW*64];  // packed bf16 hi/lo, 64B/voxel
__device__ float g_x2[BATCH*16*DD*HH*WW];
__device__ float g_x2n[BATCH*16*DD*HH*WW];
__device__ float g_logits[BATCH*DD*HH*WW];
__device__ float g_feat[BATCH*16*HH*WW];
__device__ double g_stats[3*BATCH*8*2];
__device__ __align__(16) float g_zerobuf[4];   // zero-initialized

__global__ void k_zero_stats() {
    int i = threadIdx.x;
    if (i < 3*BATCH*8*2) g_stats[i] = 0.0;
}

// ---------------- cost volume (proven) ----------------
__global__ void __launch_bounds__(128) k_costvol(const float* __restrict__ fL,
                                                 const float* __restrict__ fR) {
    __shared__ float sR[16*128];
    int x = blockIdx.x;
    int h = x & 63, g = (x >> 6) & 7, b = x >> 9;
    int tid = threadIdx.x;
    const float* baseL = fL + (((size_t)(b*128 + g*16))*HH + h)*WW;
    const float* baseR = fR + (((size_t)(b*128 + g*16))*HH + h)*WW;
    float l[16];
#pragma unroll
    for (int c = 0; c < 16; c++) {
        l[c] = baseL[(size_t)c*HW + tid];
        sR[c*128 + tid] = baseR[(size_t)c*HW + tid];
    }
    __syncthreads();
    float* ov = g_cv + (((size_t)(b*8 + g)*DD)*HH + h)*WW + tid;
    for (int d = 0; d < DD; d++) {
        float s = 0.f;
        if (tid >= d) {
#pragma unroll
            for (int c = 0; c < 16; c++) s += l[c] * sR[c*128 + tid - d];
            s *= 0.0625f;
        }
        ov[(size_t)d*HW] = s;
    }
}

// ================= tensor-core conv3d, pipelined, conflict-free 80B rows =========
// grid = B*32*4 (b, h-pair, d-sixth), block = 512 (16 warps)
#define ROW_B   80
#define PLANE_B (520*ROW_B)
#define W_OFF   (4*PLANE_B)
#define BOUNCE_OFF (W_OFF + 27648)
#define CONV_SMEM (BOUNCE_OFF + 16640)

template<int CIN>
__global__ void __launch_bounds__(512) k_conv_tc(const float* __restrict__ wts) {
    float* out = (CIN == 8) ? g_x1 : g_x2;
    double* stats = g_stats + ((CIN == 8) ? 0 : 1)*128;

    extern __shared__ char smem[];
    __nv_bfloat16* w_sm = (__nv_bfloat16*)(smem + W_OFF);
    float* bounce = (float*)(smem + BOUNCE_OFF);
    __shared__ float sred[16];

    u32 a_base = smem_u32(smem);
    u32 w_base = smem_u32(w_sm);
    int tid = threadIdx.x, lane = tid & 31, wrp = tid >> 5;
    int hl = wrp >> 3, wq = wrp & 7, w0 = wq*16;
    if (tid < 16) sred[tid] = 0.f;

    int x = blockIdx.x;
    int dq = x & 3, hp = (x >> 2) & 31, b = x >> 7;
    int d0 = dq*6, h0 = hp*2;

    // zero all 4 plane slots once (halo cols + conv1's zero channels 8-15)
    for (int i = tid; i < 4*PLANE_B/4; i += 512) ((u32*)smem)[i] = 0u;

    // weights: [split][tap][oc16][ic16] bf16
    for (int i = tid; i < 27*256; i += 512) {
        int ic = i & 15, oc = (i >> 4) & 15, tap = i >> 8;
        float v = (ic < CIN) ? wts[(oc*CIN + ic)*27 + tap] : 0.f;
        __nv_bfloat16 hi = __float2bfloat16(v);
        __nv_bfloat16 lo = __float2bfloat16(v - __bfloat162float(hi));
        w_sm[i] = hi; w_sm[27*256 + i] = lo;
    }
    __syncthreads();

    auto stage = [&](int zd) {
        int slot = (zd - d0 + 1) & 3;
        bool pv = ((unsigned)zd < 24u);
        if (CIN == 8) {
            char* pl = smem + slot*PLANE_B;
            // it -> cp (channel pair) in low bits: 32 lanes = 8 rows x 4 cp -> 32 distinct banks
            for (int it = tid; it < 2048; it += 512) {
                int cp = it & 3, w = (it >> 2) & 127, zhl = it >> 9;
                int zh = h0 - 1 + zhl;
                float v0 = 0.f, v1 = 0.f;
                if (pv && (unsigned)zh < 64u) {
                    const float* p = g_cv + (((size_t)(b*8 + 2*cp)*DD + zd)*HH + zh)*WW + w;
                    v0 = p[0]; v1 = p[(size_t)DD*HW];
                }
                u16 h0b = bfb(v0), h1b = bfb(v1);
                u16 l0b = bfb(v0 - __bfloat162float(__ushort_as_bfloat16(h0b)));
                u16 l1b = bfb(v1 - __bfloat162float(__ushort_as_bfloat16(h1b)));
                int r = zhl*130 + w + 1;
                char* rowb = pl + r*ROW_B;
                *(u32*)(rowb + cp*4)      = (u32)h0b | ((u32)h1b << 16);
                *(u32*)(rowb + 32 + cp*4) = (u32)l0b | ((u32)l1b << 16);
            }
        } else {
            for (int it = tid; it < 2048; it += 512) {
                int ch = it & 3, w = (it >> 2) & 127, zhl = it >> 9;
                int zh = h0 - 1 + zhl;
                int r = zhl*130 + w + 1;
                u32 dst = a_base + slot*PLANE_B + (u32)r*ROW_B + ch*16;
                const void* src = (pv && (unsigned)zh < 64u)
                    ? (const void*)(g_x1p + ((((size_t)(b*24 + zd)*64 + zh)*128 + w)*64 + ch*16))
                    : (const void*)g_zerobuf;
                cp16(dst, src);
            }
        }
        asm volatile("cp.async.commit_group;" ::: "memory");
    };

    stage(d0 - 1); stage(d0); stage(d0 + 1);

    float gsum[2] = {0.f, 0.f}, gss[2] = {0.f, 0.f};

    for (int dl = 0; dl < 6; dl++) {
        int d = d0 + dl;
        stage(d + 2);
        asm volatile("cp.async.wait_group 1;" ::: "memory");
        __syncthreads();

        float acc[2][4];
#pragma unroll
        for (int oh = 0; oh < 2; oh++)
#pragma unroll
            for (int r = 0; r < 4; r++) acc[oh][r] = 0.f;

#pragma unroll
        for (int kd = 0; kd < 3; kd++) {
            u32 pbase = a_base + (u32)((dl + kd) & 3)*PLANE_B;
#pragma unroll
            for (int kh = 0; kh < 3; kh++) {
                int zhl = hl + kh;
                u32 bfr[3][2][4];
#pragma unroll
                for (int kw = 0; kw < 3; kw++) {
                    int tap = (kd*3 + kh)*3 + kw;
                    int m = lane >> 3;
#pragma unroll
                    for (int sp = 0; sp < 2; sp++) {
                        u32 ba = w_base + (u32)((sp*27 + tap)*256
                                  + ((m >> 1)*8 + (lane & 7))*16 + (m & 1)*8)*2;
                        ldsm4(ba, bfr[kw][sp][0], bfr[kw][sp][1], bfr[kw][sp][2], bfr[kw][sp][3]);
                    }
                }
#pragma unroll
                for (int kw = 0; kw < 3; kw++) {
                    int r = zhl*130 + w0 + kw + (lane & 15);
                    u32 ah = pbase + (u32)r*ROW_B + (lane >> 4)*16;
                    u32 al = ah + 32;
                    u32 h0r, h1r, h2r, h3r, l0r, l1r, l2r, l3r;
                    ldsm4(ah, h0r, h1r, h2r, h3r);
                    ldsm4(al, l0r, l1r, l2r, l3r);
#pragma unroll
                    for (int oh = 0; oh < 2; oh++) {
                        mma16816(acc[oh], h0r, h1r, h2r, h3r, bfr[kw][0][oh*2], bfr[kw][0][oh*2+1]);
                        mma16816(acc[oh], h0r, h1r, h2r, h3r, bfr[kw][1][oh*2], bfr[kw][1][oh*2+1]);
                        mma16816(acc[oh], l0r, l1r, l2r, l3r, bfr[kw][0][oh*2], bfr[kw][0][oh*2+1]);
                    }
                }
            }
        }

#pragma unroll
        for (int oh = 0; oh < 2; oh++) {
            float s = 0.f, s2 = 0.f;
#pragma unroll
            for (int r = 0; r < 4; r++) { float v = acc[oh][r]; s += v; s2 += v*v; }
            gsum[oh] += s; gss[oh] += s2;
        }

#pragma unroll
        for (int oh = 0; oh < 2; oh++)
#pragma unroll
            for (int r = 0; r < 4; r++) {
                int oc = oh*8 + (lane & 3)*2 + (r & 1);
                int px = w0 + (lane >> 2) + (r >> 1)*8;
                bounce[oc*260 + hl*128 + px] = acc[oh][r];
            }
        __syncthreads();
        float* ob = out + ((size_t)b*16*DD + d)*HW;
        for (int i = tid; i < 1024; i += 512) {
            int oc = i >> 6, rem = i & 63;
            int h2 = rem >> 5, w4 = rem & 31;
            float4 v = *(float4*)&bounce[oc*260 + h2*128 + w4*4];
            *(float4*)&ob[(size_t)oc*DD*HW + (h0 + h2)*WW + w4*4] = v;
        }
    }

    int g0 = lane & 3;
    atomicAdd(&sred[g0*2],         gsum[0]); atomicAdd(&sred[g0*2 + 1],         gss[0]);
    atomicAdd(&sred[(4 + g0)*2],   gsum[1]); atomicAdd(&sred[(4 + g0)*2 + 1],   gss[1]);
    __syncthreads();
    if (tid < 16) atomicAdd(&stats[b*16 + tid], (double)sred[tid]);
}

// ---------------- GN1 finalize + SiLU -> packed, NO smem bounce ----------------
// grid = B*24*32, block 256; thread = one (h,w) pixel
__global__ void __launch_bounds__(256) k_norm_pack(const float* __restrict__ gw,
                                                   const float* __restrict__ gb) {
    __shared__ float sA[16], sB[16];
    int x = blockIdx.x;
    int hq = x & 31, d = (x >> 5) % 24, b = x / 768;
    int tid = threadIdx.x;
    if (tid < 16) {
        const double* p = g_stats + ((size_t)b*8 + (tid >> 1))*2;
        double mu = p[0] / 393216.0;
        double var = p[1] / 393216.0 - mu*mu;
        float rstd = rsqrtf((float)var + 1e-5f);
        float A = rstd * gw[tid];
        sA[tid] = A; sB[tid] = gb[tid] - (float)mu*A;
    }
    __syncthreads();
    int w = tid & 127, h = hq*2 + (tid >> 7);
    const float* base = g_x1 + ((size_t)b*16*DD + d)*HW + h*WW + w;
    u32 hiw[8], low[8];
#pragma unroll
    for (int j = 0; j < 8; j++) {
        float v0 = base[(size_t)(2*j)*DD*HW];
        float v1 = base[(size_t)(2*j + 1)*DD*HW];
        float t0 = v0*sA[2*j] + sB[2*j];
        float t1 = v1*sA[2*j + 1] + sB[2*j + 1];
        t0 = t0 / (1.f + __expf(-t0));
        t1 = t1 / (1.f + __expf(-t1));
        u16 h0b = bfb(t0), h1b = bfb(t1);
        u16 l0b = bfb(t0 - __bfloat162float(__ushort_as_bfloat16(h0b)));
        u16 l1b = bfb(t1 - __bfloat162float(__ushort_as_bfloat16(h1b)));
        hiw[j] = (u32)h0b | ((u32)h1b << 16);
        low[j] = (u32)l0b | ((u32)l1b << 16);
    }
    u32* dst = (u32*)(g_x1p + ((((size_t)(b*24 + d)*64 + h)*128 + w)*64));
    *(uint4*)dst        = make_uint4(hiw[0], hiw[1], hiw[2], hiw[3]);
    *(uint4*)(dst + 4)  = make_uint4(hiw[4], hiw[5], hiw[6], hiw[7]);
    *(uint4*)(dst + 8)  = make_uint4(low[0], low[1], low[2], low[3]);
    *(uint4*)(dst + 12) = make_uint4(low[4], low[5], low[6], low[7]);
}

// ---------------- GN finalize + apply + SiLU (layers 1,2) ----------------
__global__ void __launch_bounds__(256) k_norm(int which, float* outext,
                                              const float* __restrict__ gw,
                                              const float* __restrict__ gb,
                                              int nslab, float invN) {
    const float* in = (which == 1) ? g_x2 : g_feat;
    float* out = (which == 2) ? outext : g_x2n;
    const double* st = g_stats + which*128;
    __shared__ float sA, sB;
    int x = blockIdx.x;
    int s = x % nslab, c = (x / nslab) & 15, b = x / (nslab*16);
    if (threadIdx.x == 0) {
        const double* p = st + ((size_t)b*8 + (c >> 1))*2;
        double mu = p[0] * (double)invN;
        double var = p[1] * (double)invN - mu*mu;
        float rstd = rsqrtf((float)var + 1e-5f);
        float A = rstd * gw[c];
        sA = A; sB = gb[c] - (float)mu * A;
    }
    __syncthreads();
    float A = sA, Bv = sB;
    size_t base = ((size_t)(b*16 + c)*nslab + s)*8192;
    const float4* ip = (const float4*)(in + base);
    float4* op = (float4*)(out + base);
    for (int i = threadIdx.x; i < 2048; i += 256) {
        float4 v = ip[i];
        v.x = v.x*A + Bv; v.y = v.y*A + Bv; v.z = v.z*A + Bv; v.w = v.w*A + Bv;
        v.x = v.x / (1.f + __expf(-v.x));
        v.y = v.y / (1.f + __expf(-v.y));
        v.z = v.z / (1.f + __expf(-v.z));
        v.w = v.w / (1.f + __expf(-v.w));
        op[i] = v;
    }
}

// ---------------- conv3d oc=1 (FMA2, proven) ----------------
__global__ void __launch_bounds__(128) k_conv3d_oc1(const float* __restrict__ wts,
                                                    const float* __restrict__ bias) {
    __shared__ u64 swt[432];
    int tid = threadIdx.x;
    for (int i = tid; i < 432; i += 128) swt[i] = pk1(wts[i]);
    __syncthreads();
    int x = blockIdx.x;
    int ht = x & 7, d = (x >> 3) % 24, b = x / 192;
    int wt = tid & 15, hr = tid >> 4;
    int w0 = wt << 3, h = ht*8 + hr;
    u64 acc[4];
#pragma unroll
    for (int t = 0; t < 4; t++) acc[t] = 0ull;
    const float* inb = g_x2n + (size_t)b*16*DD*HW;
    for (int ic = 0; ic < 16; ic++) {
        const float* inc = inb + (size_t)ic*DD*HW;
#pragma unroll
        for (int kd = 0; kd < 3; kd++) {
            int zd = d + kd - 1;
            if ((unsigned)zd >= (unsigned)DD) continue;
#pragma unroll
            for (int kh = 0; kh < 3; kh++) {
                int zh = h + kh - 1;
                if ((unsigned)zh >= (unsigned)HH) continue;
                const float* row = inc + ((size_t)zd*HH + zh)*WW + w0;
                float r0 = (w0 == 0) ? 0.f : __ldg(row - 1);
                float4 va = *(const float4*)row;
                float4 vb = *(const float4*)(row + 4);
                float r9 = (w0 == 120) ? 0.f : __ldg(row + 8);
                u64 pe[5], po[4];
                pe[0] = pk(r0, va.x);  pe[1] = pk(va.y, va.z);
                pe[2] = pk(va.w, vb.x); pe[3] = pk(vb.y, vb.z);
                pe[4] = pk(vb.w, r9);
                po[0] = pk(va.x, va.y); po[1] = pk(va.z, va.w);
                po[2] = pk(vb.x, vb.y); po[3] = pk(vb.z, vb.w);
                int tb = (kd*3 + kh)*3;
                u64 wv0 = swt[ic*27 + tb + 0];
                u64 wv1 = swt[ic*27 + tb + 1];
                u64 wv2 = swt[ic*27 + tb + 2];
#pragma unroll
                for (int t = 0; t < 4; t++) {
                    fma2(acc[t], wv0, pe[t]);
                    fma2(acc[t], wv1, po[t]);
                    fma2(acc[t], wv2, pe[t + 1]);
                }
            }
        }
    }
    float bs = bias[0];
    float o[8];
#pragma unroll
    for (int t = 0; t < 4; t++) { float2 f = unpk(acc[t]); o[2*t] = f.x + bs; o[2*t+1] = f.y + bs; }
    float* orow = g_logits + (((size_t)b*DD + d)*HH + h)*WW + w0;
    *(float4*)orow       = make_float4(o[0], o[1], o[2], o[3]);
    *(float4*)(orow + 4) = make_float4(o[4], o[5], o[6], o[7]);
}

// ---------------- softmax (proven) ----------------
__global__ void __launch_bounds__(128) k_softmax(float* __restrict__ out) {
    int x = blockIdx.x;
    int h = x & 63, b = x >> 6;
    int w = threadIdx.x;
    const float* lp = g_logits + ((size_t)b*DD*HH + h)*WW + w;
    float l[DD];
    float m = -1e30f;
#pragma unroll
    for (int d = 0; d < DD; d++) { l[d] = lp[(size_t)d*HW]; m = fmaxf(m, l[d]); }
    float S = 0.f, E = 0.f;
#pragma unroll
    for (int d = 0; d < DD; d++) {
        float e = __expf(l[d] - m);
        S += e; E += e * (float)d;
    }
    float inv = 1.f / S;
    int oi = (b*HH + h)*WW + w;
    out[oi]           = E * inv;
    out[65536 + oi]   = 0.f;
    out[131072 + oi]  = 0.f;
    out[1245184 + oi] = inv;
}

// ---------------- feature head conv2d (FMA2, proven) ----------------
__global__ void __launch_bounds__(128, 3) k_conv2d_feat(const float* __restrict__ fL,
                                                        const float* __restrict__ wts) {
    __shared__ __align__(16) u64 swt[32*9*16];
    __shared__ float sred[16];
    int tid = threadIdx.x;
    if (tid < 16) sred[tid] = 0.f;
    int x = blockIdx.x;
    int wtile = x & 1, ht = (x >> 1) & 15, b = x >> 5;
    int wt = tid & 7, os = (tid >> 3) & 3, hr = tid >> 5;
    int w0 = wtile*64 + wt*8, h = ht*4 + hr, oc0 = os*4;
    u64 acc[4][4];
#pragma unroll
    for (int o = 0; o < 4; o++)
#pragma unroll
        for (int t = 0; t < 4; t++) acc[o][t] = 0ull;
    for (int p = 0; p < 4; p++) {
        __syncthreads();
        for (int i = tid; i < 32*144; i += 128) {
            int icl = i / 144; int r = i - icl*144; int tap = r >> 4; int oc = r & 15;
            swt[i] = pk1(wts[((size_t)oc*128 + p*32 + icl)*9 + tap]);
        }
        __syncthreads();
        for (int icl = 0; icl < 32; icl++) {
            int ic = p*32 + icl;
            const float* rowb = fL + ((size_t)(b*128 + ic)*HH)*WW;
#pragma unroll
            for (int kh = 0; kh < 3; kh++) {
                int zh = h + kh - 1;
                if ((unsigned)zh >= (unsigned)HH) continue;
                const float* row = rowb + (size_t)zh*WW + w0;
                float r0 = (w0 == 0) ? 0.f : __ldg(row - 1);
                float4 va = *(const float4*)row;
                float4 vb = *(const float4*)(row + 4);
                float r9 = (w0 == 120) ? 0.f : __ldg(row + 8);
                u64 pe[5], po[4];
                pe[0] = pk(r0, va.x);  pe[1] = pk(va.y, va.z);
                pe[2] = pk(va.w, vb.x); pe[3] = pk(vb.y, vb.z);
                pe[4] = pk(vb.w, r9);
                po[0] = pk(va.x, va.y); po[1] = pk(va.z, va.w);
                po[2] = pk(vb.x, vb.y); po[3] = pk(vb.z, vb.w);
                const u64* wbase = swt + (icl*9 + kh*3)*16 + oc0;
#pragma unroll
                for (int o = 0; o < 4; o++) {
                    u64 wv0 = wbase[o];
                    fma2(acc[o][0], wv0, pe[0]); fma2(acc[o][1], wv0, pe[1]);
                    fma2(acc[o][2], wv0, pe[2]); fma2(acc[o][3], wv0, pe[3]);
                }
#pragma unroll
                for (int o = 0; o < 4; o++) {
                    u64 wv1 = wbase[16 + o];
                    fma2(acc[o][0], wv1, po[0]); fma2(acc[o][1], wv1, po[1]);
                    fma2(acc[o][2], wv1, po[2]); fma2(acc[o][3], wv1, po[3]);
                }
#pragma unroll
                for (int o = 0; o < 4; o++) {
                    u64 wv2 = wbase[32 + o];
                    fma2(acc[o][0], wv2, pe[1]); fma2(acc[o][1], wv2, pe[2]);
                    fma2(acc[o][2], wv2, pe[3]); fma2(acc[o][3], wv2, pe[4]);
                }
            }
        }
    }
    float gs[2], gs2[2];
    gs[0] = gs[1] = gs2[0] = gs2[1] = 0.f;
#pragma unroll
    for (int o = 0; o < 4; o++) {
        float v[8];
#pragma unroll
        for (int t = 0; t < 4; t++) { float2 f = unpk(acc[o][t]); v[2*t] = f.x; v[2*t+1] = f.y; }
        int oc = oc0 + o;
        float* orow = g_feat + (((size_t)b*16 + oc)*HH + h)*WW + w0;
        *(float4*)orow       = make_float4(v[0], v[1], v[2], v[3]);
        *(float4*)(orow + 4) = make_float4(v[4], v[5], v[6], v[7]);
        float s = 0.f, s2 = 0.f;
#pragma unroll
        for (int j = 0; j < 8; j++) { s += v[j]; s2 += v[j]*v[j]; }
        gs[o >> 1] += s; gs2[o >> 1] += s2;
    }
#pragma unroll
    for (int i = 0; i < 2; i++) {
        int grp = os*2 + i;
        atomicAdd(&sred[grp*2],     gs[i]);
        atomicAdd(&sred[grp*2 + 1], gs2[i]);
    }
    __syncthreads();
    if (tid < 16) atomicAdd(&g_stats[2*128 + b*16 + tid], (double)sred[tid]);
}

// ---------------- launch ----------------
extern "C" void kernel_launch(void* const* d_in, const int* in_sizes, int n_in,
                              void* d_out, int out_size) {
    const float* fL    = (const float*)d_in[0];
    const float* fR    = (const float*)d_in[1];
    const float* w1    = (const float*)d_in[2];
    const float* gn1w  = (const float*)d_in[3];
    const float* gn1b  = (const float*)d_in[4];
    const float* w2    = (const float*)d_in[5];
    const float* gn2w  = (const float*)d_in[6];
    const float* gn2b  = (const float*)d_in[7];
    const float* w3    = (const float*)d_in[8];
    const float* b3    = (const float*)d_in[9];
    const float* fhw   = (const float*)d_in[10];
    const float* fhgnw = (const float*)d_in[11];
    const float* fhgnb = (const float*)d_in[12];
    float* out = (float*)d_out;

    const float invN3d = 1.0f / (2.0f*DD*HH*WW);
    const float invN2d = 1.0f / (2.0f*HH*WW);

    cudaFuncSetAttribute(k_conv_tc<8>,  cudaFuncAttributeMaxDynamicSharedMemorySize, CONV_SMEM);
    cudaFuncSetAttribute(k_conv_tc<16>, cudaFuncAttributeMaxDynamicSharedMemorySize, CONV_SMEM);

    k_zero_stats<<<1, 384>>>();
    k_costvol<<<BATCH*8*HH, 128>>>(fL, fR);
    k_conv_tc<8><<<1024, 512, CONV_SMEM>>>(w1);
    k_norm_pack<<<BATCH*24*32, 256>>>(gn1w, gn1b);
    k_zero_stats<<<1, 384>>>();
    k_conv_tc<16><<<1024, 512, CONV_SMEM>>>(w2);
    k_norm<<<BATCH*16*24, 256>>>(1, nullptr, gn2w, gn2b, 24, invN3d);
    k_conv3d_oc1<<<BATCH*24*8, 128>>>(w3, b3);
    k_softmax<<<BATCH*HH, 128>>>(out);
    k_conv2d_feat<<<BATCH*16*2, 128>>>(fL, fhw);
    k_norm<<<BATCH*16, 256>>>(2, out + 196608, fhgnw, fhgnb, 1, invN2d);
}

// round 9
// speedup vs baseline: 1.2853x; 1.0259x over previous
#include <cuda_runtime.h>
#include <cuda_bf16.h>
#include <math.h>

#define BATCH 8
#define DD 24
#define HH 64
#define WW 128
#define HW (HH*WW)

typedef unsigned long long u64;
typedef unsigned int u32;
typedef unsigned short u16;

// ---------------- packed fp32x2 helpers ----------------
__device__ __forceinline__ u64 pk(float lo, float hi) {
    u64 r; asm("mov.b64 %0, {%1,%2};" : "=l"(r) : "f"(lo), "f"(hi)); return r;
}
__device__ __forceinline__ u64 pk1(float v) { return pk(v, v); }
__device__ __forceinline__ void fma2(u64& d, u64 a, u64 b) {
    asm("fma.rn.f32x2 %0, %1, %2, %0;" : "+l"(d) : "l"(a), "l"(b));
}
__device__ __forceinline__ float2 unpk(u64 v) {
    float2 f; asm("mov.b64 {%0,%1}, %2;" : "=f"(f.x), "=f"(f.y) : "l"(v)); return f;
}

// ---------------- mma / ldmatrix helpers ----------------
__device__ __forceinline__ u32 smem_u32(const void* p) {
    u32 a; asm("{ .reg .u64 t; cvta.to.shared.u64 t, %1; cvt.u32.u64 %0, t; }" : "=r"(a) : "l"(p));
    return a;
}
__device__ __forceinline__ void ldsm4(u32 a, u32& r0, u32& r1, u32& r2, u32& r3) {
    asm volatile("ldmatrix.sync.aligned.m8n8.x4.shared.b16 {%0,%1,%2,%3}, [%4];"
                 : "=r"(r0), "=r"(r1), "=r"(r2), "=r"(r3) : "r"(a));
}
__device__ __forceinline__ void mma16816(float* d, u32 a0, u32 a1, u32 a2, u32 a3, u32 b0, u32 b1) {
    asm volatile("mma.sync.aligned.m16n8k16.row.col.f32.bf16.bf16.f32 "
                 "{%0,%1,%2,%3}, {%4,%5,%6,%7}, {%8,%9}, {%0,%1,%2,%3};"
                 : "+f"(d[0]), "+f"(d[1]), "+f"(d[2]), "+f"(d[3])
                 : "r"(a0), "r"(a1), "r"(a2), "r"(a3), "r"(b0), "r"(b1));
}
__device__ __forceinline__ void cp16(u32 dst, const void* src) {
    asm volatile("cp.async.ca.shared.global [%0], [%1], 16;" :: "r"(dst), "l"(src));
}
__device__ __forceinline__ u16 bfb(float f) {
    return __bfloat16_as_ushort(__float2bfloat16(f));
}
__device__ __forceinline__ float bff(u16 b) {
    return __bfloat162float(__ushort_as_bfloat16(b));
}

// ---------------- scratch ----------------
__device__ __align__(16) char g_cvp[(size_t)BATCH*DD*HH*WW*32];  // packed cost volume, 32B/voxel
__device__ float g_x1[BATCH*16*DD*HH*WW];
__device__ __align__(16) char g_x1p[(size_t)BATCH*DD*HH*WW*64];  // packed x1n, 64B/voxel
__device__ float g_x2[BATCH*16*DD*HH*WW];
__device__ float g_x2n[BATCH*16*DD*HH*WW];
__device__ float g_logits[BATCH*DD*HH*WW];
__device__ float g_feat[BATCH*16*HH*WW];
__device__ double g_stats[3*BATCH*8*2];
__device__ __align__(16) float g_zerobuf[4];   // zero-initialized

__global__ void k_zero_stats() {
    int i = threadIdx.x;
    if (i < 3*BATCH*8*2) g_stats[i] = 0.0;
}

// ---------------- cost volume -> packed bf16 hi/lo channels-last ----------------
// grid = B*HH, block = 256 (w x dhalf); dynamic smem = 128KB
__global__ void __launch_bounds__(256) k_costvol(const float* __restrict__ fL,
                                                 const float* __restrict__ fR) {
    extern __shared__ float scv[];           // sL[16384] then sR[16384]
    float* sL = scv;
    float* sR = scv + 16384;
    int b = blockIdx.x >> 6, h = blockIdx.x & 63;
    int tid = threadIdx.x;
    for (int i = tid; i < 16384; i += 256) {
        size_t gidx = ((size_t)(b*128 + (i >> 7))*HH + h)*WW + (i & 127);
        sL[i] = fL[gidx];
        sR[i] = fR[gidx];
    }
    __syncthreads();
    int w = tid & 127, dh = tid >> 7;
    for (int dl = 0; dl < 12; dl++) {
        int d = dh*12 + dl;
        u32 hiw[4], low[4];
#pragma unroll
        for (int gp = 0; gp < 4; gp++) {
            float s0 = 0.f, s1 = 0.f;
            if (w >= d) {
                const float* pL = sL + gp*32*128 + w;
                const float* pR = sR + gp*32*128 + w - d;
#pragma unroll
                for (int c = 0; c < 16; c++) {
                    s0 += pL[c*128] * pR[c*128];
                    s1 += pL[(16 + c)*128] * pR[(16 + c)*128];
                }
                s0 *= 0.0625f; s1 *= 0.0625f;
            }
            u16 h0 = bfb(s0), h1 = bfb(s1);
            u16 l0 = bfb(s0 - bff(h0)), l1 = bfb(s1 - bff(h1));
            hiw[gp] = (u32)h0 | ((u32)h1 << 16);
            low[gp] = (u32)l0 | ((u32)l1 << 16);
        }
        char* vox = g_cvp + ((((size_t)(b*24 + d)*64 + h)*128 + w)*32);
        *(uint4*)vox        = make_uint4(hiw[0], hiw[1], hiw[2], hiw[3]);
        *(uint4*)(vox + 16) = make_uint4(low[0], low[1], low[2], low[3]);
    }
}

// ================= tensor-core conv3d, pipelined, conflict-free 80B rows =========
// grid = B*32*4 (b, h-pair, d-sixth), block = 512 (16 warps)
#define ROW_B   80
#define PLANE_B (520*ROW_B)
#define W_OFF   (4*PLANE_B)
#define BOUNCE_OFF (W_OFF + 27648)
#define CONV_SMEM (BOUNCE_OFF + 16640)

template<int CIN>
__global__ void __launch_bounds__(512) k_conv_tc(const float* __restrict__ wts) {
    float* out = (CIN == 8) ? g_x1 : g_x2;
    double* stats = g_stats + ((CIN == 8) ? 0 : 1)*128;

    extern __shared__ char smem[];
    __nv_bfloat16* w_sm = (__nv_bfloat16*)(smem + W_OFF);
    float* bounce = (float*)(smem + BOUNCE_OFF);
    __shared__ float sred[16];

    u32 a_base = smem_u32(smem);
    u32 w_base = smem_u32(w_sm);
    int tid = threadIdx.x, lane = tid & 31, wrp = tid >> 5;
    int hl = wrp >> 3, wq = wrp & 7, w0 = wq*16;
    if (tid < 16) sred[tid] = 0.f;

    int x = blockIdx.x;
    int dq = x & 3, hp = (x >> 2) & 31, b = x >> 7;
    int d0 = dq*6, h0 = hp*2;

    // zero all 4 plane slots once (halo cols + conv1's zero channels 8-15)
    for (int i = tid; i < 4*PLANE_B/4; i += 512) ((u32*)smem)[i] = 0u;

    // weights: [split][tap][oc16][ic16] bf16
    for (int i = tid; i < 27*256; i += 512) {
        int ic = i & 15, oc = (i >> 4) & 15, tap = i >> 8;
        float v = (ic < CIN) ? wts[(oc*CIN + ic)*27 + tap] : 0.f;
        __nv_bfloat16 hi = __float2bfloat16(v);
        __nv_bfloat16 lo = __float2bfloat16(v - __bfloat162float(hi));
        w_sm[i] = hi; w_sm[27*256 + i] = lo;
    }
    __syncthreads();

    auto stage = [&](int zd) {
        int slot = (zd - d0 + 1) & 3;
        bool pv = ((unsigned)zd < 24u);
        if (CIN == 8) {
            // packed cv: voxel 32B = [hi g0-7][lo g0-7]; plane chunks 0 (hi) and 2 (lo)
            for (int it = tid; it < 1024; it += 512) {
                int ch = it & 1, w = (it >> 1) & 127, zhl = it >> 8;
                int zh = h0 - 1 + zhl;
                int r = zhl*130 + w + 1;
                u32 dst = a_base + slot*PLANE_B + (u32)r*ROW_B + (ch*2)*16;
                const void* src = (pv && (unsigned)zh < 64u)
                    ? (const void*)(g_cvp + ((((size_t)(b*24 + zd)*64 + zh)*128 + w)*32 + ch*16))
                    : (const void*)g_zerobuf;
                cp16(dst, src);
            }
        } else {
            for (int it = tid; it < 2048; it += 512) {
                int ch = it & 3, w = (it >> 2) & 127, zhl = it >> 9;
                int zh = h0 - 1 + zhl;
                int r = zhl*130 + w + 1;
                u32 dst = a_base + slot*PLANE_B + (u32)r*ROW_B + ch*16;
                const void* src = (pv && (unsigned)zh < 64u)
                    ? (const void*)(g_x1p + ((((size_t)(b*24 + zd)*64 + zh)*128 + w)*64 + ch*16))
                    : (const void*)g_zerobuf;
                cp16(dst, src);
            }
        }
        asm volatile("cp.async.commit_group;" ::: "memory");
    };

    stage(d0 - 1); stage(d0); stage(d0 + 1);

    float gsum[2] = {0.f, 0.f}, gss[2] = {0.f, 0.f};

    for (int dl = 0; dl < 6; dl++) {
        int d = d0 + dl;
        stage(d + 2);
        asm volatile("cp.async.wait_group 1;" ::: "memory");
        __syncthreads();

        float acc[2][4];
#pragma unroll
        for (int oh = 0; oh < 2; oh++)
#pragma unroll
            for (int r = 0; r < 4; r++) acc[oh][r] = 0.f;

#pragma unroll
        for (int kd = 0; kd < 3; kd++) {
            u32 pbase = a_base + (u32)((dl + kd) & 3)*PLANE_B;
#pragma unroll
            for (int kh = 0; kh < 3; kh++) {
                int zhl = hl + kh;
                u32 bfr[3][2][4];
#pragma unroll
                for (int kw = 0; kw < 3; kw++) {
                    int tap = (kd*3 + kh)*3 + kw;
                    int m = lane >> 3;
#pragma unroll
                    for (int sp = 0; sp < 2; sp++) {
                        u32 ba = w_base + (u32)((sp*27 + tap)*256
                                  + ((m >> 1)*8 + (lane & 7))*16 + (m & 1)*8)*2;
                        ldsm4(ba, bfr[kw][sp][0], bfr[kw][sp][1], bfr[kw][sp][2], bfr[kw][sp][3]);
                    }
                }
#pragma unroll
                for (int kw = 0; kw < 3; kw++) {
                    int r = zhl*130 + w0 + kw + (lane & 15);
                    u32 ah = pbase + (u32)r*ROW_B + (lane >> 4)*16;
                    u32 al = ah + 32;
                    u32 h0r, h1r, h2r, h3r, l0r, l1r, l2r, l3r;
                    ldsm4(ah, h0r, h1r, h2r, h3r);
                    ldsm4(al, l0r, l1r, l2r, l3r);
#pragma unroll
                    for (int oh = 0; oh < 2; oh++) {
                        mma16816(acc[oh], h0r, h1r, h2r, h3r, bfr[kw][0][oh*2], bfr[kw][0][oh*2+1]);
                        mma16816(acc[oh], h0r, h1r, h2r, h3r, bfr[kw][1][oh*2], bfr[kw][1][oh*2+1]);
                        mma16816(acc[oh], l0r, l1r, l2r, l3r, bfr[kw][0][oh*2], bfr[kw][0][oh*2+1]);
                    }
                }
            }
        }

#pragma unroll
        for (int oh = 0; oh < 2; oh++) {
            float s = 0.f, s2 = 0.f;
#pragma unroll
            for (int r = 0; r < 4; r++) { float v = acc[oh][r]; s += v; s2 += v*v; }
            gsum[oh] += s; gss[oh] += s2;
        }

#pragma unroll
        for (int oh = 0; oh < 2; oh++)
#pragma unroll
            for (int r = 0; r < 4; r++) {
                int oc = oh*8 + (lane & 3)*2 + (r & 1);
                int px = w0 + (lane >> 2) + (r >> 1)*8;
                bounce[oc*260 + hl*128 + px] = acc[oh][r];
            }
        __syncthreads();
        float* ob = out + ((size_t)b*16*DD + d)*HW;
        for (int i = tid; i < 1024; i += 512) {
            int oc = i >> 6, rem = i & 63;
            int h2 = rem >> 5, w4 = rem & 31;
            float4 v = *(float4*)&bounce[oc*260 + h2*128 + w4*4];
            *(float4*)&ob[(size_t)oc*DD*HW + (h0 + h2)*WW + w4*4] = v;
        }
    }

    int g0 = lane & 3;
    atomicAdd(&sred[g0*2],         gsum[0]); atomicAdd(&sred[g0*2 + 1],         gss[0]);
    atomicAdd(&sred[(4 + g0)*2],   gsum[1]); atomicAdd(&sred[(4 + g0)*2 + 1],   gss[1]);
    __syncthreads();
    if (tid < 16) atomicAdd(&stats[b*16 + tid], (double)sred[tid]);
}

// ---------------- GN1 finalize + SiLU -> packed (proven, 55us) ----------------
__global__ void __launch_bounds__(256) k_norm_pack(const float* __restrict__ gw,
                                                   const float* __restrict__ gb) {
    __shared__ float sA[16], sB[16];
    int x = blockIdx.x;
    int hq = x & 31, d = (x >> 5) % 24, b = x / 768;
    int tid = threadIdx.x;
    if (tid < 16) {
        const double* p = g_stats + ((size_t)b*8 + (tid >> 1))*2;
        double mu = p[0] / 393216.0;
        double var = p[1] / 393216.0 - mu*mu;
        float rstd = rsqrtf((float)var + 1e-5f);
        float A = rstd * gw[tid];
        sA[tid] = A; sB[tid] = gb[tid] - (float)mu*A;
    }
    __syncthreads();
    int w = tid & 127, h = hq*2 + (tid >> 7);
    const float* base = g_x1 + ((size_t)b*16*DD + d)*HW + h*WW + w;
    u32 hiw[8], low[8];
#pragma unroll
    for (int j = 0; j < 8; j++) {
        float v0 = base[(size_t)(2*j)*DD*HW];
        float v1 = base[(size_t)(2*j + 1)*DD*HW];
        float t0 = v0*sA[2*j] + sB[2*j];
        float t1 = v1*sA[2*j + 1] + sB[2*j + 1];
        t0 = t0 / (1.f + __expf(-t0));
        t1 = t1 / (1.f + __expf(-t1));
        u16 h0b = bfb(t0), h1b = bfb(t1);
        u16 l0b = bfb(t0 - bff(h0b));
        u16 l1b = bfb(t1 - bff(h1b));
        hiw[j] = (u32)h0b | ((u32)h1b << 16);
        low[j] = (u32)l0b | ((u32)l1b << 16);
    }
    u32* dst = (u32*)(g_x1p + ((((size_t)(b*24 + d)*64 + h)*128 + w)*64));
    *(uint4*)dst        = make_uint4(hiw[0], hiw[1], hiw[2], hiw[3]);
    *(uint4*)(dst + 4)  = make_uint4(hiw[4], hiw[5], hiw[6], hiw[7]);
    *(uint4*)(dst + 8)  = make_uint4(low[0], low[1], low[2], low[3]);
    *(uint4*)(dst + 12) = make_uint4(low[4], low[5], low[6], low[7]);
}

// ---------------- GN finalize + apply + SiLU (layers 1,2) ----------------
__global__ void __launch_bounds__(256) k_norm(int which, float* outext,
                                              const float* __restrict__ gw,
                                              const float* __restrict__ gb,
                                              int nslab, float invN) {
    const float* in = (which == 1) ? g_x2 : g_feat;
    float* out = (which == 2) ? outext : g_x2n;
    const double* st = g_stats + which*128;
    __shared__ float sA, sB;
    int x = blockIdx.x;
    int s = x % nslab, c = (x / nslab) & 15, b = x / (nslab*16);
    if (threadIdx.x == 0) {
        const double* p = st + ((size_t)b*8 + (c >> 1))*2;
        double mu = p[0] * (double)invN;
        double var = p[1] * (double)invN - mu*mu;
        float rstd = rsqrtf((float)var + 1e-5f);
        float A = rstd * gw[c];
        sA = A; sB = gb[c] - (float)mu * A;
    }
    __syncthreads();
    float A = sA, Bv = sB;
    size_t base = ((size_t)(b*16 + c)*nslab + s)*8192;
    const float4* ip = (const float4*)(in + base);
    float4* op = (float4*)(out + base);
    for (int i = threadIdx.x; i < 2048; i += 256) {
        float4 v = ip[i];
        v.x = v.x*A + Bv; v.y = v.y*A + Bv; v.z = v.z*A + Bv; v.w = v.w*A + Bv;
        v.x = v.x / (1.f + __expf(-v.x));
        v.y = v.y / (1.f + __expf(-v.y));
        v.z = v.z / (1.f + __expf(-v.z));
        v.w = v.w / (1.f + __expf(-v.w));
        op[i] = v;
    }
}

// ---------------- conv3d oc=1 (FMA2, proven) ----------------
__global__ void __launch_bounds__(128) k_conv3d_oc1(const float* __restrict__ wts,
                                                    const float* __restrict__ bias) {
    __shared__ u64 swt[432];
    int tid = threadIdx.x;
    for (int i = tid; i < 432; i += 128) swt[i] = pk1(wts[i]);
    __syncthreads();
    int x = blockIdx.x;
    int ht = x & 7, d = (x >> 3) % 24, b = x / 192;
    int wt = tid & 15, hr = tid >> 4;
    int w0 = wt << 3, h = ht*8 + hr;
    u64 acc[4];
#pragma unroll
    for (int t = 0; t < 4; t++) acc[t] = 0ull;
    const float* inb = g_x2n + (size_t)b*16*DD*HW;
    for (int ic = 0; ic < 16; ic++) {
        const float* inc = inb + (size_t)ic*DD*HW;
#pragma unroll
        for (int kd = 0; kd < 3; kd++) {
            int zd = d + kd - 1;
            if ((unsigned)zd >= (unsigned)DD) continue;
#pragma unroll
            for (int kh = 0; kh < 3; kh++) {
                int zh = h + kh - 1;
                if ((unsigned)zh >= (unsigned)HH) continue;
                const float* row = inc + ((size_t)zd*HH + zh)*WW + w0;
                float r0 = (w0 == 0) ? 0.f : __ldg(row - 1);
                float4 va = *(const float4*)row;
                float4 vb = *(const float4*)(row + 4);
                float r9 = (w0 == 120) ? 0.f : __ldg(row + 8);
                u64 pe[5], po[4];
                pe[0] = pk(r0, va.x);  pe[1] = pk(va.y, va.z);
                pe[2] = pk(va.w, vb.x); pe[3] = pk(vb.y, vb.z);
                pe[4] = pk(vb.w, r9);
                po[0] = pk(va.x, va.y); po[1] = pk(va.z, va.w);
                po[2] = pk(vb.x, vb.y); po[3] = pk(vb.z, vb.w);
                int tb = (kd*3 + kh)*3;
                u64 wv0 = swt[ic*27 + tb + 0];
                u64 wv1 = swt[ic*27 + tb + 1];
                u64 wv2 = swt[ic*27 + tb + 2];
#pragma unroll
                for (int t = 0; t < 4; t++) {
                    fma2(acc[t], wv0, pe[t]);
                    fma2(acc[t], wv1, po[t]);
                    fma2(acc[t], wv2, pe[t + 1]);
                }
            }
        }
    }
    float bs = bias[0];
    float o[8];
#pragma unroll
    for (int t = 0; t < 4; t++) { float2 f = unpk(acc[t]); o[2*t] = f.x + bs; o[2*t+1] = f.y + bs; }
    float* orow = g_logits + (((size_t)b*DD + d)*HH + h)*WW + w0;
    *(float4*)orow       = make_float4(o[0], o[1], o[2], o[3]);
    *(float4*)(orow + 4) = make_float4(o[4], o[5], o[6], o[7]);
}

// ---------------- softmax (proven) ----------------
__global__ void __launch_bounds__(128) k_softmax(float* __restrict__ out) {
    int x = blockIdx.x;
    int h = x & 63, b = x >> 6;
    int w = threadIdx.x;
    const float* lp = g_logits + ((size_t)b*DD*HH + h)*WW + w;
    float l[DD];
    float m = -1e30f;
#pragma unroll
    for (int d = 0; d < DD; d++) { l[d] = lp[(size_t)d*HW]; m = fmaxf(m, l[d]); }
    float S = 0.f, E = 0.f;
#pragma unroll
    for (int d = 0; d < DD; d++) {
        float e = __expf(l[d] - m);
        S += e; E += e * (float)d;
    }
    float inv = 1.f / S;
    int oi = (b*HH + h)*WW + w;
    out[oi]           = E * inv;
    out[65536 + oi]   = 0.f;
    out[131072 + oi]  = 0.f;
    out[1245184 + oi] = inv;
}

// ---------------- feature head conv2d (FMA2, proven) ----------------
__global__ void __launch_bounds__(128, 3) k_conv2d_feat(const float* __restrict__ fL,
                                                        const float* __restrict__ wts) {
    __shared__ __align__(16) u64 swt[32*9*16];
    __shared__ float sred[16];
    int tid = threadIdx.x;
    if (tid < 16) sred[tid] = 0.f;
    int x = blockIdx.x;
    int wtile = x & 1, ht = (x >> 1) & 15, b = x >> 5;
    int wt = tid & 7, os = (tid >> 3) & 3, hr = tid >> 5;
    int w0 = wtile*64 + wt*8, h = ht*4 + hr, oc0 = os*4;
    u64 acc[4][4];
#pragma unroll
    for (int o = 0; o < 4; o++)
#pragma unroll
        for (int t = 0; t < 4; t++) acc[o][t] = 0ull;
    for (int p = 0; p < 4; p++) {
        __syncthreads();
        for (int i = tid; i < 32*144; i += 128) {
            int icl = i / 144; int r = i - icl*144; int tap = r >> 4; int oc = r & 15;
            swt[i] = pk1(wts[((size_t)oc*128 + p*32 + icl)*9 + tap]);
        }
        __syncthreads();
        for (int icl = 0; icl < 32; icl++) {
            int ic = p*32 + icl;
            const float* rowb = fL + ((size_t)(b*128 + ic)*HH)*WW;
#pragma unroll
            for (int kh = 0; kh < 3; kh++) {
                int zh = h + kh - 1;
                if ((unsigned)zh >= (unsigned)HH) continue;
                const float* row = rowb + (size_t)zh*WW + w0;
                float r0 = (w0 == 0) ? 0.f : __ldg(row - 1);
                float4 va = *(const float4*)row;
                float4 vb = *(const float4*)(row + 4);
                float r9 = (w0 == 120) ? 0.f : __ldg(row + 8);
                u64 pe[5], po[4];
                pe[0] = pk(r0, va.x);  pe[1] = pk(va.y, va.z);
                pe[2] = pk(va.w, vb.x); pe[3] = pk(vb.y, vb.z);
                pe[4] = pk(vb.w, r9);
                po[0] = pk(va.x, va.y); po[1] = pk(va.z, va.w);
                po[2] = pk(vb.x, vb.y); po[3] = pk(vb.z, vb.w);
                const u64* wbase = swt + (icl*9 + kh*3)*16 + oc0;
#pragma unroll
                for (int o = 0; o < 4; o++) {
                    u64 wv0 = wbase[o];
                    fma2(acc[o][0], wv0, pe[0]); fma2(acc[o][1], wv0, pe[1]);
                    fma2(acc[o][2], wv0, pe[2]); fma2(acc[o][3], wv0, pe[3]);
                }
#pragma unroll
                for (int o = 0; o < 4; o++) {
                    u64 wv1 = wbase[16 + o];
                    fma2(acc[o][0], wv1, po[0]); fma2(acc[o][1], wv1, po[1]);
                    fma2(acc[o][2], wv1, po[2]); fma2(acc[o][3], wv1, po[3]);
                }
#pragma unroll
                for (int o = 0; o < 4; o++) {
                    u64 wv2 = wbase[32 + o];
                    fma2(acc[o][0], wv2, pe[1]); fma2(acc[o][1], wv2, pe[2]);
                    fma2(acc[o][2], wv2, pe[3]); fma2(acc[o][3], wv2, pe[4]);
                }
            }
        }
    }
    float gs[2], gs2[2];
    gs[0] = gs[1] = gs2[0] = gs2[1] = 0.f;
#pragma unroll
    for (int o = 0; o < 4; o++) {
        float v[8];
#pragma unroll
        for (int t = 0; t < 4; t++) { float2 f = unpk(acc[o][t]); v[2*t] = f.x; v[2*t+1] = f.y; }
        int oc = oc0 + o;
        float* orow = g_feat + (((size_t)b*16 + oc)*HH + h)*WW + w0;
        *(float4*)orow       = make_float4(v[0], v[1], v[2], v[3]);
        *(float4*)(orow + 4) = make_float4(v[4], v[5], v[6], v[7]);
        float s = 0.f, s2 = 0.f;
#pragma unroll
        for (int j = 0; j < 8; j++) { s += v[j]; s2 += v[j]*v[j]; }
        gs[o >> 1] += s; gs2[o >> 1] += s2;
    }
#pragma unroll
    for (int i = 0; i < 2; i++) {
        int grp = os*2 + i;
        atomicAdd(&sred[grp*2],     gs[i]);
        atomicAdd(&sred[grp*2 + 1], gs2[i]);
    }
    __syncthreads();
    if (tid < 16) atomicAdd(&g_stats[2*128 + b*16 + tid], (double)sred[tid]);
}

// ---------------- launch ----------------
extern "C" void kernel_launch(void* const* d_in, const int* in_sizes, int n_in,
                              void* d_out, int out_size) {
    const float* fL    = (const float*)d_in[0];
    const float* fR    = (const float*)d_in[1];
    const float* w1    = (const float*)d_in[2];
    const float* gn1w  = (const float*)d_in[3];
    const float* gn1b  = (const float*)d_in[4];
    const float* w2    = (const float*)d_in[5];
    const float* gn2w  = (const float*)d_in[6];
    const float* gn2b  = (const float*)d_in[7];
    const float* w3    = (const float*)d_in[8];
    const float* b3    = (const float*)d_in[9];
    const float* fhw   = (const float*)d_in[10];
    const float* fhgnw = (const float*)d_in[11];
    const float* fhgnb = (const float*)d_in[12];
    float* out = (float*)d_out;

    const float invN3d = 1.0f / (2.0f*DD*HH*WW);
    const float invN2d = 1.0f / (2.0f*HH*WW);

    cudaFuncSetAttribute(k_costvol,     cudaFuncAttributeMaxDynamicSharedMemorySize, 131072);
    cudaFuncSetAttribute(k_conv_tc<8>,  cudaFuncAttributeMaxDynamicSharedMemorySize, CONV_SMEM);
    cudaFuncSetAttribute(k_conv_tc<16>, cudaFuncAttributeMaxDynamicSharedMemorySize, CONV_SMEM);

    k_zero_stats<<<1, 384>>>();                                  // 0
    k_costvol<<<BATCH*HH, 256, 131072>>>(fL, fR);                // 1
    k_zero_stats<<<1, 384>>>();                                  // 2 (dummy)
    k_conv_tc<8><<<1024, 512, CONV_SMEM>>>(w1);                  // 3 <-- profiled
    k_norm_pack<<<BATCH*24*32, 256>>>(gn1w, gn1b);               // 4
    k_conv_tc<16><<<1024, 512, CONV_SMEM>>>(w2);                 // 5
    k_norm<<<BATCH*16*24, 256>>>(1, nullptr, gn2w, gn2b, 24, invN3d);  // 6
    k_conv3d_oc1<<<BATCH*24*8, 128>>>(w3, b3);                   // 7
    k_softmax<<<BATCH*HH, 128>>>(out);                           // 8
    k_conv2d_feat<<<BATCH*16*2, 128>>>(fL, fhw);                 // 9
    k_norm<<<BATCH*16, 256>>>(2, out + 196608, fhgnw, fhgnb, 1, invN2d); // 10
}

// round 10
// speedup vs baseline: 1.5308x; 1.1909x over previous
#include <cuda_runtime.h>
#include <cuda_bf16.h>
#include <math.h>

#define BATCH 8
#define DD 24
#define HH 64
#define WW 128
#define HW (HH*WW)

typedef unsigned long long u64;
typedef unsigned int u32;
typedef unsigned short u16;

// ---------------- packed fp32x2 helpers ----------------
__device__ __forceinline__ u64 pk(float lo, float hi) {
    u64 r; asm("mov.b64 %0, {%1,%2};" : "=l"(r) : "f"(lo), "f"(hi)); return r;
}
__device__ __forceinline__ u64 pk1(float v) { return pk(v, v); }
__device__ __forceinline__ void fma2(u64& d, u64 a, u64 b) {
    asm("fma.rn.f32x2 %0, %1, %2, %0;" : "+l"(d) : "l"(a), "l"(b));
}
__device__ __forceinline__ float2 unpk(u64 v) {
    float2 f; asm("mov.b64 {%0,%1}, %2;" : "=f"(f.x), "=f"(f.y) : "l"(v)); return f;
}

// ---------------- mma / ldmatrix helpers ----------------
__device__ __forceinline__ u32 smem_u32(const void* p) {
    u32 a; asm("{ .reg .u64 t; cvta.to.shared.u64 t, %1; cvt.u32.u64 %0, t; }" : "=r"(a) : "l"(p));
    return a;
}
__device__ __forceinline__ void ldsm4(u32 a, u32& r0, u32& r1, u32& r2, u32& r3) {
    asm volatile("ldmatrix.sync.aligned.m8n8.x4.shared.b16 {%0,%1,%2,%3}, [%4];"
                 : "=r"(r0), "=r"(r1), "=r"(r2), "=r"(r3) : "r"(a));
}
__device__ __forceinline__ void mma16816(float* d, u32 a0, u32 a1, u32 a2, u32 a3, u32 b0, u32 b1) {
    asm volatile("mma.sync.aligned.m16n8k16.row.col.f32.bf16.bf16.f32 "
                 "{%0,%1,%2,%3}, {%4,%5,%6,%7}, {%8,%9}, {%0,%1,%2,%3};"
                 : "+f"(d[0]), "+f"(d[1]), "+f"(d[2]), "+f"(d[3])
                 : "r"(a0), "r"(a1), "r"(a2), "r"(a3), "r"(b0), "r"(b1));
}
__device__ __forceinline__ void cp16(u32 dst, const void* src) {
    asm volatile("cp.async.ca.shared.global [%0], [%1], 16;" :: "r"(dst), "l"(src));
}
__device__ __forceinline__ u16 bfb(float f) {
    return __bfloat16_as_ushort(__float2bfloat16(f));
}
__device__ __forceinline__ float bff(u16 b) {
    return __bfloat162float(__ushort_as_bfloat16(b));
}

// ---------------- scratch ----------------
__device__ __align__(16) char g_cvp[(size_t)BATCH*DD*HH*WW*32];  // packed cost volume, 32B/voxel
__device__ float g_x1[BATCH*16*DD*HH*WW];
__device__ __align__(16) char g_x1p[(size_t)BATCH*DD*HH*WW*64];  // packed x1n, 64B/voxel
__device__ float g_x2[BATCH*16*DD*HH*WW];
__device__ float g_x2n[BATCH*16*DD*HH*WW];
__device__ float g_logits[BATCH*DD*HH*WW];
__device__ float g_feat[BATCH*16*HH*WW];
__device__ double g_stats[3*BATCH*8*2];
__device__ __align__(16) float g_zerobuf[4];   // zero-initialized

__global__ void k_zero_stats() {
    int i = threadIdx.x;
    if (i < 3*BATCH*8*2) g_stats[i] = 0.0;
}

// ---------------- cost volume -> packed bf16 hi/lo channels-last (proven) ----------------
__global__ void __launch_bounds__(256) k_costvol(const float* __restrict__ fL,
                                                 const float* __restrict__ fR) {
    extern __shared__ float scv[];
    float* sL = scv;
    float* sR = scv + 16384;
    int b = blockIdx.x >> 6, h = blockIdx.x & 63;
    int tid = threadIdx.x;
    for (int i = tid; i < 16384; i += 256) {
        size_t gidx = ((size_t)(b*128 + (i >> 7))*HH + h)*WW + (i & 127);
        sL[i] = fL[gidx];
        sR[i] = fR[gidx];
    }
    __syncthreads();
    int w = tid & 127, dh = tid >> 7;
    for (int dl = 0; dl < 12; dl++) {
        int d = dh*12 + dl;
        u32 hiw[4], low[4];
#pragma unroll
        for (int gp = 0; gp < 4; gp++) {
            float s0 = 0.f, s1 = 0.f;
            if (w >= d) {
                const float* pL = sL + gp*32*128 + w;
                const float* pR = sR + gp*32*128 + w - d;
#pragma unroll
                for (int c = 0; c < 16; c++) {
                    s0 += pL[c*128] * pR[c*128];
                    s1 += pL[(16 + c)*128] * pR[(16 + c)*128];
                }
                s0 *= 0.0625f; s1 *= 0.0625f;
            }
            u16 h0 = bfb(s0), h1 = bfb(s1);
            u16 l0 = bfb(s0 - bff(h0)), l1 = bfb(s1 - bff(h1));
            hiw[gp] = (u32)h0 | ((u32)h1 << 16);
            low[gp] = (u32)l0 | ((u32)l1 << 16);
        }
        char* vox = g_cvp + ((((size_t)(b*24 + d)*64 + h)*128 + w)*32);
        *(uint4*)vox        = make_uint4(hiw[0], hiw[1], hiw[2], hiw[3]);
        *(uint4*)(vox + 16) = make_uint4(low[0], low[1], low[2], low[3]);
    }
}

// ================= tensor-core conv3d: d-PAIR processing (B + plane reuse) =========
// grid = B*32*4 (b, h-pair, d-sixth), block = 512 (16 warps)
#define ROW_B   80
#define PLANE_B (520*ROW_B)
#define W_OFF   (4*PLANE_B)
#define BOUNCE_OFF (W_OFF + 27648)
#define CONV_SMEM (BOUNCE_OFF + 16640)

template<int CIN>
__global__ void __launch_bounds__(512) k_conv_tc(const float* __restrict__ wts) {
    float* out = (CIN == 8) ? g_x1 : g_x2;
    double* stats = g_stats + ((CIN == 8) ? 0 : 1)*128;

    extern __shared__ char smem[];
    __nv_bfloat16* w_sm = (__nv_bfloat16*)(smem + W_OFF);
    float* bounce = (float*)(smem + BOUNCE_OFF);
    __shared__ float sred[16];

    u32 a_base = smem_u32(smem);
    u32 w_base = smem_u32(w_sm);
    int tid = threadIdx.x, lane = tid & 31, wrp = tid >> 5;
    int hl = wrp >> 3, wq = wrp & 7, w0 = wq*16;
    if (tid < 16) sred[tid] = 0.f;

    int x = blockIdx.x;
    int dq = x & 3, hp = (x >> 2) & 31, b = x >> 7;
    int d0 = dq*6, h0 = hp*2;

    // zero all 4 plane slots once (halo cols + conv1's zero channels 8-15)
    for (int i = tid; i < 4*PLANE_B/4; i += 512) ((u32*)smem)[i] = 0u;

    // weights: [split][tap][oc16][ic16] bf16
    for (int i = tid; i < 27*256; i += 512) {
        int ic = i & 15, oc = (i >> 4) & 15, tap = i >> 8;
        float v = (ic < CIN) ? wts[(oc*CIN + ic)*27 + tap] : 0.f;
        __nv_bfloat16 hi = __float2bfloat16(v);
        __nv_bfloat16 lo = __float2bfloat16(v - __bfloat162float(hi));
        w_sm[i] = hi; w_sm[27*256 + i] = lo;
    }
    __syncthreads();

    auto stage = [&](int zd) {
        int slot = (zd - d0 + 1) & 3;
        bool pv = ((unsigned)zd < 24u);
        if (CIN == 8) {
            for (int it = tid; it < 1024; it += 512) {
                int ch = it & 1, w = (it >> 1) & 127, zhl = it >> 8;
                int zh = h0 - 1 + zhl;
                int r = zhl*130 + w + 1;
                u32 dst = a_base + slot*PLANE_B + (u32)r*ROW_B + (ch*2)*16;
                const void* src = (pv && (unsigned)zh < 64u)
                    ? (const void*)(g_cvp + ((((size_t)(b*24 + zd)*64 + zh)*128 + w)*32 + ch*16))
                    : (const void*)g_zerobuf;
                cp16(dst, src);
            }
        } else {
            for (int it = tid; it < 2048; it += 512) {
                int ch = it & 3, w = (it >> 2) & 127, zhl = it >> 9;
                int zh = h0 - 1 + zhl;
                int r = zhl*130 + w + 1;
                u32 dst = a_base + slot*PLANE_B + (u32)r*ROW_B + ch*16;
                const void* src = (pv && (unsigned)zh < 64u)
                    ? (const void*)(g_x1p + ((((size_t)(b*24 + zd)*64 + zh)*128 + w)*64 + ch*16))
                    : (const void*)g_zerobuf;
                cp16(dst, src);
            }
        }
    };

    float gsum[2] = {0.f, 0.f}, gss[2] = {0.f, 0.f};

    for (int pair = 0; pair < 3; pair++) {
        int d = d0 + 2*pair;
        if (pair == 0) {
            stage(d0 - 1); stage(d0); stage(d0 + 1); stage(d0 + 2);
        } else {
            stage(d + 1); stage(d + 2);
        }
        asm volatile("cp.async.commit_group;" ::: "memory");
        asm volatile("cp.async.wait_group 0;" ::: "memory");
        __syncthreads();

        float acc[2][2][4];   // [dd][oh][r]
#pragma unroll
        for (int dd = 0; dd < 2; dd++)
#pragma unroll
            for (int oh = 0; oh < 2; oh++)
#pragma unroll
                for (int r = 0; r < 4; r++) acc[dd][oh][r] = 0.f;

#pragma unroll
        for (int kh = 0; kh < 3; kh++) {
            int zhl = hl + kh;
#pragma unroll
            for (int kw = 0; kw < 3; kw++) {
                // B fragments for all 3 kd at this (kh,kw): 6 ldsm4
                u32 bfr[3][2][4];
                int m = lane >> 3;
#pragma unroll
                for (int kd = 0; kd < 3; kd++) {
                    int tap = kd*9 + kh*3 + kw;
#pragma unroll
                    for (int sp = 0; sp < 2; sp++) {
                        u32 ba = w_base + (u32)((sp*27 + tap)*256
                                  + ((m >> 1)*8 + (lane & 7))*16 + (m & 1)*8)*2;
                        ldsm4(ba, bfr[kd][sp][0], bfr[kd][sp][1], bfr[kd][sp][2], bfr[kd][sp][3]);
                    }
                }
                int r = zhl*130 + w0 + kw + (lane & 15);
                u32 rowoff = (u32)r*ROW_B + (lane >> 4)*16;
                // 4 resident planes q -> zd = d-1+q
#pragma unroll
                for (int q = 0; q < 4; q++) {
                    u32 pbase = a_base + (u32)((2*pair + q) & 3)*PLANE_B;
                    u32 ah = pbase + rowoff, al = ah + 32;
                    u32 h0r, h1r, h2r, h3r, l0r, l1r, l2r, l3r;
                    ldsm4(ah, h0r, h1r, h2r, h3r);
                    ldsm4(al, l0r, l1r, l2r, l3r);
                    if (q <= 2) {     // output d : kd = q
#pragma unroll
                        for (int oh = 0; oh < 2; oh++) {
                            mma16816(acc[0][oh], h0r, h1r, h2r, h3r, bfr[q][0][oh*2], bfr[q][0][oh*2+1]);
                            mma16816(acc[0][oh], h0r, h1r, h2r, h3r, bfr[q][1][oh*2], bfr[q][1][oh*2+1]);
                            mma16816(acc[0][oh], l0r, l1r, l2r, l3r, bfr[q][0][oh*2], bfr[q][0][oh*2+1]);
                        }
                    }
                    if (q >= 1) {     // output d+1 : kd = q-1
#pragma unroll
                        for (int oh = 0; oh < 2; oh++) {
                            mma16816(acc[1][oh], h0r, h1r, h2r, h3r, bfr[q-1][0][oh*2], bfr[q-1][0][oh*2+1]);
                            mma16816(acc[1][oh], h0r, h1r, h2r, h3r, bfr[q-1][1][oh*2], bfr[q-1][1][oh*2+1]);
                            mma16816(acc[1][oh], l0r, l1r, l2r, l3r, bfr[q-1][0][oh*2], bfr[q-1][0][oh*2+1]);
                        }
                    }
                }
            }
        }

        // epilogue: stats + bounce + store, per slice
#pragma unroll
        for (int dd = 0; dd < 2; dd++) {
#pragma unroll
            for (int oh = 0; oh < 2; oh++) {
                float s = 0.f, s2 = 0.f;
#pragma unroll
                for (int r = 0; r < 4; r++) { float v = acc[dd][oh][r]; s += v; s2 += v*v; }
                gsum[oh] += s; gss[oh] += s2;
            }
            __syncthreads();
#pragma unroll
            for (int oh = 0; oh < 2; oh++)
#pragma unroll
                for (int r = 0; r < 4; r++) {
                    int oc = oh*8 + (lane & 3)*2 + (r & 1);
                    int px = w0 + (lane >> 2) + (r >> 1)*8;
                    bounce[oc*260 + hl*128 + px] = acc[dd][oh][r];
                }
            __syncthreads();
            float* ob = out + ((size_t)b*16*DD + d + dd)*HW;
            for (int i = tid; i < 1024; i += 512) {
                int oc = i >> 6, rem = i & 63;
                int h2 = rem >> 5, w4 = rem & 31;
                float4 v = *(float4*)&bounce[oc*260 + h2*128 + w4*4];
                *(float4*)&ob[(size_t)oc*DD*HW + (h0 + h2)*WW + w4*4] = v;
            }
        }
        __syncthreads();
    }

    int g0 = lane & 3;
    atomicAdd(&sred[g0*2],         gsum[0]); atomicAdd(&sred[g0*2 + 1],         gss[0]);
    atomicAdd(&sred[(4 + g0)*2],   gsum[1]); atomicAdd(&sred[(4 + g0)*2 + 1],   gss[1]);
    __syncthreads();
    if (tid < 16) atomicAdd(&stats[b*16 + tid], (double)sred[tid]);
}

// ---------------- GN1 finalize + SiLU -> packed (proven, 55us) ----------------
__global__ void __launch_bounds__(256) k_norm_pack(const float* __restrict__ gw,
                                                   const float* __restrict__ gb) {
    __shared__ float sA[16], sB[16];
    int x = blockIdx.x;
    int hq = x & 31, d = (x >> 5) % 24, b = x / 768;
    int tid = threadIdx.x;
    if (tid < 16) {
        const double* p = g_stats + ((size_t)b*8 + (tid >> 1))*2;
        double mu = p[0] / 393216.0;
        double var = p[1] / 393216.0 - mu*mu;
        float rstd = rsqrtf((float)var + 1e-5f);
        float A = rstd * gw[tid];
        sA[tid] = A; sB[tid] = gb[tid] - (float)mu*A;
    }
    __syncthreads();
    int w = tid & 127, h = hq*2 + (tid >> 7);
    const float* base = g_x1 + ((size_t)b*16*DD + d)*HW + h*WW + w;
    u32 hiw[8], low[8];
#pragma unroll
    for (int j = 0; j < 8; j++) {
        float v0 = base[(size_t)(2*j)*DD*HW];
        float v1 = base[(size_t)(2*j + 1)*DD*HW];
        float t0 = v0*sA[2*j] + sB[2*j];
        float t1 = v1*sA[2*j + 1] + sB[2*j + 1];
        t0 = t0 / (1.f + __expf(-t0));
        t1 = t1 / (1.f + __expf(-t1));
        u16 h0b = bfb(t0), h1b = bfb(t1);
        u16 l0b = bfb(t0 - bff(h0b));
        u16 l1b = bfb(t1 - bff(h1b));
        hiw[j] = (u32)h0b | ((u32)h1b << 16);
        low[j] = (u32)l0b | ((u32)l1b << 16);
    }
    u32* dst = (u32*)(g_x1p + ((((size_t)(b*24 + d)*64 + h)*128 + w)*64));
    *(uint4*)dst        = make_uint4(hiw[0], hiw[1], hiw[2], hiw[3]);
    *(uint4*)(dst + 4)  = make_uint4(hiw[4], hiw[5], hiw[6], hiw[7]);
    *(uint4*)(dst + 8)  = make_uint4(low[0], low[1], low[2], low[3]);
    *(uint4*)(dst + 12) = make_uint4(low[4], low[5], low[6], low[7]);
}

// ---------------- GN finalize + apply + SiLU (layers 1,2) ----------------
__global__ void __launch_bounds__(256) k_norm(int which, float* outext,
                                              const float* __restrict__ gw,
                                              const float* __restrict__ gb,
                                              int nslab, float invN) {
    const float* in = (which == 1) ? g_x2 : g_feat;
    float* out = (which == 2) ? outext : g_x2n;
    const double* st = g_stats + which*128;
    __shared__ float sA, sB;
    int x = blockIdx.x;
    int s = x % nslab, c = (x / nslab) & 15, b = x / (nslab*16);
    if (threadIdx.x == 0) {
        const double* p = st + ((size_t)b*8 + (c >> 1))*2;
        double mu = p[0] * (double)invN;
        double var = p[1] * (double)invN - mu*mu;
        float rstd = rsqrtf((float)var + 1e-5f);
        float A = rstd * gw[c];
        sA = A; sB = gb[c] - (float)mu * A;
    }
    __syncthreads();
    float A = sA, Bv = sB;
    size_t base = ((size_t)(b*16 + c)*nslab + s)*8192;
    const float4* ip = (const float4*)(in + base);
    float4* op = (float4*)(out + base);
    for (int i = threadIdx.x; i < 2048; i += 256) {
        float4 v = ip[i];
        v.x = v.x*A + Bv; v.y = v.y*A + Bv; v.z = v.z*A + Bv; v.w = v.w*A + Bv;
        v.x = v.x / (1.f + __expf(-v.x));
        v.y = v.y / (1.f + __expf(-v.y));
        v.z = v.z / (1.f + __expf(-v.z));
        v.w = v.w / (1.f + __expf(-v.w));
        op[i] = v;
    }
}

// ---------------- conv3d oc=1 (FMA2, proven) ----------------
__global__ void __launch_bounds__(128) k_conv3d_oc1(const float* __restrict__ wts,
                                                    const float* __restrict__ bias) {
    __shared__ u64 swt[432];
    int tid = threadIdx.x;
    for (int i = tid; i < 432; i += 128) swt[i] = pk1(wts[i]);
    __syncthreads();
    int x = blockIdx.x;
    int ht = x & 7, d = (x >> 3) % 24, b = x / 192;
    int wt = tid & 15, hr = tid >> 4;
    int w0 = wt << 3, h = ht*8 + hr;
    u64 acc[4];
#pragma unroll
    for (int t = 0; t < 4; t++) acc[t] = 0ull;
    const float* inb = g_x2n + (size_t)b*16*DD*HW;
    for (int ic = 0; ic < 16; ic++) {
        const float* inc = inb + (size_t)ic*DD*HW;
#pragma unroll
        for (int kd = 0; kd < 3; kd++) {
            int zd = d + kd - 1;
            if ((unsigned)zd >= (unsigned)DD) continue;
#pragma unroll
            for (int kh = 0; kh < 3; kh++) {
                int zh = h + kh - 1;
                if ((unsigned)zh >= (unsigned)HH) continue;
                const float* row = inc + ((size_t)zd*HH + zh)*WW + w0;
                float r0 = (w0 == 0) ? 0.f : __ldg(row - 1);
                float4 va = *(const float4*)row;
                float4 vb = *(const float4*)(row + 4);
                float r9 = (w0 == 120) ? 0.f : __ldg(row + 8);
                u64 pe[5], po[4];
                pe[0] = pk(r0, va.x);  pe[1] = pk(va.y, va.z);
                pe[2] = pk(va.w, vb.x); pe[3] = pk(vb.y, vb.z);
                pe[4] = pk(vb.w, r9);
                po[0] = pk(va.x, va.y); po[1] = pk(va.z, va.w);
                po[2] = pk(vb.x, vb.y); po[3] = pk(vb.z, vb.w);
                int tb = (kd*3 + kh)*3;
                u64 wv0 = swt[ic*27 + tb + 0];
                u64 wv1 = swt[ic*27 + tb + 1];
                u64 wv2 = swt[ic*27 + tb + 2];
#pragma unroll
                for (int t = 0; t < 4; t++) {
                    fma2(acc[t], wv0, pe[t]);
                    fma2(acc[t], wv1, po[t]);
                    fma2(acc[t], wv2, pe[t + 1]);
                }
            }
        }
    }
    float bs = bias[0];
    float o[8];
#pragma unroll
    for (int t = 0; t < 4; t++) { float2 f = unpk(acc[t]); o[2*t] = f.x + bs; o[2*t+1] = f.y + bs; }
    float* orow = g_logits + (((size_t)b*DD + d)*HH + h)*WW + w0;
    *(float4*)orow       = make_float4(o[0], o[1], o[2], o[3]);
    *(float4*)(orow + 4) = make_float4(o[4], o[5], o[6], o[7]);
}

// ---------------- softmax (proven) ----------------
__global__ void __launch_bounds__(128) k_softmax(float* __restrict__ out) {
    int x = blockIdx.x;
    int h = x & 63, b = x >> 6;
    int w = threadIdx.x;
    const float* lp = g_logits + ((size_t)b*DD*HH + h)*WW + w;
    float l[DD];
    float m = -1e30f;
#pragma unroll
    for (int d = 0; d < DD; d++) { l[d] = lp[(size_t)d*HW]; m = fmaxf(m, l[d]); }
    float S = 0.f, E = 0.f;
#pragma unroll
    for (int d = 0; d < DD; d++) {
        float e = __expf(l[d] - m);
        S += e; E += e * (float)d;
    }
    float inv = 1.f / S;
    int oi = (b*HH + h)*WW + w;
    out[oi]           = E * inv;
    out[65536 + oi]   = 0.f;
    out[131072 + oi]  = 0.f;
    out[1245184 + oi] = inv;
}

// ---------------- feature head conv2d (FMA2, proven) ----------------
__global__ void __launch_bounds__(128, 3) k_conv2d_feat(const float* __restrict__ fL,
                                                        const float* __restrict__ wts) {
    __shared__ __align__(16) u64 swt[32*9*16];
    __shared__ float sred[16];
    int tid = threadIdx.x;
    if (tid < 16) sred[tid] = 0.f;
    int x = blockIdx.x;
    int wtile = x & 1, ht = (x >> 1) & 15, b = x >> 5;
    int wt = tid & 7, os = (tid >> 3) & 3, hr = tid >> 5;
    int w0 = wtile*64 + wt*8, h = ht*4 + hr, oc0 = os*4;
    u64 acc[4][4];
#pragma unroll
    for (int o = 0; o < 4; o++)
#pragma unroll
        for (int t = 0; t < 4; t++) acc[o][t] = 0ull;
    for (int p = 0; p < 4; p++) {
        __syncthreads();
        for (int i = tid; i < 32*144; i += 128) {
            int icl = i / 144; int r = i - icl*144; int tap = r >> 4; int oc = r & 15;
            swt[i] = pk1(wts[((size_t)oc*128 + p*32 + icl)*9 + tap]);
        }
        __syncthreads();
        for (int icl = 0; icl < 32; icl++) {
            int ic = p*32 + icl;
            const float* rowb = fL + ((size_t)(b*128 + ic)*HH)*WW;
#pragma unroll
            for (int kh = 0; kh < 3; kh++) {
                int zh = h + kh - 1;
                if ((unsigned)zh >= (unsigned)HH) continue;
                const float* row = rowb + (size_t)zh*WW + w0;
                float r0 = (w0 == 0) ? 0.f : __ldg(row - 1);
                float4 va = *(const float4*)row;
                float4 vb = *(const float4*)(row + 4);
                float r9 = (w0 == 120) ? 0.f : __ldg(row + 8);
                u64 pe[5], po[4];
                pe[0] = pk(r0, va.x);  pe[1] = pk(va.y, va.z);
                pe[2] = pk(va.w, vb.x); pe[3] = pk(vb.y, vb.z);
                pe[4] = pk(vb.w, r9);
                po[0] = pk(va.x, va.y); po[1] = pk(va.z, va.w);
                po[2] = pk(vb.x, vb.y); po[3] = pk(vb.z, vb.w);
                const u64* wbase = swt + (icl*9 + kh*3)*16 + oc0;
#pragma unroll
                for (int o = 0; o < 4; o++) {
                    u64 wv0 = wbase[o];
                    fma2(acc[o][0], wv0, pe[0]); fma2(acc[o][1], wv0, pe[1]);
                    fma2(acc[o][2], wv0, pe[2]); fma2(acc[o][3], wv0, pe[3]);
                }
#pragma unroll
                for (int o = 0; o < 4; o++) {
                    u64 wv1 = wbase[16 + o];
                    fma2(acc[o][0], wv1, po[0]); fma2(acc[o][1], wv1, po[1]);
                    fma2(acc[o][2], wv1, po[2]); fma2(acc[o][3], wv1, po[3]);
                }
#pragma unroll
                for (int o = 0; o < 4; o++) {
                    u64 wv2 = wbase[32 + o];
                    fma2(acc[o][0], wv2, pe[1]); fma2(acc[o][1], wv2, pe[2]);
                    fma2(acc[o][2], wv2, pe[3]); fma2(acc[o][3], wv2, pe[4]);
                }
            }
        }
    }
    float gs[2], gs2[2];
    gs[0] = gs[1] = gs2[0] = gs2[1] = 0.f;
#pragma unroll
    for (int o = 0; o < 4; o++) {
        float v[8];
#pragma unroll
        for (int t = 0; t < 4; t++) { float2 f = unpk(acc[o][t]); v[2*t] = f.x; v[2*t+1] = f.y; }
        int oc = oc0 + o;
        float* orow = g_feat + (((size_t)b*16 + oc)*HH + h)*WW + w0;
        *(float4*)orow       = make_float4(v[0], v[1], v[2], v[3]);
        *(float4*)(orow + 4) = make_float4(v[4], v[5], v[6], v[7]);
        float s = 0.f, s2 = 0.f;
#pragma unroll
        for (int j = 0; j < 8; j++) { s += v[j]; s2 += v[j]*v[j]; }
        gs[o >> 1] += s; gs2[o >> 1] += s2;
    }
#pragma unroll
    for (int i = 0; i < 2; i++) {
        int grp = os*2 + i;
        atomicAdd(&sred[grp*2],     gs[i]);
        atomicAdd(&sred[grp*2 + 1], gs2[i]);
    }
    __syncthreads();
    if (tid < 16) atomicAdd(&g_stats[2*128 + b*16 + tid], (double)sred[tid]);
}

// ---------------- launch ----------------
extern "C" void kernel_launch(void* const* d_in, const int* in_sizes, int n_in,
                              void* d_out, int out_size) {
    const float* fL    = (const float*)d_in[0];
    const float* fR    = (const float*)d_in[1];
    const float* w1    = (const float*)d_in[2];
    const float* gn1w  = (const float*)d_in[3];
    const float* gn1b  = (const float*)d_in[4];
    const float* w2    = (const float*)d_in[5];
    const float* gn2w  = (const float*)d_in[6];
    const float* gn2b  = (const float*)d_in[7];
    const float* w3    = (const float*)d_in[8];
    const float* b3    = (const float*)d_in[9];
    const float* fhw   = (const float*)d_in[10];
    const float* fhgnw = (const float*)d_in[11];
    const float* fhgnb = (const float*)d_in[12];
    float* out = (float*)d_out;

    const float invN3d = 1.0f / (2.0f*DD*HH*WW);
    const float invN2d = 1.0f / (2.0f*HH*WW);

    cudaFuncSetAttribute(k_costvol,     cudaFuncAttributeMaxDynamicSharedMemorySize, 131072);
    cudaFuncSetAttribute(k_conv_tc<8>,  cudaFuncAttributeMaxDynamicSharedMemorySize, CONV_SMEM);
    cudaFuncSetAttribute(k_conv_tc<16>, cudaFuncAttributeMaxDynamicSharedMemorySize, CONV_SMEM);

    k_zero_stats<<<1, 384>>>();                                  // 0
    k_costvol<<<BATCH*HH, 256, 131072>>>(fL, fR);                // 1
    k_zero_stats<<<1, 384>>>();                                  // 2 (dummy)
    k_conv_tc<8><<<1024, 512, CONV_SMEM>>>(w1);                  // 3 <-- profiled
    k_norm_pack<<<BATCH*24*32, 256>>>(gn1w, gn1b);               // 4
    k_conv_tc<16><<<1024, 512, CONV_SMEM>>>(w2);                 // 5
    k_norm<<<BATCH*16*24, 256>>>(1, nullptr, gn2w, gn2b, 24, invN3d);  // 6
    k_conv3d_oc1<<<BATCH*24*8, 128>>>(w3, b3);                   // 7
    k_softmax<<<BATCH*HH, 128>>>(out);                           // 8
    k_conv2d_feat<<<BATCH*16*2, 128>>>(fL, fhw);                 // 9
    k_norm<<<BATCH*16, 256>>>(2, out + 196608, fhgnw, fhgnb, 1, invN2d); // 10
}

// round 12
// speedup vs baseline: 1.5616x; 1.0201x over previous
#include <cuda_runtime.h>
#include <cuda_bf16.h>
#include <math.h>

#define BATCH 8
#define DD 24
#define HH 64
#define WW 128
#define HW (HH*WW)

typedef unsigned long long u64;
typedef unsigned int u32;
typedef unsigned short u16;

// ---------------- packed fp32x2 helpers ----------------
__device__ __forceinline__ u64 pk(float lo, float hi) {
    u64 r; asm("mov.b64 %0, {%1,%2};" : "=l"(r) : "f"(lo), "f"(hi)); return r;
}
__device__ __forceinline__ u64 pk1(float v) { return pk(v, v); }
__device__ __forceinline__ void fma2(u64& d, u64 a, u64 b) {
    asm("fma.rn.f32x2 %0, %1, %2, %0;" : "+l"(d) : "l"(a), "l"(b));
}
__device__ __forceinline__ float2 unpk(u64 v) {
    float2 f; asm("mov.b64 {%0,%1}, %2;" : "=f"(f.x), "=f"(f.y) : "l"(v)); return f;
}

// ---------------- mma / ldmatrix helpers ----------------
__device__ __forceinline__ u32 smem_u32(const void* p) {
    u32 a; asm("{ .reg .u64 t; cvta.to.shared.u64 t, %1; cvt.u32.u64 %0, t; }" : "=r"(a) : "l"(p));
    return a;
}
__device__ __forceinline__ void ldsm4(u32 a, u32& r0, u32& r1, u32& r2, u32& r3) {
    asm volatile("ldmatrix.sync.aligned.m8n8.x4.shared.b16 {%0,%1,%2,%3}, [%4];"
                 : "=r"(r0), "=r"(r1), "=r"(r2), "=r"(r3) : "r"(a));
}
__device__ __forceinline__ void mma16816(float* d, u32 a0, u32 a1, u32 a2, u32 a3, u32 b0, u32 b1) {
    asm volatile("mma.sync.aligned.m16n8k16.row.col.f32.bf16.bf16.f32 "
                 "{%0,%1,%2,%3}, {%4,%5,%6,%7}, {%8,%9}, {%0,%1,%2,%3};"
                 : "+f"(d[0]), "+f"(d[1]), "+f"(d[2]), "+f"(d[3])
                 : "r"(a0), "r"(a1), "r"(a2), "r"(a3), "r"(b0), "r"(b1));
}
__device__ __forceinline__ void cp16(u32 dst, const void* src) {
    asm volatile("cp.async.ca.shared.global [%0], [%1], 16;" :: "r"(dst), "l"(src));
}
__device__ __forceinline__ u16 bfb(float f) {
    return __bfloat16_as_ushort(__float2bfloat16(f));
}
__device__ __forceinline__ float bff(u16 b) {
    return __bfloat162float(__ushort_as_bfloat16(b));
}

// ---------------- scratch ----------------
__device__ __align__(16) char g_cvp[(size_t)BATCH*DD*HH*WW*32];  // packed cost volume, 32B/voxel
__device__ float g_x1[BATCH*16*DD*HH*WW];
__device__ __align__(16) char g_x1p[(size_t)BATCH*DD*HH*WW*64];  // packed x1n, 64B/voxel
__device__ float g_x2[BATCH*16*DD*HH*WW];
__device__ float g_x2n[BATCH*16*DD*HH*WW];
__device__ float g_logits[BATCH*DD*HH*WW];
__device__ float g_feat[BATCH*16*HH*WW];
__device__ double g_stats[3*BATCH*8*2];
__device__ __align__(16) float g_zerobuf[4];   // zero-initialized

__global__ void k_zero_stats() {
    int i = threadIdx.x;
    if (i < 3*BATCH*8*2) g_stats[i] = 0.0;
}

// ---------------- cost volume -> packed bf16 hi/lo channels-last (proven) ----------------
__global__ void __launch_bounds__(256) k_costvol(const float* __restrict__ fL,
                                                 const float* __restrict__ fR) {
    extern __shared__ float scv[];
    float* sL = scv;
    float* sR = scv + 16384;
    int b = blockIdx.x >> 6, h = blockIdx.x & 63;
    int tid = threadIdx.x;
    for (int i = tid; i < 16384; i += 256) {
        size_t gidx = ((size_t)(b*128 + (i >> 7))*HH + h)*WW + (i & 127);
        sL[i] = fL[gidx];
        sR[i] = fR[gidx];
    }
    __syncthreads();
    int w = tid & 127, dh = tid >> 7;
    for (int dl = 0; dl < 12; dl++) {
        int d = dh*12 + dl;
        u32 hiw[4], low[4];
#pragma unroll
        for (int gp = 0; gp < 4; gp++) {
            float s0 = 0.f, s1 = 0.f;
            if (w >= d) {
                const float* pL = sL + gp*32*128 + w;
                const float* pR = sR + gp*32*128 + w - d;
#pragma unroll
                for (int c = 0; c < 16; c++) {
                    s0 += pL[c*128] * pR[c*128];
                    s1 += pL[(16 + c)*128] * pR[(16 + c)*128];
                }
                s0 *= 0.0625f; s1 *= 0.0625f;
            }
            u16 h0 = bfb(s0), h1 = bfb(s1);
            u16 l0 = bfb(s0 - bff(h0)), l1 = bfb(s1 - bff(h1));
            hiw[gp] = (u32)h0 | ((u32)h1 << 16);
            low[gp] = (u32)l0 | ((u32)l1 << 16);
        }
        char* vox = g_cvp + ((((size_t)(b*24 + d)*64 + h)*128 + w)*32);
        *(uint4*)vox        = make_uint4(hiw[0], hiw[1], hiw[2], hiw[3]);
        *(uint4*)(vox + 16) = make_uint4(low[0], low[1], low[2], low[3]);
    }
}

// ================= tensor-core conv3d: d-pairs, W split, 2 CTAs/SM =========
// grid = B*32*4*2 (b, h-pair, d-sixth, w-half), block = 256 (8 warps)
#define ROW_B   80
#define NCOL    66
#define PLANE_B (264*ROW_B)          // 21120
#define W_OFF   (4*PLANE_B)          // 84480
#define CONV_SMEM (W_OFF + 27648)    // 112128 -> 2 CTAs/SM

template<int CIN>
__global__ void __launch_bounds__(256) k_conv_tc(const float* __restrict__ wts) {
    float* out = (CIN == 8) ? g_x1 : g_x2;
    double* stats = g_stats + ((CIN == 8) ? 0 : 1)*128;

    extern __shared__ char smem[];
    __nv_bfloat16* w_sm = (__nv_bfloat16*)(smem + W_OFF);
    __shared__ float sred[16];

    u32 a_base = smem_u32(smem);
    u32 w_base = smem_u32(w_sm);
    int tid = threadIdx.x, lane = tid & 31, wrp = tid >> 5;
    int hl = wrp >> 2, wq = wrp & 3, w0l = wq*16;
    if (tid < 16) sred[tid] = 0.f;

    int x = blockIdx.x;
    int wt = x & 1, dq = (x >> 1) & 3, hp = (x >> 3) & 31, b = x >> 8;
    int d0 = dq*6, h0 = hp*2, wg0 = wt*64;

    // zero all 4 plane slots once
    for (int i = tid; i < 4*PLANE_B/4; i += 256) ((u32*)smem)[i] = 0u;

    // weights: [split][tap][oc16][ic16] bf16
    for (int i = tid; i < 27*256; i += 256) {
        int ic = i & 15, oc = (i >> 4) & 15, tap = i >> 8;
        float v = (ic < CIN) ? wts[(oc*CIN + ic)*27 + tap] : 0.f;
        __nv_bfloat16 hi = __float2bfloat16(v);
        __nv_bfloat16 lo = __float2bfloat16(v - __bfloat162float(hi));
        w_sm[i] = hi; w_sm[27*256 + i] = lo;
    }
    __syncthreads();

    // stage fully rewrites bytes 0..63 of every row (bounce aliasing requires this!)
    auto stage = [&](int zd) {
        int slot = (zd - d0 + 1) & 3;
        bool pv = ((unsigned)zd < 24u);
        for (int it = tid; it < 1056; it += 256) {
            int ch = it & 3;
            int t2 = it >> 2;            // 0..263
            int zhl = t2 / 66;
            int wl = t2 - zhl*66;
            int zh = h0 - 1 + zhl;
            int wgl = wg0 + wl - 1;
            u32 dst = a_base + slot*PLANE_B + (u32)t2*ROW_B + ch*16;
            const void* src;
            if (CIN == 8) {
                // chunks: 0 = hi ch0-7 (cvp+0), 1 = hi ch8-15 (zeros),
                //         2 = lo ch0-7 (cvp+16), 3 = lo ch8-15 (zeros)
                if ((ch & 1) || !(pv && (unsigned)zh < 64u && (unsigned)wgl < 128u))
                    src = (const void*)g_zerobuf;
                else
                    src = (const void*)(g_cvp + ((((size_t)(b*24 + zd)*64 + zh)*128 + wgl)*32 + (ch >> 1)*16));
            } else {
                src = (pv && (unsigned)zh < 64u && (unsigned)wgl < 128u)
                    ? (const void*)(g_x1p + ((((size_t)(b*24 + zd)*64 + zh)*128 + wgl)*64 + ch*16))
                    : (const void*)g_zerobuf;
            }
            cp16(dst, src);
        }
    };

    float gsum[2] = {0.f, 0.f}, gss[2] = {0.f, 0.f};

    for (int pair = 0; pair < 3; pair++) {
        int d = d0 + 2*pair;
        if (pair == 0) {
            stage(d0 - 1); stage(d0); stage(d0 + 1); stage(d0 + 2);
        } else {
            stage(d + 1); stage(d + 2);
        }
        asm volatile("cp.async.commit_group;" ::: "memory");
        asm volatile("cp.async.wait_group 0;" ::: "memory");
        __syncthreads();

        float acc[2][2][4];   // [dd][oh][r]
#pragma unroll
        for (int dd = 0; dd < 2; dd++)
#pragma unroll
            for (int oh = 0; oh < 2; oh++)
#pragma unroll
                for (int r = 0; r < 4; r++) acc[dd][oh][r] = 0.f;

#pragma unroll
        for (int kh = 0; kh < 3; kh++) {
            int zhl = hl + kh;
#pragma unroll
            for (int kw = 0; kw < 3; kw++) {
                u32 bfr[3][2][4];
                int m = lane >> 3;
#pragma unroll
                for (int kd = 0; kd < 3; kd++) {
                    int tap = kd*9 + kh*3 + kw;
#pragma unroll
                    for (int sp = 0; sp < 2; sp++) {
                        u32 ba = w_base + (u32)((sp*27 + tap)*256
                                  + ((m >> 1)*8 + (lane & 7))*16 + (m & 1)*8)*2;
                        ldsm4(ba, bfr[kd][sp][0], bfr[kd][sp][1], bfr[kd][sp][2], bfr[kd][sp][3]);
                    }
                }
                int r = zhl*66 + w0l + (lane & 15) + kw;
                u32 rowoff = (u32)r*ROW_B + (lane >> 4)*16;
#pragma unroll
                for (int q = 0; q < 4; q++) {
                    u32 pbase = a_base + (u32)((2*pair + q) & 3)*PLANE_B;
                    u32 ah = pbase + rowoff, al = ah + 32;
                    u32 h0r, h1r, h2r, h3r, l0r, l1r, l2r, l3r;
                    ldsm4(ah, h0r, h1r, h2r, h3r);
                    ldsm4(al, l0r, l1r, l2r, l3r);
                    if (q <= 2) {
#pragma unroll
                        for (int oh = 0; oh < 2; oh++) {
                            mma16816(acc[0][oh], h0r, h1r, h2r, h3r, bfr[q][0][oh*2], bfr[q][0][oh*2+1]);
                            mma16816(acc[0][oh], h0r, h1r, h2r, h3r, bfr[q][1][oh*2], bfr[q][1][oh*2+1]);
                            mma16816(acc[0][oh], l0r, l1r, l2r, l3r, bfr[q][0][oh*2], bfr[q][0][oh*2+1]);
                        }
                    }
                    if (q >= 1) {
#pragma unroll
                        for (int oh = 0; oh < 2; oh++) {
                            mma16816(acc[1][oh], h0r, h1r, h2r, h3r, bfr[q-1][0][oh*2], bfr[q-1][0][oh*2+1]);
                            mma16816(acc[1][oh], h0r, h1r, h2r, h3r, bfr[q-1][1][oh*2], bfr[q-1][1][oh*2+1]);
                            mma16816(acc[1][oh], l0r, l1r, l2r, l3r, bfr[q-1][0][oh*2], bfr[q-1][0][oh*2+1]);
                        }
                    }
                }
            }
        }

        // stats
#pragma unroll
        for (int dd = 0; dd < 2; dd++)
#pragma unroll
            for (int oh = 0; oh < 2; oh++) {
                float s = 0.f, s2 = 0.f;
#pragma unroll
                for (int r = 0; r < 4; r++) { float v = acc[dd][oh][r]; s += v; s2 += v*v; }
                gsum[oh] += s; gss[oh] += s2;
            }

        // bounce into the two retiring plane slots (free smem), then coalesced store
        __syncthreads();   // all MMAs done; slots (2p)&3, (2p+1)&3 retire
#pragma unroll
        for (int dd = 0; dd < 2; dd++) {
            float* bounce = (float*)(smem + ((2*pair + dd) & 3)*PLANE_B);
#pragma unroll
            for (int oh = 0; oh < 2; oh++)
#pragma unroll
                for (int r = 0; r < 4; r++) {
                    int oc = oh*8 + (lane & 3)*2 + (r & 1);
                    int px = w0l + (lane >> 2) + (r >> 1)*8;
                    bounce[oc*132 + hl*64 + px] = acc[dd][oh][r];
                }
        }
        __syncthreads();
        for (int i = tid; i < 1024; i += 256) {
            int dd = i >> 9, rem9 = i & 511;
            int oc = rem9 >> 5, rem = rem9 & 31;
            int h2 = rem >> 4, w4 = rem & 15;
            const float* bounce = (const float*)(smem + ((2*pair + dd) & 3)*PLANE_B);
            float4 v = *(const float4*)&bounce[oc*132 + h2*64 + w4*4];
            float* ob = out + ((size_t)b*16*DD + d + dd)*HW;
            *(float4*)&ob[(size_t)oc*DD*HW + (h0 + h2)*WW + wg0 + w4*4] = v;
        }
        __syncthreads();   // stores done before next pair's staging overwrites slots
    }

    int g0 = lane & 3;
    atomicAdd(&sred[g0*2],         gsum[0]); atomicAdd(&sred[g0*2 + 1],         gss[0]);
    atomicAdd(&sred[(4 + g0)*2],   gsum[1]); atomicAdd(&sred[(4 + g0)*2 + 1],   gss[1]);
    __syncthreads();
    if (tid < 16) atomicAdd(&stats[b*16 + tid], (double)sred[tid]);
}

// ---------------- GN1 finalize + SiLU -> packed (proven, 55us) ----------------
__global__ void __launch_bounds__(256) k_norm_pack(const float* __restrict__ gw,
                                                   const float* __restrict__ gb) {
    __shared__ float sA[16], sB[16];
    int x = blockIdx.x;
    int hq = x & 31, d = (x >> 5) % 24, b = x / 768;
    int tid = threadIdx.x;
    if (tid < 16) {
        const double* p = g_stats + ((size_t)b*8 + (tid >> 1))*2;
        double mu = p[0] / 393216.0;
        double var = p[1] / 393216.0 - mu*mu;
        float rstd = rsqrtf((float)var + 1e-5f);
        float A = rstd * gw[tid];
        sA[tid] = A; sB[tid] = gb[tid] - (float)mu*A;
    }
    __syncthreads();
    int w = tid & 127, h = hq*2 + (tid >> 7);
    const float* base = g_x1 + ((size_t)b*16*DD + d)*HW + h*WW + w;
    u32 hiw[8], low[8];
#pragma unroll
    for (int j = 0; j < 8; j++) {
        float v0 = base[(size_t)(2*j)*DD*HW];
        float v1 = base[(size_t)(2*j + 1)*DD*HW];
        float t0 = v0*sA[2*j] + sB[2*j];
        float t1 = v1*sA[2*j + 1] + sB[2*j + 1];
        t0 = t0 / (1.f + __expf(-t0));
        t1 = t1 / (1.f + __expf(-t1));
        u16 h0b = bfb(t0), h1b = bfb(t1);
        u16 l0b = bfb(t0 - bff(h0b));
        u16 l1b = bfb(t1 - bff(h1b));
        hiw[j] = (u32)h0b | ((u32)h1b << 16);
        low[j] = (u32)l0b | ((u32)l1b << 16);
    }
    u32* dst = (u32*)(g_x1p + ((((size_t)(b*24 + d)*64 + h)*128 + w)*64));
    *(uint4*)dst        = make_uint4(hiw[0], hiw[1], hiw[2], hiw[3]);
    *(uint4*)(dst + 4)  = make_uint4(hiw[4], hiw[5], hiw[6], hiw[7]);
    *(uint4*)(dst + 8)  = make_uint4(low[0], low[1], low[2], low[3]);
    *(uint4*)(dst + 12) = make_uint4(low[4], low[5], low[6], low[7]);
}

// ---------------- GN finalize + apply + SiLU (layers 1,2) ----------------
__global__ void __launch_bounds__(256) k_norm(int which, float* outext,
                                              const float* __restrict__ gw,
                                              const float* __restrict__ gb,
                                              int nslab, float invN) {
    const float* in = (which == 1) ? g_x2 : g_feat;
    float* out = (which == 2) ? outext : g_x2n;
    const double* st = g_stats + which*128;
    __shared__ float sA, sB;
    int x = blockIdx.x;
    int s = x % nslab, c = (x / nslab) & 15, b = x / (nslab*16);
    if (threadIdx.x == 0) {
        const double* p = st + ((size_t)b*8 + (c >> 1))*2;
        double mu = p[0] * (double)invN;
        double var = p[1] * (double)invN - mu*mu;
        float rstd = rsqrtf((float)var + 1e-5f);
        float A = rstd * gw[c];
        sA = A; sB = gb[c] - (float)mu * A;
    }
    __syncthreads();
    float A = sA, Bv = sB;
    size_t base = ((size_t)(b*16 + c)*nslab + s)*8192;
    const float4* ip = (const float4*)(in + base);
    float4* op = (float4*)(out + base);
    for (int i = threadIdx.x; i < 2048; i += 256) {
        float4 v = ip[i];
        v.x = v.x*A + Bv; v.y = v.y*A + Bv; v.z = v.z*A + Bv; v.w = v.w*A + Bv;
        v.x = v.x / (1.f + __expf(-v.x));
        v.y = v.y / (1.f + __expf(-v.y));
        v.z = v.z / (1.f + __expf(-v.z));
        v.w = v.w / (1.f + __expf(-v.w));
        op[i] = v;
    }
}

// ---------------- conv3d oc=1 (FMA2, proven) ----------------
__global__ void __launch_bounds__(128) k_conv3d_oc1(const float* __restrict__ wts,
                                                    const float* __restrict__ bias) {
    __shared__ u64 swt[432];
    int tid = threadIdx.x;
    for (int i = tid; i < 432; i += 128) swt[i] = pk1(wts[i]);
    __syncthreads();
    int x = blockIdx.x;
    int ht = x & 7, d = (x >> 3) % 24, b = x / 192;
    int wt = tid & 15, hr = tid >> 4;
    int w0 = wt << 3, h = ht*8 + hr;
    u64 acc[4];
#pragma unroll
    for (int t = 0; t < 4; t++) acc[t] = 0ull;
    const float* inb = g_x2n + (size_t)b*16*DD*HW;
    for (int ic = 0; ic < 16; ic++) {
        const float* inc = inb + (size_t)ic*DD*HW;
#pragma unroll
        for (int kd = 0; kd < 3; kd++) {
            int zd = d + kd - 1;
            if ((unsigned)zd >= (unsigned)DD) continue;
#pragma unroll
            for (int kh = 0; kh < 3; kh++) {
                int zh = h + kh - 1;
                if ((unsigned)zh >= (unsigned)HH) continue;
                const float* row = inc + ((size_t)zd*HH + zh)*WW + w0;
                float r0 = (w0 == 0) ? 0.f : __ldg(row - 1);
                float4 va = *(const float4*)row;
                float4 vb = *(const float4*)(row + 4);
                float r9 = (w0 == 120) ? 0.f : __ldg(row + 8);
                u64 pe[5], po[4];
                pe[0] = pk(r0, va.x);  pe[1] = pk(va.y, va.z);
                pe[2] = pk(va.w, vb.x); pe[3] = pk(vb.y, vb.z);
                pe[4] = pk(vb.w, r9);
                po[0] = pk(va.x, va.y); po[1] = pk(va.z, va.w);
                po[2] = pk(vb.x, vb.y); po[3] = pk(vb.z, vb.w);
                int tb = (kd*3 + kh)*3;
                u64 wv0 = swt[ic*27 + tb + 0];
                u64 wv1 = swt[ic*27 + tb + 1];
                u64 wv2 = swt[ic*27 + tb + 2];
#pragma unroll
                for (int t = 0; t < 4; t++) {
                    fma2(acc[t], wv0, pe[t]);
                    fma2(acc[t], wv1, po[t]);
                    fma2(acc[t], wv2, pe[t + 1]);
                }
            }
        }
    }
    float bs = bias[0];
    float o[8];
#pragma unroll
    for (int t = 0; t < 4; t++) { float2 f = unpk(acc[t]); o[2*t] = f.x + bs; o[2*t+1] = f.y + bs; }
    float* orow = g_logits + (((size_t)b*DD + d)*HH + h)*WW + w0;
    *(float4*)orow       = make_float4(o[0], o[1], o[2], o[3]);
    *(float4*)(orow + 4) = make_float4(o[4], o[5], o[6], o[7]);
}

// ---------------- softmax (proven) ----------------
__global__ void __launch_bounds__(128) k_softmax(float* __restrict__ out) {
    int x = blockIdx.x;
    int h = x & 63, b = x >> 6;
    int w = threadIdx.x;
    const float* lp = g_logits + ((size_t)b*DD*HH + h)*WW + w;
    float l[DD];
    float m = -1e30f;
#pragma unroll
    for (int d = 0; d < DD; d++) { l[d] = lp[(size_t)d*HW]; m = fmaxf(m, l[d]); }
    float S = 0.f, E = 0.f;
#pragma unroll
    for (int d = 0; d < DD; d++) {
        float e = __expf(l[d] - m);
        S += e; E += e * (float)d;
    }
    float inv = 1.f / S;
    int oi = (b*HH + h)*WW + w;
    out[oi]           = E * inv;
    out[65536 + oi]   = 0.f;
    out[131072 + oi]  = 0.f;
    out[1245184 + oi] = inv;
}

// ---------------- feature head conv2d (FMA2, proven) ----------------
__global__ void __launch_bounds__(128, 3) k_conv2d_feat(const float* __restrict__ fL,
                                                        const float* __restrict__ wts) {
    __shared__ __align__(16) u64 swt[32*9*16];
    __shared__ float sred[16];
    int tid = threadIdx.x;
    if (tid < 16) sred[tid] = 0.f;
    int x = blockIdx.x;
    int wtile = x & 1, ht = (x >> 1) & 15, b = x >> 5;
    int wt = tid & 7, os = (tid >> 3) & 3, hr = tid >> 5;
    int w0 = wtile*64 + wt*8, h = ht*4 + hr, oc0 = os*4;
    u64 acc[4][4];
#pragma unroll
    for (int o = 0; o < 4; o++)
#pragma unroll
        for (int t = 0; t < 4; t++) acc[o][t] = 0ull;
    for (int p = 0; p < 4; p++) {
        __syncthreads();
        for (int i = tid; i < 32*144; i += 128) {
            int icl = i / 144; int r = i - icl*144; int tap = r >> 4; int oc = r & 15;
            swt[i] = pk1(wts[((size_t)oc*128 + p*32 + icl)*9 + tap]);
        }
        __syncthreads();
        for (int icl = 0; icl < 32; icl++) {
            int ic = p*32 + icl;
            const float* rowb = fL + ((size_t)(b*128 + ic)*HH)*WW;
#pragma unroll
            for (int kh = 0; kh < 3; kh++) {
                int zh = h + kh - 1;
                if ((unsigned)zh >= (unsigned)HH) continue;
                const float* row = rowb + (size_t)zh*WW + w0;
                float r0 = (w0 == 0) ? 0.f : __ldg(row - 1);
                float4 va = *(const float4*)row;
                float4 vb = *(const float4*)(row + 4);
                float r9 = (w0 == 120) ? 0.f : __ldg(row + 8);
                u64 pe[5], po[4];
                pe[0] = pk(r0, va.x);  pe[1] = pk(va.y, va.z);
                pe[2] = pk(va.w, vb.x); pe[3] = pk(vb.y, vb.z);
                pe[4] = pk(vb.w, r9);
                po[0] = pk(va.x, va.y); po[1] = pk(va.z, va.w);
                po[2] = pk(vb.x, vb.y); po[3] = pk(vb.z, vb.w);
                const u64* wbase = swt + (icl*9 + kh*3)*16 + oc0;
#pragma unroll
                for (int o = 0; o < 4; o++) {
                    u64 wv0 = wbase[o];
                    fma2(acc[o][0], wv0, pe[0]); fma2(acc[o][1], wv0, pe[1]);
                    fma2(acc[o][2], wv0, pe[2]); fma2(acc[o][3], wv0, pe[3]);
                }
#pragma unroll
                for (int o = 0; o < 4; o++) {
                    u64 wv1 = wbase[16 + o];
                    fma2(acc[o][0], wv1, po[0]); fma2(acc[o][1], wv1, po[1]);
                    fma2(acc[o][2], wv1, po[2]); fma2(acc[o][3], wv1, po[3]);
                }
#pragma unroll
                for (int o = 0; o < 4; o++) {
                    u64 wv2 = wbase[32 + o];
                    fma2(acc[o][0], wv2, pe[1]); fma2(acc[o][1], wv2, pe[2]);
                    fma2(acc[o][2], wv2, pe[3]); fma2(acc[o][3], wv2, pe[4]);
                }
            }
        }
    }
    float gs[2], gs2[2];
    gs[0] = gs[1] = gs2[0] = gs2[1] = 0.f;
#pragma unroll
    for (int o = 0; o < 4; o++) {
        float v[8];
#pragma unroll
        for (int t = 0; t < 4; t++) { float2 f = unpk(acc[o][t]); v[2*t] = f.x; v[2*t+1] = f.y; }
        int oc = oc0 + o;
        float* orow = g_feat + (((size_t)b*16 + oc)*HH + h)*WW + w0;
        *(float4*)orow       = make_float4(v[0], v[1], v[2], v[3]);
        *(float4*)(orow + 4) = make_float4(v[4], v[5], v[6], v[7]);
        float s = 0.f, s2 = 0.f;
#pragma unroll
        for (int j = 0; j < 8; j++) { s += v[j]; s2 += v[j]*v[j]; }
        gs[o >> 1] += s; gs2[o >> 1] += s2;
    }
#pragma unroll
    for (int i = 0; i < 2; i++) {
        int grp = os*2 + i;
        atomicAdd(&sred[grp*2],     gs[i]);
        atomicAdd(&sred[grp*2 + 1], gs2[i]);
    }
    __syncthreads();
    if (tid < 16) atomicAdd(&g_stats[2*128 + b*16 + tid], (double)sred[tid]);
}

// ---------------- launch ----------------
extern "C" void kernel_launch(void* const* d_in, const int* in_sizes, int n_in,
                              void* d_out, int out_size) {
    const float* fL    = (const float*)d_in[0];
    const float* fR    = (const float*)d_in[1];
    const float* w1    = (const float*)d_in[2];
    const float* gn1w  = (const float*)d_in[3];
    const float* gn1b  = (const float*)d_in[4];
    const float* w2    = (const float*)d_in[5];
    const float* gn2w  = (const float*)d_in[6];
    const float* gn2b  = (const float*)d_in[7];
    const float* w3    = (const float*)d_in[8];
    const float* b3    = (const float*)d_in[9];
    const float* fhw   = (const float*)d_in[10];
    const float* fhgnw = (const float*)d_in[11];
    const float* fhgnb = (const float*)d_in[12];
    float* out = (float*)d_out;

    const float invN3d = 1.0f / (2.0f*DD*HH*WW);
    const float invN2d = 1.0f / (2.0f*HH*WW);

    cudaFuncSetAttribute(k_costvol,     cudaFuncAttributeMaxDynamicSharedMemorySize, 131072);
    cudaFuncSetAttribute(k_conv_tc<8>,  cudaFuncAttributeMaxDynamicSharedMemorySize, CONV_SMEM);
    cudaFuncSetAttribute(k_conv_tc<16>, cudaFuncAttributeMaxDynamicSharedMemorySize, CONV_SMEM);

    k_zero_stats<<<1, 384>>>();                                  // 0
    k_costvol<<<BATCH*HH, 256, 131072>>>(fL, fR);                // 1
    k_zero_stats<<<1, 384>>>();                                  // 2 (dummy)
    k_conv_tc<8><<<2048, 256, CONV_SMEM>>>(w1);                  // 3 <-- profiled
    k_norm_pack<<<BATCH*24*32, 256>>>(gn1w, gn1b);               // 4
    k_conv_tc<16><<<2048, 256, CONV_SMEM>>>(w2);                 // 5
    k_norm<<<BATCH*16*24, 256>>>(1, nullptr, gn2w, gn2b, 24, invN3d);  // 6
    k_conv3d_oc1<<<BATCH*24*8, 128>>>(w3, b3);                   // 7
    k_softmax<<<BATCH*HH, 128>>>(out);                           // 8
    k_conv2d_feat<<<BATCH*16*2, 128>>>(fL, fhw);                 // 9
    k_norm<<<BATCH*16, 256>>>(2, out + 196608, fhgnw, fhgnb, 1, invN2d); // 10
}

// round 13
// speedup vs baseline: 2.0805x; 1.3323x over previous
#include <cuda_runtime.h>
#include <cuda_fp16.h>
#include <math.h>

#define BATCH 8
#define DD 24
#define HH 64
#define WW 128
#define HW (HH*WW)

typedef unsigned long long u64;
typedef unsigned int u32;
typedef unsigned short u16;

// ---------------- packed fp32x2 helpers ----------------
__device__ __forceinline__ u64 pk(float lo, float hi) {
    u64 r; asm("mov.b64 %0, {%1,%2};" : "=l"(r) : "f"(lo), "f"(hi)); return r;
}
__device__ __forceinline__ u64 pk1(float v) { return pk(v, v); }
__device__ __forceinline__ void fma2(u64& d, u64 a, u64 b) {
    asm("fma.rn.f32x2 %0, %1, %2, %0;" : "+l"(d) : "l"(a), "l"(b));
}
__device__ __forceinline__ float2 unpk(u64 v) {
    float2 f; asm("mov.b64 {%0,%1}, %2;" : "=f"(f.x), "=f"(f.y) : "l"(v)); return f;
}

// ---------------- mma / ldmatrix helpers ----------------
__device__ __forceinline__ u32 smem_u32(const void* p) {
    u32 a; asm("{ .reg .u64 t; cvta.to.shared.u64 t, %1; cvt.u32.u64 %0, t; }" : "=r"(a) : "l"(p));
    return a;
}
__device__ __forceinline__ void ldsm4(u32 a, u32& r0, u32& r1, u32& r2, u32& r3) {
    asm volatile("ldmatrix.sync.aligned.m8n8.x4.shared.b16 {%0,%1,%2,%3}, [%4];"
                 : "=r"(r0), "=r"(r1), "=r"(r2), "=r"(r3) : "r"(a));
}
__device__ __forceinline__ void mma16816h(float* d, u32 a0, u32 a1, u32 a2, u32 a3, u32 b0, u32 b1) {
    asm volatile("mma.sync.aligned.m16n8k16.row.col.f32.f16.f16.f32 "
                 "{%0,%1,%2,%3}, {%4,%5,%6,%7}, {%8,%9}, {%0,%1,%2,%3};"
                 : "+f"(d[0]), "+f"(d[1]), "+f"(d[2]), "+f"(d[3])
                 : "r"(a0), "r"(a1), "r"(a2), "r"(a3), "r"(b0), "r"(b1));
}
__device__ __forceinline__ void cp16(u32 dst, const void* src) {
    asm volatile("cp.async.ca.shared.global [%0], [%1], 16;" :: "r"(dst), "l"(src));
}
__device__ __forceinline__ u16 hfb(float f) {
    return __half_as_ushort(__float2half(f));
}

// ---------------- scratch ----------------
__device__ __align__(16) char g_cvp[(size_t)BATCH*DD*HH*WW*16];  // packed cv, 16B/voxel (8 grp fp16)
__device__ float g_x1[BATCH*16*DD*HH*WW];
__device__ __align__(16) char g_x1p[(size_t)BATCH*DD*HH*WW*32];  // packed x1n, 32B/voxel (16 ch fp16)
__device__ float g_x2[BATCH*16*DD*HH*WW];
__device__ float g_x2n[BATCH*16*DD*HH*WW];
__device__ float g_logits[BATCH*DD*HH*WW];
__device__ float g_feat[BATCH*16*HH*WW];
__device__ double g_stats[3*BATCH*8*2];
__device__ __align__(16) float g_zerobuf[4];   // zero-initialized

__global__ void k_zero_stats() {
    int i = threadIdx.x;
    if (i < 3*BATCH*8*2) g_stats[i] = 0.0;
}

// ---------------- cost volume -> packed fp16 channels-last ----------------
__global__ void __launch_bounds__(256) k_costvol(const float* __restrict__ fL,
                                                 const float* __restrict__ fR) {
    extern __shared__ float scv[];
    float* sL = scv;
    float* sR = scv + 16384;
    int b = blockIdx.x >> 6, h = blockIdx.x & 63;
    int tid = threadIdx.x;
    for (int i = tid; i < 16384; i += 256) {
        size_t gidx = ((size_t)(b*128 + (i >> 7))*HH + h)*WW + (i & 127);
        sL[i] = fL[gidx];
        sR[i] = fR[gidx];
    }
    __syncthreads();
    int w = tid & 127, dh = tid >> 7;
    for (int dl = 0; dl < 12; dl++) {
        int d = dh*12 + dl;
        u32 pw[4];
#pragma unroll
        for (int gp = 0; gp < 4; gp++) {
            float s0 = 0.f, s1 = 0.f;
            if (w >= d) {
                const float* pL = sL + gp*32*128 + w;
                const float* pR = sR + gp*32*128 + w - d;
#pragma unroll
                for (int c = 0; c < 16; c++) {
                    s0 += pL[c*128] * pR[c*128];
                    s1 += pL[(16 + c)*128] * pR[(16 + c)*128];
                }
                s0 *= 0.0625f; s1 *= 0.0625f;
            }
            pw[gp] = (u32)hfb(s0) | ((u32)hfb(s1) << 16);
        }
        char* vox = g_cvp + ((((size_t)(b*24 + d)*64 + h)*128 + w)*16);
        *(uint4*)vox = make_uint4(pw[0], pw[1], pw[2], pw[3]);
    }
}

// ================= tensor-core conv3d: fp16, d-pairs, W split =========
// grid = B*32*4*2 (b, h-pair, d-sixth, w-half), block = 256 (8 warps)
#define ROW_B   48
#define PLANE_B (264*ROW_B)          // 12672
#define W_OFF   (4*PLANE_B)          // 50688
#define WROW_B  48
#define CONV_SMEM (W_OFF + 27*16*WROW_B)  // 50688 + 20736 = 71424 -> 3 CTAs/SM

template<int CIN>
__global__ void __launch_bounds__(256) k_conv_tc(const float* __restrict__ wts) {
    float* out = (CIN == 8) ? g_x1 : g_x2;
    double* stats = g_stats + ((CIN == 8) ? 0 : 1)*128;

    extern __shared__ char smem[];
    char* w_sm = smem + W_OFF;
    __shared__ float sred[16];

    u32 a_base = smem_u32(smem);
    u32 w_base = smem_u32(w_sm);
    int tid = threadIdx.x, lane = tid & 31, wrp = tid >> 5;
    int hl = wrp >> 2, wq = wrp & 3, w0l = wq*16;
    if (tid < 16) sred[tid] = 0.f;

    int x = blockIdx.x;
    int wt = x & 1, dq = (x >> 1) & 3, hp = (x >> 3) & 31, b = x >> 8;
    int d0 = dq*6, h0 = hp*2, wg0 = wt*64;

    // zero all 4 plane slots once
    for (int i = tid; i < 4*PLANE_B/4; i += 256) ((u32*)smem)[i] = 0u;

    // weights: [tap][oc] rows of 48B (16 ic fp16 in bytes 0..31)
    for (int i = tid; i < 27*256; i += 256) {
        int ic = i & 15, oc = (i >> 4) & 15, tap = i >> 8;
        float v = (ic < CIN) ? wts[(oc*CIN + ic)*27 + tap] : 0.f;
        *(u16*)(w_sm + (tap*16 + oc)*WROW_B + ic*2) = hfb(v);
    }
    __syncthreads();

    // stage fully rewrites bytes 0..31 of every row (bounce aliasing requires this)
    auto stage = [&](int zd) {
        int slot = (zd - d0 + 1) & 3;
        bool pv = ((unsigned)zd < 24u);
        for (int it = tid; it < 528; it += 256) {
            int ch = it & 1;
            int t2 = it >> 1;            // 0..263
            int zhl = t2 / 66;
            int wl = t2 - zhl*66;
            int zh = h0 - 1 + zhl;
            int wgl = wg0 + wl - 1;
            u32 dst = a_base + slot*PLANE_B + (u32)t2*ROW_B + ch*16;
            const void* src;
            bool iv = pv && (unsigned)zh < 64u && (unsigned)wgl < 128u;
            if (CIN == 8) {
                // chunk 0 = ch0-7 fp16 (cvp 16B), chunk 1 = ch8-15 zeros
                src = (iv && ch == 0)
                    ? (const void*)(g_cvp + ((((size_t)(b*24 + zd)*64 + zh)*128 + wgl)*16))
                    : (const void*)g_zerobuf;
            } else {
                src = iv
                    ? (const void*)(g_x1p + ((((size_t)(b*24 + zd)*64 + zh)*128 + wgl)*32 + ch*16))
                    : (const void*)g_zerobuf;
            }
            cp16(dst, src);
        }
    };

    float gsum[2] = {0.f, 0.f}, gss[2] = {0.f, 0.f};

    for (int pair = 0; pair < 3; pair++) {
        int d = d0 + 2*pair;
        if (pair == 0) {
            stage(d0 - 1); stage(d0); stage(d0 + 1); stage(d0 + 2);
        } else {
            stage(d + 1); stage(d + 2);
        }
        asm volatile("cp.async.commit_group;" ::: "memory");
        asm volatile("cp.async.wait_group 0;" ::: "memory");
        __syncthreads();

        float acc[2][2][4];   // [dd][oh][r]
#pragma unroll
        for (int dd = 0; dd < 2; dd++)
#pragma unroll
            for (int oh = 0; oh < 2; oh++)
#pragma unroll
                for (int r = 0; r < 4; r++) acc[dd][oh][r] = 0.f;

#pragma unroll
        for (int kh = 0; kh < 3; kh++) {
            int zhl = hl + kh;
#pragma unroll
            for (int kw = 0; kw < 3; kw++) {
                // B fragments for 3 kd at this (kh,kw): 3 ldsm4 (covers both oh)
                u32 bfr[3][4];
                int m = lane >> 3;
#pragma unroll
                for (int kd = 0; kd < 3; kd++) {
                    int tap = kd*9 + kh*3 + kw;
                    u32 ba = w_base + (u32)((tap*16 + (m >> 1)*8 + (lane & 7))*WROW_B + (m & 1)*16);
                    ldsm4(ba, bfr[kd][0], bfr[kd][1], bfr[kd][2], bfr[kd][3]);
                }
                int r = zhl*66 + w0l + (lane & 15) + kw;
                u32 rowoff = (u32)r*ROW_B + (lane >> 4)*16;
#pragma unroll
                for (int q = 0; q < 4; q++) {
                    u32 pbase = a_base + (u32)((2*pair + q) & 3)*PLANE_B;
                    u32 a0, a1, a2, a3;
                    ldsm4(pbase + rowoff, a0, a1, a2, a3);
                    if (q <= 2) {
#pragma unroll
                        for (int oh = 0; oh < 2; oh++)
                            mma16816h(acc[0][oh], a0, a1, a2, a3, bfr[q][oh*2], bfr[q][oh*2+1]);
                    }
                    if (q >= 1) {
#pragma unroll
                        for (int oh = 0; oh < 2; oh++)
                            mma16816h(acc[1][oh], a0, a1, a2, a3, bfr[q-1][oh*2], bfr[q-1][oh*2+1]);
                    }
                }
            }
        }

        // stats
#pragma unroll
        for (int dd = 0; dd < 2; dd++)
#pragma unroll
            for (int oh = 0; oh < 2; oh++) {
                float s = 0.f, s2 = 0.f;
#pragma unroll
                for (int r = 0; r < 4; r++) { float v = acc[dd][oh][r]; s += v; s2 += v*v; }
                gsum[oh] += s; gss[oh] += s2;
            }

        // bounce into the two retiring plane slots, then coalesced store
        __syncthreads();
#pragma unroll
        for (int dd = 0; dd < 2; dd++) {
            float* bounce = (float*)(smem + ((2*pair + dd) & 3)*PLANE_B);
#pragma unroll
            for (int oh = 0; oh < 2; oh++)
#pragma unroll
                for (int r = 0; r < 4; r++) {
                    int oc = oh*8 + (lane & 3)*2 + (r & 1);
                    int px = w0l + (lane >> 2) + (r >> 1)*8;
                    bounce[oc*132 + hl*64 + px] = acc[dd][oh][r];
                }
        }
        __syncthreads();
        for (int i = tid; i < 1024; i += 256) {
            int dd = i >> 9, rem9 = i & 511;
            int oc = rem9 >> 5, rem = rem9 & 31;
            int h2 = rem >> 4, w4 = rem & 15;
            const float* bounce = (const float*)(smem + ((2*pair + dd) & 3)*PLANE_B);
            float4 v = *(const float4*)&bounce[oc*132 + h2*64 + w4*4];
            float* ob = out + ((size_t)b*16*DD + d + dd)*HW;
            *(float4*)&ob[(size_t)oc*DD*HW + (h0 + h2)*WW + wg0 + w4*4] = v;
        }
        __syncthreads();
    }

    int g0 = lane & 3;
    atomicAdd(&sred[g0*2],         gsum[0]); atomicAdd(&sred[g0*2 + 1],         gss[0]);
    atomicAdd(&sred[(4 + g0)*2],   gsum[1]); atomicAdd(&sred[(4 + g0)*2 + 1],   gss[1]);
    __syncthreads();
    if (tid < 16) atomicAdd(&stats[b*16 + tid], (double)sred[tid]);
}

// ---------------- GN1 finalize + SiLU -> packed fp16 ----------------
__global__ void __launch_bounds__(256) k_norm_pack(const float* __restrict__ gw,
                                                   const float* __restrict__ gb) {
    __shared__ float sA[16], sB[16];
    int x = blockIdx.x;
    int hq = x & 31, d = (x >> 5) % 24, b = x / 768;
    int tid = threadIdx.x;
    if (tid < 16) {
        const double* p = g_stats + ((size_t)b*8 + (tid >> 1))*2;
        double mu = p[0] / 393216.0;
        double var = p[1] / 393216.0 - mu*mu;
        float rstd = rsqrtf((float)var + 1e-5f);
        float A = rstd * gw[tid];
        sA[tid] = A; sB[tid] = gb[tid] - (float)mu*A;
    }
    __syncthreads();
    int w = tid & 127, h = hq*2 + (tid >> 7);
    const float* base = g_x1 + ((size_t)b*16*DD + d)*HW + h*WW + w;
    u32 pw[8];
#pragma unroll
    for (int j = 0; j < 8; j++) {
        float v0 = base[(size_t)(2*j)*DD*HW];
        float v1 = base[(size_t)(2*j + 1)*DD*HW];
        float t0 = v0*sA[2*j] + sB[2*j];
        float t1 = v1*sA[2*j + 1] + sB[2*j + 1];
        t0 = t0 / (1.f + __expf(-t0));
        t1 = t1 / (1.f + __expf(-t1));
        pw[j] = (u32)hfb(t0) | ((u32)hfb(t1) << 16);
    }
    u32* dst = (u32*)(g_x1p + ((((size_t)(b*24 + d)*64 + h)*128 + w)*32));
    *(uint4*)dst       = make_uint4(pw[0], pw[1], pw[2], pw[3]);
    *(uint4*)(dst + 4) = make_uint4(pw[4], pw[5], pw[6], pw[7]);
}

// ---------------- GN finalize + apply + SiLU (layers 1,2) ----------------
__global__ void __launch_bounds__(256) k_norm(int which, float* outext,
                                              const float* __restrict__ gw,
                                              const float* __restrict__ gb,
                                              int nslab, float invN) {
    const float* in = (which == 1) ? g_x2 : g_feat;
    float* out = (which == 2) ? outext : g_x2n;
    const double* st = g_stats + which*128;
    __shared__ float sA, sB;
    int x = blockIdx.x;
    int s = x % nslab, c = (x / nslab) & 15, b = x / (nslab*16);
    if (threadIdx.x == 0) {
        const double* p = st + ((size_t)b*8 + (c >> 1))*2;
        double mu = p[0] * (double)invN;
        double var = p[1] * (double)invN - mu*mu;
        float rstd = rsqrtf((float)var + 1e-5f);
        float A = rstd * gw[c];
        sA = A; sB = gb[c] - (float)mu * A;
    }
    __syncthreads();
    float A = sA, Bv = sB;
    size_t base = ((size_t)(b*16 + c)*nslab + s)*8192;
    const float4* ip = (const float4*)(in + base);
    float4* op = (float4*)(out + base);
    for (int i = threadIdx.x; i < 2048; i += 256) {
        float4 v = ip[i];
        v.x = v.x*A + Bv; v.y = v.y*A + Bv; v.z = v.z*A + Bv; v.w = v.w*A + Bv;
        v.x = v.x / (1.f + __expf(-v.x));
        v.y = v.y / (1.f + __expf(-v.y));
        v.z = v.z / (1.f + __expf(-v.z));
        v.w = v.w / (1.f + __expf(-v.w));
        op[i] = v;
    }
}

// ---------------- conv3d oc=1 (FMA2, proven) ----------------
__global__ void __launch_bounds__(128) k_conv3d_oc1(const float* __restrict__ wts,
                                                    const float* __restrict__ bias) {
    __shared__ u64 swt[432];
    int tid = threadIdx.x;
    for (int i = tid; i < 432; i += 128) swt[i] = pk1(wts[i]);
    __syncthreads();
    int x = blockIdx.x;
    int ht = x & 7, d = (x >> 3) % 24, b = x / 192;
    int wt = tid & 15, hr = tid >> 4;
    int w0 = wt << 3, h = ht*8 + hr;
    u64 acc[4];
#pragma unroll
    for (int t = 0; t < 4; t++) acc[t] = 0ull;
    const float* inb = g_x2n + (size_t)b*16*DD*HW;
    for (int ic = 0; ic < 16; ic++) {
        const float* inc = inb + (size_t)ic*DD*HW;
#pragma unroll
        for (int kd = 0; kd < 3; kd++) {
            int zd = d + kd - 1;
            if ((unsigned)zd >= (unsigned)DD) continue;
#pragma unroll
            for (int kh = 0; kh < 3; kh++) {
                int zh = h + kh - 1;
                if ((unsigned)zh >= (unsigned)HH) continue;
                const float* row = inc + ((size_t)zd*HH + zh)*WW + w0;
                float r0 = (w0 == 0) ? 0.f : __ldg(row - 1);
                float4 va = *(const float4*)row;
                float4 vb = *(const float4*)(row + 4);
                float r9 = (w0 == 120) ? 0.f : __ldg(row + 8);
                u64 pe[5], po[4];
                pe[0] = pk(r0, va.x);  pe[1] = pk(va.y, va.z);
                pe[2] = pk(va.w, vb.x); pe[3] = pk(vb.y, vb.z);
                pe[4] = pk(vb.w, r9);
                po[0] = pk(va.x, va.y); po[1] = pk(va.z, va.w);
                po[2] = pk(vb.x, vb.y); po[3] = pk(vb.z, vb.w);
                int tb = (kd*3 + kh)*3;
                u64 wv0 = swt[ic*27 + tb + 0];
                u64 wv1 = swt[ic*27 + tb + 1];
                u64 wv2 = swt[ic*27 + tb + 2];
#pragma unroll
                for (int t = 0; t < 4; t++) {
                    fma2(acc[t], wv0, pe[t]);
                    fma2(acc[t], wv1, po[t]);
                    fma2(acc[t], wv2, pe[t + 1]);
                }
            }
        }
    }
    float bs = bias[0];
    float o[8];
#pragma unroll
    for (int t = 0; t < 4; t++) { float2 f = unpk(acc[t]); o[2*t] = f.x + bs; o[2*t+1] = f.y + bs; }
    float* orow = g_logits + (((size_t)b*DD + d)*HH + h)*WW + w0;
    *(float4*)orow       = make_float4(o[0], o[1], o[2], o[3]);
    *(float4*)(orow + 4) = make_float4(o[4], o[5], o[6], o[7]);
}

// ---------------- softmax (proven) ----------------
__global__ void __launch_bounds__(128) k_softmax(float* __restrict__ out) {
    int x = blockIdx.x;
    int h = x & 63, b = x >> 6;
    int w = threadIdx.x;
    const float* lp = g_logits + ((size_t)b*DD*HH + h)*WW + w;
    float l[DD];
    float m = -1e30f;
#pragma unroll
    for (int d = 0; d < DD; d++) { l[d] = lp[(size_t)d*HW]; m = fmaxf(m, l[d]); }
    float S = 0.f, E = 0.f;
#pragma unroll
    for (int d = 0; d < DD; d++) {
        float e = __expf(l[d] - m);
        S += e; E += e * (float)d;
    }
    float inv = 1.f / S;
    int oi = (b*HH + h)*WW + w;
    out[oi]           = E * inv;
    out[65536 + oi]   = 0.f;
    out[131072 + oi]  = 0.f;
    out[1245184 + oi] = inv;
}

// ---------------- feature head conv2d (FMA2, proven) ----------------
__global__ void __launch_bounds__(128, 3) k_conv2d_feat(const float* __restrict__ fL,
                                                        const float* __restrict__ wts) {
    __shared__ __align__(16) u64 swt[32*9*16];
    __shared__ float sred[16];
    int tid = threadIdx.x;
    if (tid < 16) sred[tid] = 0.f;
    int x = blockIdx.x;
    int wtile = x & 1, ht = (x >> 1) & 15, b = x >> 5;
    int wt = tid & 7, os = (tid >> 3) & 3, hr = tid >> 5;
    int w0 = wtile*64 + wt*8, h = ht*4 + hr, oc0 = os*4;
    u64 acc[4][4];
#pragma unroll
    for (int o = 0; o < 4; o++)
#pragma unroll
        for (int t = 0; t < 4; t++) acc[o][t] = 0ull;
    for (int p = 0; p < 4; p++) {
        __syncthreads();
        for (int i = tid; i < 32*144; i += 128) {
            int icl = i / 144; int r = i - icl*144; int tap = r >> 4; int oc = r & 15;
            swt[i] = pk1(wts[((size_t)oc*128 + p*32 + icl)*9 + tap]);
        }
        __syncthreads();
        for (int icl = 0; icl < 32; icl++) {
            int ic = p*32 + icl;
            const float* rowb = fL + ((size_t)(b*128 + ic)*HH)*WW;
#pragma unroll
            for (int kh = 0; kh < 3; kh++) {
                int zh = h + kh - 1;
                if ((unsigned)zh >= (unsigned)HH) continue;
                const float* row = rowb + (size_t)zh*WW + w0;
                float r0 = (w0 == 0) ? 0.f : __ldg(row - 1);
                float4 va = *(const float4*)row;
                float4 vb = *(const float4*)(row + 4);
                float r9 = (w0 == 120) ? 0.f : __ldg(row + 8);
                u64 pe[5], po[4];
                pe[0] = pk(r0, va.x);  pe[1] = pk(va.y, va.z);
                pe[2] = pk(va.w, vb.x); pe[3] = pk(vb.y, vb.z);
                pe[4] = pk(vb.w, r9);
                po[0] = pk(va.x, va.y); po[1] = pk(va.z, va.w);
                po[2] = pk(vb.x, vb.y); po[3] = pk(vb.z, vb.w);
                const u64* wbase = swt + (icl*9 + kh*3)*16 + oc0;
#pragma unroll
                for (int o = 0; o < 4; o++) {
                    u64 wv0 = wbase[o];
                    fma2(acc[o][0], wv0, pe[0]); fma2(acc[o][1], wv0, pe[1]);
                    fma2(acc[o][2], wv0, pe[2]); fma2(acc[o][3], wv0, pe[3]);
                }
#pragma unroll
                for (int o = 0; o < 4; o++) {
                    u64 wv1 = wbase[16 + o];
                    fma2(acc[o][0], wv1, po[0]); fma2(acc[o][1], wv1, po[1]);
                    fma2(acc[o][2], wv1, po[2]); fma2(acc[o][3], wv1, po[3]);
                }
#pragma unroll
                for (int o = 0; o < 4; o++) {
                    u64 wv2 = wbase[32 + o];
                    fma2(acc[o][0], wv2, pe[1]); fma2(acc[o][1], wv2, pe[2]);
                    fma2(acc[o][2], wv2, pe[3]); fma2(acc[o][3], wv2, pe[4]);
                }
            }
        }
    }
    float gs[2], gs2[2];
    gs[0] = gs[1] = gs2[0] = gs2[1] = 0.f;
#pragma unroll
    for (int o = 0; o < 4; o++) {
        float v[8];
#pragma unroll
        for (int t = 0; t < 4; t++) { float2 f = unpk(acc[o][t]); v[2*t] = f.x; v[2*t+1] = f.y; }
        int oc = oc0 + o;
        float* orow = g_feat + (((size_t)b*16 + oc)*HH + h)*WW + w0;
        *(float4*)orow       = make_float4(v[0], v[1], v[2], v[3]);
        *(float4*)(orow + 4) = make_float4(v[4], v[5], v[6], v[7]);
        float s = 0.f, s2 = 0.f;
#pragma unroll
        for (int j = 0; j < 8; j++) { s += v[j]; s2 += v[j]*v[j]; }
        gs[o >> 1] += s; gs2[o >> 1] += s2;
    }
#pragma unroll
    for (int i = 0; i < 2; i++) {
        int grp = os*2 + i;
        atomicAdd(&sred[grp*2],     gs[i]);
        atomicAdd(&sred[grp*2 + 1], gs2[i]);
    }
    __syncthreads();
    if (tid < 16) atomicAdd(&g_stats[2*128 + b*16 + tid], (double)sred[tid]);
}

// ---------------- launch ----------------
extern "C" void kernel_launch(void* const* d_in, const int* in_sizes, int n_in,
                              void* d_out, int out_size) {
    const float* fL    = (const float*)d_in[0];
    const float* fR    = (const float*)d_in[1];
    const float* w1    = (const float*)d_in[2];
    const float* gn1w  = (const float*)d_in[3];
    const float* gn1b  = (const float*)d_in[4];
    const float* w2    = (const float*)d_in[5];
    const float* gn2w  = (const float*)d_in[6];
    const float* gn2b  = (const float*)d_in[7];
    const float* w3    = (const float*)d_in[8];
    const float* b3    = (const float*)d_in[9];
    const float* fhw   = (const float*)d_in[10];
    const float* fhgnw = (const float*)d_in[11];
    const float* fhgnb = (const float*)d_in[12];
    float* out = (float*)d_out;

    const float invN3d = 1.0f / (2.0f*DD*HH*WW);
    const float invN2d = 1.0f / (2.0f*HH*WW);

    cudaFuncSetAttribute(k_costvol,     cudaFuncAttributeMaxDynamicSharedMemorySize, 131072);
    cudaFuncSetAttribute(k_conv_tc<8>,  cudaFuncAttributeMaxDynamicSharedMemorySize, CONV_SMEM);
    cudaFuncSetAttribute(k_conv_tc<16>, cudaFuncAttributeMaxDynamicSharedMemorySize, CONV_SMEM);

    k_zero_stats<<<1, 384>>>();                                  // 0
    k_costvol<<<BATCH*HH, 256, 131072>>>(fL, fR);                // 1
    k_zero_stats<<<1, 384>>>();                                  // 2 (dummy)
    k_conv_tc<8><<<2048, 256, CONV_SMEM>>>(w1);                  // 3 <-- profiled
    k_norm_pack<<<BATCH*24*32, 256>>>(gn1w, gn1b);               // 4
    k_conv_tc<16><<<2048, 256, CONV_SMEM>>>(w2);                 // 5
    k_norm<<<BATCH*16*24, 256>>>(1, nullptr, gn2w, gn2b, 24, invN3d);  // 6
    k_conv3d_oc1<<<BATCH*24*8, 128>>>(w3, b3);                   // 7
    k_softmax<<<BATCH*HH, 128>>>(out);                           // 8
    k_conv2d_feat<<<BATCH*16*2, 128>>>(fL, fhw);                 // 9
    k_norm<<<BATCH*16, 256>>>(2, out + 196608, fhgnw, fhgnb, 1, invN2d); // 10
}

// round 14
// speedup vs baseline: 2.3817x; 1.1448x over previous
#include <cuda_runtime.h>
#include <cuda_fp16.h>
#include <math.h>

#define BATCH 8
#define DD 24
#define HH 64
#define WW 128
#define HW (HH*WW)

typedef unsigned long long u64;
typedef unsigned int u32;
typedef unsigned short u16;

// ---------------- packed fp32x2 helpers ----------------
__device__ __forceinline__ u64 pk(float lo, float hi) {
    u64 r; asm("mov.b64 %0, {%1,%2};" : "=l"(r) : "f"(lo), "f"(hi)); return r;
}
__device__ __forceinline__ u64 pk1(float v) { return pk(v, v); }
__device__ __forceinline__ void fma2(u64& d, u64 a, u64 b) {
    asm("fma.rn.f32x2 %0, %1, %2, %0;" : "+l"(d) : "l"(a), "l"(b));
}
__device__ __forceinline__ float2 unpk(u64 v) {
    float2 f; asm("mov.b64 {%0,%1}, %2;" : "=f"(f.x), "=f"(f.y) : "l"(v)); return f;
}

// ---------------- mma / ldmatrix helpers ----------------
__device__ __forceinline__ u32 smem_u32(const void* p) {
    u32 a; asm("{ .reg .u64 t; cvta.to.shared.u64 t, %1; cvt.u32.u64 %0, t; }" : "=r"(a) : "l"(p));
    return a;
}
__device__ __forceinline__ void ldsm4(u32 a, u32& r0, u32& r1, u32& r2, u32& r3) {
    asm volatile("ldmatrix.sync.aligned.m8n8.x4.shared.b16 {%0,%1,%2,%3}, [%4];"
                 : "=r"(r0), "=r"(r1), "=r"(r2), "=r"(r3) : "r"(a));
}
__device__ __forceinline__ void mma16816h(float* d, u32 a0, u32 a1, u32 a2, u32 a3, u32 b0, u32 b1) {
    asm volatile("mma.sync.aligned.m16n8k16.row.col.f32.f16.f16.f32 "
                 "{%0,%1,%2,%3}, {%4,%5,%6,%7}, {%8,%9}, {%0,%1,%2,%3};"
                 : "+f"(d[0]), "+f"(d[1]), "+f"(d[2]), "+f"(d[3])
                 : "r"(a0), "r"(a1), "r"(a2), "r"(a3), "r"(b0), "r"(b1));
}
__device__ __forceinline__ void cp16(u32 dst, const void* src) {
    asm volatile("cp.async.ca.shared.global [%0], [%1], 16;" :: "r"(dst), "l"(src));
}
__device__ __forceinline__ u16 hfb(float f) {
    return __half_as_ushort(__float2half(f));
}

// ---------------- scratch ----------------
__device__ __align__(16) char g_cvp[(size_t)BATCH*DD*HH*WW*16];  // packed cv, 16B/voxel
__device__ float g_x1[BATCH*16*DD*HH*WW];
__device__ __align__(16) char g_x1p[(size_t)BATCH*DD*HH*WW*32];  // packed x1n, 32B/voxel
__device__ float g_x2[BATCH*16*DD*HH*WW];
__device__ float g_x2n[BATCH*16*DD*HH*WW];
__device__ float g_logits[BATCH*DD*HH*WW];
__device__ float g_feat[BATCH*16*HH*WW];
__device__ __align__(16) char g_fLp[(size_t)BATCH*HH*WW*256];    // packed fL, 256B/voxel (128ch fp16)
__device__ double g_stats[3*BATCH*8*2];
__device__ __align__(16) float g_zerobuf[4];   // zero-initialized

__global__ void k_zero_stats() {
    int i = threadIdx.x;
    if (i < 3*BATCH*8*2) g_stats[i] = 0.0;
}

// ---------------- cost volume -> packed fp16 channels-last (proven) ----------------
__global__ void __launch_bounds__(256) k_costvol(const float* __restrict__ fL,
                                                 const float* __restrict__ fR) {
    extern __shared__ float scv[];
    float* sL = scv;
    float* sR = scv + 16384;
    int b = blockIdx.x >> 6, h = blockIdx.x & 63;
    int tid = threadIdx.x;
    for (int i = tid; i < 16384; i += 256) {
        size_t gidx = ((size_t)(b*128 + (i >> 7))*HH + h)*WW + (i & 127);
        sL[i] = fL[gidx];
        sR[i] = fR[gidx];
    }
    __syncthreads();
    int w = tid & 127, dh = tid >> 7;
    for (int dl = 0; dl < 12; dl++) {
        int d = dh*12 + dl;
        u32 pw[4];
#pragma unroll
        for (int gp = 0; gp < 4; gp++) {
            float s0 = 0.f, s1 = 0.f;
            if (w >= d) {
                const float* pL = sL + gp*32*128 + w;
                const float* pR = sR + gp*32*128 + w - d;
#pragma unroll
                for (int c = 0; c < 16; c++) {
                    s0 += pL[c*128] * pR[c*128];
                    s1 += pL[(16 + c)*128] * pR[(16 + c)*128];
                }
                s0 *= 0.0625f; s1 *= 0.0625f;
            }
            pw[gp] = (u32)hfb(s0) | ((u32)hfb(s1) << 16);
        }
        char* vox = g_cvp + ((((size_t)(b*24 + d)*64 + h)*128 + w)*16);
        *(uint4*)vox = make_uint4(pw[0], pw[1], pw[2], pw[3]);
    }
}

// ---------------- pack fL -> channels-last fp16 (for feat mma) ----------------
// grid = B*HH, block 256: (w, half)
__global__ void __launch_bounds__(256) k_packfL(const float* __restrict__ fL) {
    int b = blockIdx.x >> 6, h = blockIdx.x & 63;
    int tid = threadIdx.x;
    int w = tid & 127, half = tid >> 7;
    const float* base = fL + (size_t)b*128*HW + h*WW + w;
#pragma unroll
    for (int q = 0; q < 4; q++) {
        int c8 = half*4 + q;
        u32 pw[8];
#pragma unroll
        for (int j = 0; j < 8; j++) {
            float v0 = base[(size_t)(c8*16 + 2*j)*HW];
            float v1 = base[(size_t)(c8*16 + 2*j + 1)*HW];
            pw[j] = (u32)hfb(v0) | ((u32)hfb(v1) << 16);
        }
        u32* dst = (u32*)(g_fLp + (((size_t)b*64 + h)*128 + w)*256 + c8*32);
        *(uint4*)dst       = make_uint4(pw[0], pw[1], pw[2], pw[3]);
        *(uint4*)(dst + 4) = make_uint4(pw[4], pw[5], pw[6], pw[7]);
    }
}

// ================= tensor-core conv3d: fp16, d-pairs, W split (proven 727us) =========
#define ROW_B   48
#define PLANE_B (264*ROW_B)          // 12672
#define W_OFF   (4*PLANE_B)          // 50688
#define WROW_B  48
#define CONV_SMEM (W_OFF + 27*16*WROW_B)  // 71424 -> 3 CTAs/SM

template<int CIN>
__global__ void __launch_bounds__(256) k_conv_tc(const float* __restrict__ wts) {
    float* out = (CIN == 8) ? g_x1 : g_x2;
    double* stats = g_stats + ((CIN == 8) ? 0 : 1)*128;

    extern __shared__ char smem[];
    char* w_sm = smem + W_OFF;
    __shared__ float sred[16];

    u32 a_base = smem_u32(smem);
    u32 w_base = smem_u32(w_sm);
    int tid = threadIdx.x, lane = tid & 31, wrp = tid >> 5;
    int hl = wrp >> 2, wq = wrp & 3, w0l = wq*16;
    if (tid < 16) sred[tid] = 0.f;

    int x = blockIdx.x;
    int wt = x & 1, dq = (x >> 1) & 3, hp = (x >> 3) & 31, b = x >> 8;
    int d0 = dq*6, h0 = hp*2, wg0 = wt*64;

    for (int i = tid; i < 4*PLANE_B/4; i += 256) ((u32*)smem)[i] = 0u;

    for (int i = tid; i < 27*256; i += 256) {
        int ic = i & 15, oc = (i >> 4) & 15, tap = i >> 8;
        float v = (ic < CIN) ? wts[(oc*CIN + ic)*27 + tap] : 0.f;
        *(u16*)(w_sm + (tap*16 + oc)*WROW_B + ic*2) = hfb(v);
    }
    __syncthreads();

    auto stage = [&](int zd) {
        int slot = (zd - d0 + 1) & 3;
        bool pv = ((unsigned)zd < 24u);
        for (int it = tid; it < 528; it += 256) {
            int ch = it & 1;
            int t2 = it >> 1;
            int zhl = t2 / 66;
            int wl = t2 - zhl*66;
            int zh = h0 - 1 + zhl;
            int wgl = wg0 + wl - 1;
            u32 dst = a_base + slot*PLANE_B + (u32)t2*ROW_B + ch*16;
            const void* src;
            bool iv = pv && (unsigned)zh < 64u && (unsigned)wgl < 128u;
            if (CIN == 8) {
                src = (iv && ch == 0)
                    ? (const void*)(g_cvp + ((((size_t)(b*24 + zd)*64 + zh)*128 + wgl)*16))
                    : (const void*)g_zerobuf;
            } else {
                src = iv
                    ? (const void*)(g_x1p + ((((size_t)(b*24 + zd)*64 + zh)*128 + wgl)*32 + ch*16))
                    : (const void*)g_zerobuf;
            }
            cp16(dst, src);
        }
    };

    float gsum[2] = {0.f, 0.f}, gss[2] = {0.f, 0.f};

    for (int pair = 0; pair < 3; pair++) {
        int d = d0 + 2*pair;
        if (pair == 0) {
            stage(d0 - 1); stage(d0); stage(d0 + 1); stage(d0 + 2);
        } else {
            stage(d + 1); stage(d + 2);
        }
        asm volatile("cp.async.commit_group;" ::: "memory");
        asm volatile("cp.async.wait_group 0;" ::: "memory");
        __syncthreads();

        float acc[2][2][4];
#pragma unroll
        for (int dd = 0; dd < 2; dd++)
#pragma unroll
            for (int oh = 0; oh < 2; oh++)
#pragma unroll
                for (int r = 0; r < 4; r++) acc[dd][oh][r] = 0.f;

#pragma unroll
        for (int kh = 0; kh < 3; kh++) {
            int zhl = hl + kh;
#pragma unroll
            for (int kw = 0; kw < 3; kw++) {
                u32 bfr[3][4];
                int m = lane >> 3;
#pragma unroll
                for (int kd = 0; kd < 3; kd++) {
                    int tap = kd*9 + kh*3 + kw;
                    u32 ba = w_base + (u32)((tap*16 + (m >> 1)*8 + (lane & 7))*WROW_B + (m & 1)*16);
                    ldsm4(ba, bfr[kd][0], bfr[kd][1], bfr[kd][2], bfr[kd][3]);
                }
                int r = zhl*66 + w0l + (lane & 15) + kw;
                u32 rowoff = (u32)r*ROW_B + (lane >> 4)*16;
#pragma unroll
                for (int q = 0; q < 4; q++) {
                    u32 pbase = a_base + (u32)((2*pair + q) & 3)*PLANE_B;
                    u32 a0, a1, a2, a3;
                    ldsm4(pbase + rowoff, a0, a1, a2, a3);
                    if (q <= 2) {
#pragma unroll
                        for (int oh = 0; oh < 2; oh++)
                            mma16816h(acc[0][oh], a0, a1, a2, a3, bfr[q][oh*2], bfr[q][oh*2+1]);
                    }
                    if (q >= 1) {
#pragma unroll
                        for (int oh = 0; oh < 2; oh++)
                            mma16816h(acc[1][oh], a0, a1, a2, a3, bfr[q-1][oh*2], bfr[q-1][oh*2+1]);
                    }
                }
            }
        }

#pragma unroll
        for (int dd = 0; dd < 2; dd++)
#pragma unroll
            for (int oh = 0; oh < 2; oh++) {
                float s = 0.f, s2 = 0.f;
#pragma unroll
                for (int r = 0; r < 4; r++) { float v = acc[dd][oh][r]; s += v; s2 += v*v; }
                gsum[oh] += s; gss[oh] += s2;
            }

        __syncthreads();
#pragma unroll
        for (int dd = 0; dd < 2; dd++) {
            float* bounce = (float*)(smem + ((2*pair + dd) & 3)*PLANE_B);
#pragma unroll
            for (int oh = 0; oh < 2; oh++)
#pragma unroll
                for (int r = 0; r < 4; r++) {
                    int oc = oh*8 + (lane & 3)*2 + (r & 1);
                    int px = w0l + (lane >> 2) + (r >> 1)*8;
                    bounce[oc*132 + hl*64 + px] = acc[dd][oh][r];
                }
        }
        __syncthreads();
        for (int i = tid; i < 1024; i += 256) {
            int dd = i >> 9, rem9 = i & 511;
            int oc = rem9 >> 5, rem = rem9 & 31;
            int h2 = rem >> 4, w4 = rem & 15;
            const float* bounce = (const float*)(smem + ((2*pair + dd) & 3)*PLANE_B);
            float4 v = *(const float4*)&bounce[oc*132 + h2*64 + w4*4];
            float* ob = out + ((size_t)b*16*DD + d + dd)*HW;
            *(float4*)&ob[(size_t)oc*DD*HW + (h0 + h2)*WW + wg0 + w4*4] = v;
        }
        __syncthreads();
    }

    int g0 = lane & 3;
    atomicAdd(&sred[g0*2],         gsum[0]); atomicAdd(&sred[g0*2 + 1],         gss[0]);
    atomicAdd(&sred[(4 + g0)*2],   gsum[1]); atomicAdd(&sred[(4 + g0)*2 + 1],   gss[1]);
    __syncthreads();
    if (tid < 16) atomicAdd(&stats[b*16 + tid], (double)sred[tid]);
}

// ================= feature head: fp16 mma conv2d (128->16 ch) =================
// grid = B*32*2 (b, h-pair, w-half), block = 256 (8 warps)
#define FROW_B  48
#define FPLANE  (264*FROW_B)                 // 12672
#define FW_OFF  FPLANE
#define FEAT_SMEM (FPLANE + 8*9*16*FROW_B)   // 12672 + 55296 = 67968 -> 3 CTAs/SM

__global__ void __launch_bounds__(256) k_feat_tc(const float* __restrict__ wts) {
    extern __shared__ char smem[];
    char* w_sm = smem + FW_OFF;
    __shared__ float sred[16];

    u32 a_base = smem_u32(smem);
    u32 w_base = smem_u32(w_sm);
    int tid = threadIdx.x, lane = tid & 31, wrp = tid >> 5;
    int hl = wrp >> 2, wq = wrp & 3, w0l = wq*16;
    if (tid < 16) sred[tid] = 0.f;

    int x = blockIdx.x;
    int wt = x & 1, hp = (x >> 1) & 31, b = x >> 6;
    int h0 = hp*2, wg0 = wt*64;

    // stage ALL weights: [chunk c][tap][oc] rows of 48B, 16 ic each
    for (int i = tid; i < 18432; i += 256) {
        int icl = i & 15;
        int rest = i >> 4;
        int oc = rest & 15;
        int tapc = rest >> 4;                 // 0..71 = c*9 + tap
        int c = tapc / 9, tap = tapc - c*9;
        float v = wts[((size_t)oc*128 + c*16 + icl)*9 + tap];
        *(u16*)(w_sm + (tapc*16 + oc)*FROW_B + icl*2) = hfb(v);
    }
    __syncthreads();

    float acc[2][4];
#pragma unroll
    for (int oh = 0; oh < 2; oh++)
#pragma unroll
        for (int r = 0; r < 4; r++) acc[oh][r] = 0.f;

    for (int c = 0; c < 8; c++) {
        // stage ic-chunk c: 264 rows x 32B
        for (int it = tid; it < 528; it += 256) {
            int ch = it & 1;
            int t2 = it >> 1;
            int zhl = t2 / 66;
            int wl = t2 - zhl*66;
            int zh = h0 - 1 + zhl;
            int wgl = wg0 + wl - 1;
            u32 dst = a_base + (u32)t2*FROW_B + ch*16;
            const void* src = ((unsigned)zh < 64u && (unsigned)wgl < 128u)
                ? (const void*)(g_fLp + (((size_t)b*64 + zh)*128 + wgl)*256 + c*32 + ch*16)
                : (const void*)g_zerobuf;
            cp16(dst, src);
        }
        asm volatile("cp.async.commit_group;" ::: "memory");
        asm volatile("cp.async.wait_group 0;" ::: "memory");
        __syncthreads();

#pragma unroll
        for (int kh = 0; kh < 3; kh++) {
            int zhl = hl + kh;
#pragma unroll
            for (int kw = 0; kw < 3; kw++) {
                int tapc = c*9 + kh*3 + kw;
                int m = lane >> 3;
                u32 bfr0, bfr1, bfr2, bfr3;
                u32 ba = w_base + (u32)((tapc*16 + (m >> 1)*8 + (lane & 7))*FROW_B + (m & 1)*16);
                ldsm4(ba, bfr0, bfr1, bfr2, bfr3);
                int r = zhl*66 + w0l + (lane & 15) + kw;
                u32 a0, a1, a2, a3;
                ldsm4(a_base + (u32)r*FROW_B + (lane >> 4)*16, a0, a1, a2, a3);
                mma16816h(acc[0], a0, a1, a2, a3, bfr0, bfr1);
                mma16816h(acc[1], a0, a1, a2, a3, bfr2, bfr3);
            }
        }
        __syncthreads();   // compute done before next chunk's staging overwrites A
    }

    // stats (layer 2)
    float gsum[2], gss[2];
#pragma unroll
    for (int oh = 0; oh < 2; oh++) {
        float s = 0.f, s2 = 0.f;
#pragma unroll
        for (int r = 0; r < 4; r++) { float v = acc[oh][r]; s += v; s2 += v*v; }
        gsum[oh] = s; gss[oh] = s2;
    }

    // bounce into A buffer (free now) + coalesced store
    float* bounce = (float*)smem;
#pragma unroll
    for (int oh = 0; oh < 2; oh++)
#pragma unroll
        for (int r = 0; r < 4; r++) {
            int oc = oh*8 + (lane & 3)*2 + (r & 1);
            int px = w0l + (lane >> 2) + (r >> 1)*8;
            bounce[oc*132 + hl*64 + px] = acc[oh][r];
        }
    __syncthreads();
    for (int i = tid; i < 512; i += 256) {
        int oc = i >> 5, rem = i & 31;
        int h2 = rem >> 4, w4 = rem & 15;
        float4 v = *(const float4*)&bounce[oc*132 + h2*64 + w4*4];
        *(float4*)&g_feat[((size_t)(b*16 + oc)*HH + h0 + h2)*WW + wg0 + w4*4] = v;
    }

    int g0 = lane & 3;
    atomicAdd(&sred[g0*2],         gsum[0]); atomicAdd(&sred[g0*2 + 1],         gss[0]);
    atomicAdd(&sred[(4 + g0)*2],   gsum[1]); atomicAdd(&sred[(4 + g0)*2 + 1],   gss[1]);
    __syncthreads();
    if (tid < 16) atomicAdd(&g_stats[2*128 + b*16 + tid], (double)sred[tid]);
}

// ---------------- GN1 finalize + SiLU -> packed fp16 (proven) ----------------
__global__ void __launch_bounds__(256) k_norm_pack(const float* __restrict__ gw,
                                                   const float* __restrict__ gb) {
    __shared__ float sA[16], sB[16];
    int x = blockIdx.x;
    int hq = x & 31, d = (x >> 5) % 24, b = x / 768;
    int tid = threadIdx.x;
    if (tid < 16) {
        const double* p = g_stats + ((size_t)b*8 + (tid >> 1))*2;
        double mu = p[0] / 393216.0;
        double var = p[1] / 393216.0 - mu*mu;
        float rstd = rsqrtf((float)var + 1e-5f);
        float A = rstd * gw[tid];
        sA[tid] = A; sB[tid] = gb[tid] - (float)mu*A;
    }
    __syncthreads();
    int w = tid & 127, h = hq*2 + (tid >> 7);
    const float* base = g_x1 + ((size_t)b*16*DD + d)*HW + h*WW + w;
    u32 pw[8];
#pragma unroll
    for (int j = 0; j < 8; j++) {
        float v0 = base[(size_t)(2*j)*DD*HW];
        float v1 = base[(size_t)(2*j + 1)*DD*HW];
        float t0 = v0*sA[2*j] + sB[2*j];
        float t1 = v1*sA[2*j + 1] + sB[2*j + 1];
        t0 = t0 / (1.f + __expf(-t0));
        t1 = t1 / (1.f + __expf(-t1));
        pw[j] = (u32)hfb(t0) | ((u32)hfb(t1) << 16);
    }
    u32* dst = (u32*)(g_x1p + ((((size_t)(b*24 + d)*64 + h)*128 + w)*32));
    *(uint4*)dst       = make_uint4(pw[0], pw[1], pw[2], pw[3]);
    *(uint4*)(dst + 4) = make_uint4(pw[4], pw[5], pw[6], pw[7]);
}

// ---------------- GN finalize + apply + SiLU (layers 1,2) ----------------
__global__ void __launch_bounds__(256) k_norm(int which, float* outext,
                                              const float* __restrict__ gw,
                                              const float* __restrict__ gb,
                                              int nslab, float invN) {
    const float* in = (which == 1) ? g_x2 : g_feat;
    float* out = (which == 2) ? outext : g_x2n;
    const double* st = g_stats + which*128;
    __shared__ float sA, sB;
    int x = blockIdx.x;
    int s = x % nslab, c = (x / nslab) & 15, b = x / (nslab*16);
    if (threadIdx.x == 0) {
        const double* p = st + ((size_t)b*8 + (c >> 1))*2;
        double mu = p[0] * (double)invN;
        double var = p[1] * (double)invN - mu*mu;
        float rstd = rsqrtf((float)var + 1e-5f);
        float A = rstd * gw[c];
        sA = A; sB = gb[c] - (float)mu * A;
    }
    __syncthreads();
    float A = sA, Bv = sB;
    size_t base = ((size_t)(b*16 + c)*nslab + s)*8192;
    const float4* ip = (const float4*)(in + base);
    float4* op = (float4*)(out + base);
    for (int i = threadIdx.x; i < 2048; i += 256) {
        float4 v = ip[i];
        v.x = v.x*A + Bv; v.y = v.y*A + Bv; v.z = v.z*A + Bv; v.w = v.w*A + Bv;
        v.x = v.x / (1.f + __expf(-v.x));
        v.y = v.y / (1.f + __expf(-v.y));
        v.z = v.z / (1.f + __expf(-v.z));
        v.w = v.w / (1.f + __expf(-v.w));
        op[i] = v;
    }
}

// ---------------- conv3d oc=1 (FMA2, proven) ----------------
__global__ void __launch_bounds__(128) k_conv3d_oc1(const float* __restrict__ wts,
                                                    const float* __restrict__ bias) {
    __shared__ u64 swt[432];
    int tid = threadIdx.x;
    for (int i = tid; i < 432; i += 128) swt[i] = pk1(wts[i]);
    __syncthreads();
    int x = blockIdx.x;
    int ht = x & 7, d = (x >> 3) % 24, b = x / 192;
    int wt = tid & 15, hr = tid >> 4;
    int w0 = wt << 3, h = ht*8 + hr;
    u64 acc[4];
#pragma unroll
    for (int t = 0; t < 4; t++) acc[t] = 0ull;
    const float* inb = g_x2n + (size_t)b*16*DD*HW;
    for (int ic = 0; ic < 16; ic++) {
        const float* inc = inb + (size_t)ic*DD*HW;
#pragma unroll
        for (int kd = 0; kd < 3; kd++) {
            int zd = d + kd - 1;
            if ((unsigned)zd >= (unsigned)DD) continue;
#pragma unroll
            for (int kh = 0; kh < 3; kh++) {
                int zh = h + kh - 1;
                if ((unsigned)zh >= (unsigned)HH) continue;
                const float* row = inc + ((size_t)zd*HH + zh)*WW + w0;
                float r0 = (w0 == 0) ? 0.f : __ldg(row - 1);
                float4 va = *(const float4*)row;
                float4 vb = *(const float4*)(row + 4);
                float r9 = (w0 == 120) ? 0.f : __ldg(row + 8);
                u64 pe[5], po[4];
                pe[0] = pk(r0, va.x);  pe[1] = pk(va.y, va.z);
                pe[2] = pk(va.w, vb.x); pe[3] = pk(vb.y, vb.z);
                pe[4] = pk(vb.w, r9);
                po[0] = pk(va.x, va.y); po[1] = pk(va.z, va.w);
                po[2] = pk(vb.x, vb.y); po[3] = pk(vb.z, vb.w);
                int tb = (kd*3 + kh)*3;
                u64 wv0 = swt[ic*27 + tb + 0];
                u64 wv1 = swt[ic*27 + tb + 1];
                u64 wv2 = swt[ic*27 + tb + 2];
#pragma unroll
                for (int t = 0; t < 4; t++) {
                    fma2(acc[t], wv0, pe[t]);
                    fma2(acc[t], wv1, po[t]);
                    fma2(acc[t], wv2, pe[t + 1]);
                }
            }
        }
    }
    float bs = bias[0];
    float o[8];
#pragma unroll
    for (int t = 0; t < 4; t++) { float2 f = unpk(acc[t]); o[2*t] = f.x + bs; o[2*t+1] = f.y + bs; }
    float* orow = g_logits + (((size_t)b*DD + d)*HH + h)*WW + w0;
    *(float4*)orow       = make_float4(o[0], o[1], o[2], o[3]);
    *(float4*)(orow + 4) = make_float4(o[4], o[5], o[6], o[7]);
}

// ---------------- softmax (proven) ----------------
__global__ void __launch_bounds__(128) k_softmax(float* __restrict__ out) {
    int x = blockIdx.x;
    int h = x & 63, b = x >> 6;
    int w = threadIdx.x;
    const float* lp = g_logits + ((size_t)b*DD*HH + h)*WW + w;
    float l[DD];
    float m = -1e30f;
#pragma unroll
    for (int d = 0; d < DD; d++) { l[d] = lp[(size_t)d*HW]; m = fmaxf(m, l[d]); }
    float S = 0.f, E = 0.f;
#pragma unroll
    for (int d = 0; d < DD; d++) {
        float e = __expf(l[d] - m);
        S += e; E += e * (float)d;
    }
    float inv = 1.f / S;
    int oi = (b*HH + h)*WW + w;
    out[oi]           = E * inv;
    out[65536 + oi]   = 0.f;
    out[131072 + oi]  = 0.f;
    out[1245184 + oi] = inv;
}

// ---------------- launch ----------------
extern "C" void kernel_launch(void* const* d_in, const int* in_sizes, int n_in,
                              void* d_out, int out_size) {
    const float* fL    = (const float*)d_in[0];
    const float* fR    = (const float*)d_in[1];
    const float* w1    = (const float*)d_in[2];
    const float* gn1w  = (const float*)d_in[3];
    const float* gn1b  = (const float*)d_in[4];
    const float* w2    = (const float*)d_in[5];
    const float* gn2w  = (const float*)d_in[6];
    const float* gn2b  = (const float*)d_in[7];
    const float* w3    = (const float*)d_in[8];
    const float* b3    = (const float*)d_in[9];
    const float* fhw   = (const float*)d_in[10];
    const float* fhgnw = (const float*)d_in[11];
    const float* fhgnb = (const float*)d_in[12];
    float* out = (float*)d_out;

    const float invN3d = 1.0f / (2.0f*DD*HH*WW);
    const float invN2d = 1.0f / (2.0f*HH*WW);

    cudaFuncSetAttribute(k_costvol,     cudaFuncAttributeMaxDynamicSharedMemorySize, 131072);
    cudaFuncSetAttribute(k_conv_tc<8>,  cudaFuncAttributeMaxDynamicSharedMemorySize, CONV_SMEM);
    cudaFuncSetAttribute(k_conv_tc<16>, cudaFuncAttributeMaxDynamicSharedMemorySize, CONV_SMEM);
    cudaFuncSetAttribute(k_feat_tc,     cudaFuncAttributeMaxDynamicSharedMemorySize, FEAT_SMEM);

    k_zero_stats<<<1, 384>>>();                                  // 0
    k_costvol<<<BATCH*HH, 256, 131072>>>(fL, fR);                // 1
    k_zero_stats<<<1, 384>>>();                                  // 2 (dummy)
    k_conv_tc<8><<<2048, 256, CONV_SMEM>>>(w1);                  // 3 <-- profiled
    k_norm_pack<<<BATCH*24*32, 256>>>(gn1w, gn1b);               // 4
    k_conv_tc<16><<<2048, 256, CONV_SMEM>>>(w2);                 // 5
    k_norm<<<BATCH*16*24, 256>>>(1, nullptr, gn2w, gn2b, 24, invN3d);  // 6
    k_conv3d_oc1<<<BATCH*24*8, 128>>>(w3, b3);                   // 7
    k_softmax<<<BATCH*HH, 128>>>(out);                           // 8
    k_packfL<<<BATCH*HH, 256>>>(fL);                             // 9
    k_feat_tc<<<BATCH*32*2, 256, FEAT_SMEM>>>(fhw);              // 10
    k_norm<<<BATCH*16, 256>>>(2, out + 196608, fhgnw, fhgnb, 1, invN2d); // 11
}

// round 15
// speedup vs baseline: 2.6211x; 1.1005x over previous
#include <cuda_runtime.h>
#include <cuda_fp16.h>
#include <math.h>

#define BATCH 8
#define DD 24
#define HH 64
#define WW 128
#define HW (HH*WW)

typedef unsigned long long u64;
typedef unsigned int u32;
typedef unsigned short u16;

// ---------------- packed fp32x2 helpers ----------------
__device__ __forceinline__ u64 pk(float lo, float hi) {
    u64 r; asm("mov.b64 %0, {%1,%2};" : "=l"(r) : "f"(lo), "f"(hi)); return r;
}
__device__ __forceinline__ u64 pk1(float v) { return pk(v, v); }
__device__ __forceinline__ void fma2(u64& d, u64 a, u64 b) {
    asm("fma.rn.f32x2 %0, %1, %2, %0;" : "+l"(d) : "l"(a), "l"(b));
}
__device__ __forceinline__ float2 unpk(u64 v) {
    float2 f; asm("mov.b64 {%0,%1}, %2;" : "=f"(f.x), "=f"(f.y) : "l"(v)); return f;
}

// ---------------- mma / ldmatrix helpers ----------------
__device__ __forceinline__ u32 smem_u32(const void* p) {
    u32 a; asm("{ .reg .u64 t; cvta.to.shared.u64 t, %1; cvt.u32.u64 %0, t; }" : "=r"(a) : "l"(p));
    return a;
}
__device__ __forceinline__ void ldsm4(u32 a, u32& r0, u32& r1, u32& r2, u32& r3) {
    asm volatile("ldmatrix.sync.aligned.m8n8.x4.shared.b16 {%0,%1,%2,%3}, [%4];"
                 : "=r"(r0), "=r"(r1), "=r"(r2), "=r"(r3) : "r"(a));
}
__device__ __forceinline__ void mma16816h(float* d, u32 a0, u32 a1, u32 a2, u32 a3, u32 b0, u32 b1) {
    asm volatile("mma.sync.aligned.m16n8k16.row.col.f32.f16.f16.f32 "
                 "{%0,%1,%2,%3}, {%4,%5,%6,%7}, {%8,%9}, {%0,%1,%2,%3};"
                 : "+f"(d[0]), "+f"(d[1]), "+f"(d[2]), "+f"(d[3])
                 : "r"(a0), "r"(a1), "r"(a2), "r"(a3), "r"(b0), "r"(b1));
}
__device__ __forceinline__ void cp16(u32 dst, const void* src) {
    asm volatile("cp.async.ca.shared.global [%0], [%1], 16;" :: "r"(dst), "l"(src));
}
__device__ __forceinline__ u16 hfb(float f) {
    return __half_as_ushort(__float2half(f));
}

// ---------------- scratch ----------------
__device__ __align__(16) char g_cvp[(size_t)BATCH*DD*HH*WW*16];  // packed cv, 16B/voxel
__device__ float g_x1[BATCH*16*DD*HH*WW];
__device__ __align__(16) char g_x1p[(size_t)BATCH*DD*HH*WW*32];  // packed x1n, 32B/voxel
__device__ float g_x2[BATCH*16*DD*HH*WW];
__device__ float g_x2n[BATCH*16*DD*HH*WW];
__device__ float g_logits[BATCH*DD*HH*WW];
__device__ float g_feat[BATCH*16*HH*WW];
__device__ __align__(16) char g_fLp[(size_t)BATCH*HH*WW*256];    // packed fL, 256B/voxel
__device__ double g_stats[3*BATCH*8*2];
__device__ __align__(16) float g_zerobuf[4];   // zero-initialized

__global__ void k_zero_stats() {
    int i = threadIdx.x;
    if (i < 3*BATCH*8*2) g_stats[i] = 0.0;
}

// ---------------- cost volume -> packed fp16 + fused fL packing ----------------
__global__ void __launch_bounds__(256) k_costvol(const float* __restrict__ fL,
                                                 const float* __restrict__ fR) {
    extern __shared__ float scv[];
    float* sL = scv;
    float* sR = scv + 16384;
    int b = blockIdx.x >> 6, h = blockIdx.x & 63;
    int tid = threadIdx.x;
    for (int i = tid; i < 16384; i += 256) {
        size_t gidx = ((size_t)(b*128 + (i >> 7))*HH + h)*WW + (i & 127);
        sL[i] = fL[gidx];
        sR[i] = fR[gidx];
    }
    __syncthreads();
    int w = tid & 127, dh = tid >> 7;

    // fused: emit packed fL (channels-last fp16) straight from smem
#pragma unroll
    for (int q = 0; q < 4; q++) {
        int c8 = dh*4 + q;
        u32 pw[8];
#pragma unroll
        for (int j = 0; j < 8; j++) {
            float v0 = sL[(c8*16 + 2*j)*128 + w];
            float v1 = sL[(c8*16 + 2*j + 1)*128 + w];
            pw[j] = (u32)hfb(v0) | ((u32)hfb(v1) << 16);
        }
        u32* dst = (u32*)(g_fLp + (((size_t)b*64 + h)*128 + w)*256 + c8*32);
        *(uint4*)dst       = make_uint4(pw[0], pw[1], pw[2], pw[3]);
        *(uint4*)(dst + 4) = make_uint4(pw[4], pw[5], pw[6], pw[7]);
    }

    for (int dl = 0; dl < 12; dl++) {
        int d = dh*12 + dl;
        u32 pw[4];
#pragma unroll
        for (int gp = 0; gp < 4; gp++) {
            float s0 = 0.f, s1 = 0.f;
            if (w >= d) {
                const float* pL = sL + gp*32*128 + w;
                const float* pR = sR + gp*32*128 + w - d;
#pragma unroll
                for (int c = 0; c < 16; c++) {
                    s0 += pL[c*128] * pR[c*128];
                    s1 += pL[(16 + c)*128] * pR[(16 + c)*128];
                }
                s0 *= 0.0625f; s1 *= 0.0625f;
            }
            pw[gp] = (u32)hfb(s0) | ((u32)hfb(s1) << 16);
        }
        char* vox = g_cvp + ((((size_t)(b*24 + d)*64 + h)*128 + w)*16);
        *(uint4*)vox = make_uint4(pw[0], pw[1], pw[2], pw[3]);
    }
}

// ================= tensor-core conv3d: fp16, d-pairs, 4h x 64w tiles =========
// grid = B*16*4*2 (b, h-quad, d-sixth, w-half), block = 256 (8 warps = 4 hl x 2 wq)
// each warp: 2 w-tiles of 16 px -> B-fragments amortized over 2 tiles
#define ROW_B   48
#define NROWP   396                  // 6 zhl x 66 cols
#define PLANE_B (NROWP*ROW_B)        // 19008
#define W_OFF   (4*PLANE_B)          // 76032
#define WROW_B  48
#define CONV_SMEM (W_OFF + 27*16*WROW_B)  // 76032 + 20736 = 96768 -> 2 CTAs/SM

template<int CIN>
__global__ void __launch_bounds__(256) k_conv_tc(const float* __restrict__ wts) {
    float* out = (CIN == 8) ? g_x1 : g_x2;
    double* stats = g_stats + ((CIN == 8) ? 0 : 1)*128;

    extern __shared__ char smem[];
    char* w_sm = smem + W_OFF;
    __shared__ float sred[16];

    u32 a_base = smem_u32(smem);
    u32 w_base = smem_u32(w_sm);
    int tid = threadIdx.x, lane = tid & 31, wrp = tid >> 5;
    int hl = wrp >> 1, wq = wrp & 1;
    if (tid < 16) sred[tid] = 0.f;

    int x = blockIdx.x;
    int wt = x & 1, dq = (x >> 1) & 3, hp = (x >> 3) & 15, b = x >> 7;
    int d0 = dq*6, h0 = hp*4, wg0 = wt*64;

    // zero all 4 plane slots once
    for (int i = tid; i < 4*PLANE_B/4; i += 256) ((u32*)smem)[i] = 0u;

    // weights: [tap][oc] rows of 48B (16 ic fp16 in bytes 0..31)
    for (int i = tid; i < 27*256; i += 256) {
        int ic = i & 15, oc = (i >> 4) & 15, tap = i >> 8;
        float v = (ic < CIN) ? wts[(oc*CIN + ic)*27 + tap] : 0.f;
        *(u16*)(w_sm + (tap*16 + oc)*WROW_B + ic*2) = hfb(v);
    }
    __syncthreads();

    // stage fully rewrites bytes 0..31 of every row
    auto stage = [&](int zd) {
        int slot = (zd - d0 + 1) & 3;
        bool pv = ((unsigned)zd < 24u);
        for (int it = tid; it < 792; it += 256) {
            int ch = it & 1;
            int t2 = it >> 1;            // 0..395
            int zhl = t2 / 66;
            int wl = t2 - zhl*66;
            int zh = h0 - 1 + zhl;
            int wgl = wg0 + wl - 1;
            u32 dst = a_base + slot*PLANE_B + (u32)t2*ROW_B + ch*16;
            const void* src;
            bool iv = pv && (unsigned)zh < 64u && (unsigned)wgl < 128u;
            if (CIN == 8) {
                src = (iv && ch == 0)
                    ? (const void*)(g_cvp + ((((size_t)(b*24 + zd)*64 + zh)*128 + wgl)*16))
                    : (const void*)g_zerobuf;
            } else {
                src = iv
                    ? (const void*)(g_x1p + ((((size_t)(b*24 + zd)*64 + zh)*128 + wgl)*32 + ch*16))
                    : (const void*)g_zerobuf;
            }
            cp16(dst, src);
        }
    };

    float gsum[2] = {0.f, 0.f}, gss[2] = {0.f, 0.f};

    for (int pair = 0; pair < 3; pair++) {
        int d = d0 + 2*pair;
        if (pair == 0) {
            stage(d0 - 1); stage(d0); stage(d0 + 1); stage(d0 + 2);
        } else {
            stage(d + 1); stage(d + 2);
        }
        asm volatile("cp.async.commit_group;" ::: "memory");
        asm volatile("cp.async.wait_group 0;" ::: "memory");
        __syncthreads();

        float acc[2][2][2][4];   // [tile][dd][oh][r]
#pragma unroll
        for (int t = 0; t < 2; t++)
#pragma unroll
            for (int dd = 0; dd < 2; dd++)
#pragma unroll
                for (int oh = 0; oh < 2; oh++)
#pragma unroll
                    for (int r = 0; r < 4; r++) acc[t][dd][oh][r] = 0.f;

#pragma unroll
        for (int kh = 0; kh < 3; kh++) {
            int zhl = hl + kh;
#pragma unroll
            for (int kw = 0; kw < 3; kw++) {
                u32 bfr[3][4];
                int m = lane >> 3;
#pragma unroll
                for (int kd = 0; kd < 3; kd++) {
                    int tap = kd*9 + kh*3 + kw;
                    u32 ba = w_base + (u32)((tap*16 + (m >> 1)*8 + (lane & 7))*WROW_B + (m & 1)*16);
                    ldsm4(ba, bfr[kd][0], bfr[kd][1], bfr[kd][2], bfr[kd][3]);
                }
#pragma unroll
                for (int t = 0; t < 2; t++) {
                    int r = zhl*66 + wq*32 + t*16 + (lane & 15) + kw;
                    u32 rowoff = (u32)r*ROW_B + (lane >> 4)*16;
#pragma unroll
                    for (int q = 0; q < 4; q++) {
                        u32 pbase = a_base + (u32)((2*pair + q) & 3)*PLANE_B;
                        u32 a0, a1, a2, a3;
                        ldsm4(pbase + rowoff, a0, a1, a2, a3);
                        if (q <= 2) {
#pragma unroll
                            for (int oh = 0; oh < 2; oh++)
                                mma16816h(acc[t][0][oh], a0, a1, a2, a3, bfr[q][oh*2], bfr[q][oh*2+1]);
                        }
                        if (q >= 1) {
#pragma unroll
                            for (int oh = 0; oh < 2; oh++)
                                mma16816h(acc[t][1][oh], a0, a1, a2, a3, bfr[q-1][oh*2], bfr[q-1][oh*2+1]);
                        }
                    }
                }
            }
        }

        // stats
#pragma unroll
        for (int t = 0; t < 2; t++)
#pragma unroll
            for (int dd = 0; dd < 2; dd++)
#pragma unroll
                for (int oh = 0; oh < 2; oh++) {
                    float s = 0.f, s2 = 0.f;
#pragma unroll
                    for (int r = 0; r < 4; r++) { float v = acc[t][dd][oh][r]; s += v; s2 += v*v; }
                    gsum[oh] += s; gss[oh] += s2;
                }

        // bounce into the two retiring plane slots, then coalesced store
        __syncthreads();
#pragma unroll
        for (int dd = 0; dd < 2; dd++) {
            float* bounce = (float*)(smem + ((2*pair + dd) & 3)*PLANE_B);
#pragma unroll
            for (int t = 0; t < 2; t++)
#pragma unroll
                for (int oh = 0; oh < 2; oh++)
#pragma unroll
                    for (int r = 0; r < 4; r++) {
                        int oc = oh*8 + (lane & 3)*2 + (r & 1);
                        int px = wq*32 + t*16 + (lane >> 2) + (r >> 1)*8;
                        bounce[oc*264 + hl*64 + px] = acc[t][dd][oh][r];
                    }
        }
        __syncthreads();
        for (int i = tid; i < 2048; i += 256) {
            int dd = i >> 10, rem = i & 1023;
            int oc = rem >> 6, rem2 = rem & 63;
            int h2 = rem2 >> 4, w4 = rem2 & 15;
            const float* bounce = (const float*)(smem + ((2*pair + dd) & 3)*PLANE_B);
            float4 v = *(const float4*)&bounce[oc*264 + h2*64 + w4*4];
            float* ob = out + ((size_t)b*16*DD + d + dd)*HW;
            *(float4*)&ob[(size_t)oc*DD*HW + (h0 + h2)*WW + wg0 + w4*4] = v;
        }
        __syncthreads();
    }

    int g0 = lane & 3;
    atomicAdd(&sred[g0*2],         gsum[0]); atomicAdd(&sred[g0*2 + 1],         gss[0]);
    atomicAdd(&sred[(4 + g0)*2],   gsum[1]); atomicAdd(&sred[(4 + g0)*2 + 1],   gss[1]);
    __syncthreads();
    if (tid < 16) atomicAdd(&stats[b*16 + tid], (double)sred[tid]);
}

// ================= feature head: fp16 mma conv2d (proven) =================
#define FROW_B  48
#define FPLANE  (264*FROW_B)
#define FW_OFF  FPLANE
#define FEAT_SMEM (FPLANE + 8*9*16*FROW_B)   // 67968 -> 3 CTAs/SM

__global__ void __launch_bounds__(256) k_feat_tc(const float* __restrict__ wts) {
    extern __shared__ char smem[];
    char* w_sm = smem + FW_OFF;
    __shared__ float sred[16];

    u32 a_base = smem_u32(smem);
    u32 w_base = smem_u32(w_sm);
    int tid = threadIdx.x, lane = tid & 31, wrp = tid >> 5;
    int hl = wrp >> 2, wq = wrp & 3, w0l = wq*16;
    if (tid < 16) sred[tid] = 0.f;

    int x = blockIdx.x;
    int wt = x & 1, hp = (x >> 1) & 31, b = x >> 6;
    int h0 = hp*2, wg0 = wt*64;

    for (int i = tid; i < 18432; i += 256) {
        int icl = i & 15;
        int rest = i >> 4;
        int oc = rest & 15;
        int tapc = rest >> 4;
        int c = tapc / 9, tap = tapc - c*9;
        float v = wts[((size_t)oc*128 + c*16 + icl)*9 + tap];
        *(u16*)(w_sm + (tapc*16 + oc)*FROW_B + icl*2) = hfb(v);
    }
    __syncthreads();

    float acc[2][4];
#pragma unroll
    for (int oh = 0; oh < 2; oh++)
#pragma unroll
        for (int r = 0; r < 4; r++) acc[oh][r] = 0.f;

    for (int c = 0; c < 8; c++) {
        for (int it = tid; it < 528; it += 256) {
            int ch = it & 1;
            int t2 = it >> 1;
            int zhl = t2 / 66;
            int wl = t2 - zhl*66;
            int zh = h0 - 1 + zhl;
            int wgl = wg0 + wl - 1;
            u32 dst = a_base + (u32)t2*FROW_B + ch*16;
            const void* src = ((unsigned)zh < 64u && (unsigned)wgl < 128u)
                ? (const void*)(g_fLp + (((size_t)b*64 + zh)*128 + wgl)*256 + c*32 + ch*16)
                : (const void*)g_zerobuf;
            cp16(dst, src);
        }
        asm volatile("cp.async.commit_group;" ::: "memory");
        asm volatile("cp.async.wait_group 0;" ::: "memory");
        __syncthreads();

#pragma unroll
        for (int kh = 0; kh < 3; kh++) {
            int zhl = hl + kh;
#pragma unroll
            for (int kw = 0; kw < 3; kw++) {
                int tapc = c*9 + kh*3 + kw;
                int m = lane >> 3;
                u32 bfr0, bfr1, bfr2, bfr3;
                u32 ba = w_base + (u32)((tapc*16 + (m >> 1)*8 + (lane & 7))*FROW_B + (m & 1)*16);
                ldsm4(ba, bfr0, bfr1, bfr2, bfr3);
                int r = zhl*66 + w0l + (lane & 15) + kw;
                u32 a0, a1, a2, a3;
                ldsm4(a_base + (u32)r*FROW_B + (lane >> 4)*16, a0, a1, a2, a3);
                mma16816h(acc[0], a0, a1, a2, a3, bfr0, bfr1);
                mma16816h(acc[1], a0, a1, a2, a3, bfr2, bfr3);
            }
        }
        __syncthreads();
    }

    float gsum[2], gss[2];
#pragma unroll
    for (int oh = 0; oh < 2; oh++) {
        float s = 0.f, s2 = 0.f;
#pragma unroll
        for (int r = 0; r < 4; r++) { float v = acc[oh][r]; s += v; s2 += v*v; }
        gsum[oh] = s; gss[oh] = s2;
    }

    float* bounce = (float*)smem;
#pragma unroll
    for (int oh = 0; oh < 2; oh++)
#pragma unroll
        for (int r = 0; r < 4; r++) {
            int oc = oh*8 + (lane & 3)*2 + (r & 1);
            int px = w0l + (lane >> 2) + (r >> 1)*8;
            bounce[oc*132 + hl*64 + px] = acc[oh][r];
        }
    __syncthreads();
    for (int i = tid; i < 512; i += 256) {
        int oc = i >> 5, rem = i & 31;
        int h2 = rem >> 4, w4 = rem & 15;
        float4 v = *(const float4*)&bounce[oc*132 + h2*64 + w4*4];
        *(float4*)&g_feat[((size_t)(b*16 + oc)*HH + h0 + h2)*WW + wg0 + w4*4] = v;
    }

    int g0 = lane & 3;
    atomicAdd(&sred[g0*2],         gsum[0]); atomicAdd(&sred[g0*2 + 1],         gss[0]);
    atomicAdd(&sred[(4 + g0)*2],   gsum[1]); atomicAdd(&sred[(4 + g0)*2 + 1],   gss[1]);
    __syncthreads();
    if (tid < 16) atomicAdd(&g_stats[2*128 + b*16 + tid], (double)sred[tid]);
}

// ---------------- GN1 finalize + SiLU -> packed fp16 (proven) ----------------
__global__ void __launch_bounds__(256) k_norm_pack(const float* __restrict__ gw,
                                                   const float* __restrict__ gb) {
    __shared__ float sA[16], sB[16];
    int x = blockIdx.x;
    int hq = x & 31, d = (x >> 5) % 24, b = x / 768;
    int tid = threadIdx.x;
    if (tid < 16) {
        const double* p = g_stats + ((size_t)b*8 + (tid >> 1))*2;
        double mu = p[0] / 393216.0;
        double var = p[1] / 393216.0 - mu*mu;
        float rstd = rsqrtf((float)var + 1e-5f);
        float A = rstd * gw[tid];
        sA[tid] = A; sB[tid] = gb[tid] - (float)mu*A;
    }
    __syncthreads();
    int w = tid & 127, h = hq*2 + (tid >> 7);
    const float* base = g_x1 + ((size_t)b*16*DD + d)*HW + h*WW + w;
    u32 pw[8];
#pragma unroll
    for (int j = 0; j < 8; j++) {
        float v0 = base[(size_t)(2*j)*DD*HW];
        float v1 = base[(size_t)(2*j + 1)*DD*HW];
        float t0 = v0*sA[2*j] + sB[2*j];
        float t1 = v1*sA[2*j + 1] + sB[2*j + 1];
        t0 = t0 / (1.f + __expf(-t0));
        t1 = t1 / (1.f + __expf(-t1));
        pw[j] = (u32)hfb(t0) | ((u32)hfb(t1) << 16);
    }
    u32* dst = (u32*)(g_x1p + ((((size_t)(b*24 + d)*64 + h)*128 + w)*32));
    *(uint4*)dst       = make_uint4(pw[0], pw[1], pw[2], pw[3]);
    *(uint4*)(dst + 4) = make_uint4(pw[4], pw[5], pw[6], pw[7]);
}

// ---------------- GN finalize + apply + SiLU (layers 1,2) ----------------
__global__ void __launch_bounds__(256) k_norm(int which, float* outext,
                                              const float* __restrict__ gw,
                                              const float* __restrict__ gb,
                                              int nslab, float invN) {
    const float* in = (which == 1) ? g_x2 : g_feat;
    float* out = (which == 2) ? outext : g_x2n;
    const double* st = g_stats + which*128;
    __shared__ float sA, sB;
    int x = blockIdx.x;
    int s = x % nslab, c = (x / nslab) & 15, b = x / (nslab*16);
    if (threadIdx.x == 0) {
        const double* p = st + ((size_t)b*8 + (c >> 1))*2;
        double mu = p[0] * (double)invN;
        double var = p[1] * (double)invN - mu*mu;
        float rstd = rsqrtf((float)var + 1e-5f);
        float A = rstd * gw[c];
        sA = A; sB = gb[c] - (float)mu * A;
    }
    __syncthreads();
    float A = sA, Bv = sB;
    size_t base = ((size_t)(b*16 + c)*nslab + s)*8192;
    const float4* ip = (const float4*)(in + base);
    float4* op = (float4*)(out + base);
    for (int i = threadIdx.x; i < 2048; i += 256) {
        float4 v = ip[i];
        v.x = v.x*A + Bv; v.y = v.y*A + Bv; v.z = v.z*A + Bv; v.w = v.w*A + Bv;
        v.x = v.x / (1.f + __expf(-v.x));
        v.y = v.y / (1.f + __expf(-v.y));
        v.z = v.z / (1.f + __expf(-v.z));
        v.w = v.w / (1.f + __expf(-v.w));
        op[i] = v;
    }
}

// ---------------- conv3d oc=1 (FMA2, proven) ----------------
__global__ void __launch_bounds__(128) k_conv3d_oc1(const float* __restrict__ wts,
                                                    const float* __restrict__ bias) {
    __shared__ u64 swt[432];
    int tid = threadIdx.x;
    for (int i = tid; i < 432; i += 128) swt[i] = pk1(wts[i]);
    __syncthreads();
    int x = blockIdx.x;
    int ht = x & 7, d = (x >> 3) % 24, b = x / 192;
    int wt = tid & 15, hr = tid >> 4;
    int w0 = wt << 3, h = ht*8 + hr;
    u64 acc[4];
#pragma unroll
    for (int t = 0; t < 4; t++) acc[t] = 0ull;
    const float* inb = g_x2n + (size_t)b*16*DD*HW;
    for (int ic = 0; ic < 16; ic++) {
        const float* inc = inb + (size_t)ic*DD*HW;
#pragma unroll
        for (int kd = 0; kd < 3; kd++) {
            int zd = d + kd - 1;
            if ((unsigned)zd >= (unsigned)DD) continue;
#pragma unroll
            for (int kh = 0; kh < 3; kh++) {
                int zh = h + kh - 1;
                if ((unsigned)zh >= (unsigned)HH) continue;
                const float* row = inc + ((size_t)zd*HH + zh)*WW + w0;
                float r0 = (w0 == 0) ? 0.f : __ldg(row - 1);
                float4 va = *(const float4*)row;
                float4 vb = *(const float4*)(row + 4);
                float r9 = (w0 == 120) ? 0.f : __ldg(row + 8);
                u64 pe[5], po[4];
                pe[0] = pk(r0, va.x);  pe[1] = pk(va.y, va.z);
                pe[2] = pk(va.w, vb.x); pe[3] = pk(vb.y, vb.z);
                pe[4] = pk(vb.w, r9);
                po[0] = pk(va.x, va.y); po[1] = pk(va.z, va.w);
                po[2] = pk(vb.x, vb.y); po[3] = pk(vb.z, vb.w);
                int tb = (kd*3 + kh)*3;
                u64 wv0 = swt[ic*27 + tb + 0];
                u64 wv1 = swt[ic*27 + tb + 1];
                u64 wv2 = swt[ic*27 + tb + 2];
#pragma unroll
                for (int t = 0; t < 4; t++) {
                    fma2(acc[t], wv0, pe[t]);
                    fma2(acc[t], wv1, po[t]);
                    fma2(acc[t], wv2, pe[t + 1]);
                }
            }
        }
    }
    float bs = bias[0];
    float o[8];
#pragma unroll
    for (int t = 0; t < 4; t++) { float2 f = unpk(acc[t]); o[2*t] = f.x + bs; o[2*t+1] = f.y + bs; }
    float* orow = g_logits + (((size_t)b*DD + d)*HH + h)*WW + w0;
    *(float4*)orow       = make_float4(o[0], o[1], o[2], o[3]);
    *(float4*)(orow + 4) = make_float4(o[4], o[5], o[6], o[7]);
}

// ---------------- softmax (proven) ----------------
__global__ void __launch_bounds__(128) k_softmax(float* __restrict__ out) {
    int x = blockIdx.x;
    int h = x & 63, b = x >> 6;
    int w = threadIdx.x;
    const float* lp = g_logits + ((size_t)b*DD*HH + h)*WW + w;
    float l[DD];
    float m = -1e30f;
#pragma unroll
    for (int d = 0; d < DD; d++) { l[d] = lp[(size_t)d*HW]; m = fmaxf(m, l[d]); }
    float S = 0.f, E = 0.f;
#pragma unroll
    for (int d = 0; d < DD; d++) {
        float e = __expf(l[d] - m);
        S += e; E += e * (float)d;
    }
    float inv = 1.f / S;
    int oi = (b*HH + h)*WW + w;
    out[oi]           = E * inv;
    out[65536 + oi]   = 0.f;
    out[131072 + oi]  = 0.f;
    out[1245184 + oi] = inv;
}

// ---------------- launch ----------------
extern "C" void kernel_launch(void* const* d_in, const int* in_sizes, int n_in,
                              void* d_out, int out_size) {
    const float* fL    = (const float*)d_in[0];
    const float* fR    = (const float*)d_in[1];
    const float* w1    = (const float*)d_in[2];
    const float* gn1w  = (const float*)d_in[3];
    const float* gn1b  = (const float*)d_in[4];
    const float* w2    = (const float*)d_in[5];
    const float* gn2w  = (const float*)d_in[6];
    const float* gn2b  = (const float*)d_in[7];
    const float* w3    = (const float*)d_in[8];
    const float* b3    = (const float*)d_in[9];
    const float* fhw   = (const float*)d_in[10];
    const float* fhgnw = (const float*)d_in[11];
    const float* fhgnb = (const float*)d_in[12];
    float* out = (float*)d_out;

    const float invN3d = 1.0f / (2.0f*DD*HH*WW);
    const float invN2d = 1.0f / (2.0f*HH*WW);

    cudaFuncSetAttribute(k_costvol,     cudaFuncAttributeMaxDynamicSharedMemorySize, 131072);
    cudaFuncSetAttribute(k_conv_tc<8>,  cudaFuncAttributeMaxDynamicSharedMemorySize, CONV_SMEM);
    cudaFuncSetAttribute(k_conv_tc<16>, cudaFuncAttributeMaxDynamicSharedMemorySize, CONV_SMEM);
    cudaFuncSetAttribute(k_feat_tc,     cudaFuncAttributeMaxDynamicSharedMemorySize, FEAT_SMEM);

    k_zero_stats<<<1, 384>>>();                                  // 0
    k_costvol<<<BATCH*HH, 256, 131072>>>(fL, fR);                // 1
    k_zero_stats<<<1, 384>>>();                                  // 2 (dummy)
    k_conv_tc<8><<<1024, 256, CONV_SMEM>>>(w1);                  // 3 <-- profiled
    k_norm_pack<<<BATCH*24*32, 256>>>(gn1w, gn1b);               // 4
    k_conv_tc<16><<<1024, 256, CONV_SMEM>>>(w2);                 // 5
    k_norm<<<BATCH*16*24, 256>>>(1, nullptr, gn2w, gn2b, 24, invN3d);  // 6
    k_conv3d_oc1<<<BATCH*24*8, 128>>>(w3, b3);                   // 7
    k_softmax<<<BATCH*HH, 128>>>(out);                           // 8
    k_feat_tc<<<BATCH*32*2, 256, FEAT_SMEM>>>(fhw);              // 9
    k_norm<<<BATCH*16, 256>>>(2, out + 196608, fhgnw, fhgnb, 1, invN2d); // 10
}

// round 16
// speedup vs baseline: 2.7963x; 1.0668x over previous
#include <cuda_runtime.h>
#include <cuda_fp16.h>
#include <math.h>

#define BATCH 8
#define DD 24
#define HH 64
#define WW 128
#define HW (HH*WW)

typedef unsigned long long u64;
typedef unsigned int u32;
typedef unsigned short u16;

// ---------------- packed fp32x2 helpers ----------------
__device__ __forceinline__ u64 pk(float lo, float hi) {
    u64 r; asm("mov.b64 %0, {%1,%2};" : "=l"(r) : "f"(lo), "f"(hi)); return r;
}
__device__ __forceinline__ u64 pk1(float v) { return pk(v, v); }
__device__ __forceinline__ void fma2(u64& d, u64 a, u64 b) {
    asm("fma.rn.f32x2 %0, %1, %2, %0;" : "+l"(d) : "l"(a), "l"(b));
}
__device__ __forceinline__ float2 unpk(u64 v) {
    float2 f; asm("mov.b64 {%0,%1}, %2;" : "=f"(f.x), "=f"(f.y) : "l"(v)); return f;
}

// ---------------- mma / ldmatrix helpers ----------------
__device__ __forceinline__ u32 smem_u32(const void* p) {
    u32 a; asm("{ .reg .u64 t; cvta.to.shared.u64 t, %1; cvt.u32.u64 %0, t; }" : "=r"(a) : "l"(p));
    return a;
}
__device__ __forceinline__ void ldsm4(u32 a, u32& r0, u32& r1, u32& r2, u32& r3) {
    asm volatile("ldmatrix.sync.aligned.m8n8.x4.shared.b16 {%0,%1,%2,%3}, [%4];"
                 : "=r"(r0), "=r"(r1), "=r"(r2), "=r"(r3) : "r"(a));
}
__device__ __forceinline__ void mma16816h(float* d, u32 a0, u32 a1, u32 a2, u32 a3, u32 b0, u32 b1) {
    asm volatile("mma.sync.aligned.m16n8k16.row.col.f32.f16.f16.f32 "
                 "{%0,%1,%2,%3}, {%4,%5,%6,%7}, {%8,%9}, {%0,%1,%2,%3};"
                 : "+f"(d[0]), "+f"(d[1]), "+f"(d[2]), "+f"(d[3])
                 : "r"(a0), "r"(a1), "r"(a2), "r"(a3), "r"(b0), "r"(b1));
}
__device__ __forceinline__ void cp16(u32 dst, const void* src) {
    asm volatile("cp.async.ca.shared.global [%0], [%1], 16;" :: "r"(dst), "l"(src));
}
__device__ __forceinline__ u16 hfb(float f) {
    return __half_as_ushort(__float2half(f));
}
__device__ __forceinline__ float fbh(u16 b) {
    return __half2float(__ushort_as_half(b));
}

// ---------------- scratch ----------------
__device__ __align__(16) char g_cvp[(size_t)BATCH*DD*HH*WW*16];  // packed cv, 16B/voxel
__device__ __align__(16) char g_x1u[(size_t)BATCH*DD*HH*WW*32];  // conv1 raw packed fp16
__device__ __align__(16) char g_x1p[(size_t)BATCH*DD*HH*WW*32];  // x1 normed packed fp16
__device__ __align__(16) char g_x2u[(size_t)BATCH*DD*HH*WW*32];  // conv2 raw packed fp16
__device__ float g_x2n[BATCH*16*DD*HH*WW];                       // x2 normed fp32 planar
__device__ float g_logits[BATCH*DD*HH*WW];
__device__ float g_feat[BATCH*16*HH*WW];
__device__ __align__(16) char g_fLp[(size_t)BATCH*HH*WW*256];    // packed fL, 256B/voxel
__device__ double g_stats[3*BATCH*8*2];
__device__ __align__(16) float g_zerobuf[4];   // zero-initialized

__global__ void k_zero_stats() {
    int i = threadIdx.x;
    if (i < 3*BATCH*8*2) g_stats[i] = 0.0;
}

// ---------------- cost volume -> packed fp16 + fused fL packing (proven) ----------------
__global__ void __launch_bounds__(256) k_costvol(const float* __restrict__ fL,
                                                 const float* __restrict__ fR) {
    extern __shared__ float scv[];
    float* sL = scv;
    float* sR = scv + 16384;
    int b = blockIdx.x >> 6, h = blockIdx.x & 63;
    int tid = threadIdx.x;
    for (int i = tid; i < 16384; i += 256) {
        size_t gidx = ((size_t)(b*128 + (i >> 7))*HH + h)*WW + (i & 127);
        sL[i] = fL[gidx];
        sR[i] = fR[gidx];
    }
    __syncthreads();
    int w = tid & 127, dh = tid >> 7;

#pragma unroll
    for (int q = 0; q < 4; q++) {
        int c8 = dh*4 + q;
        u32 pw[8];
#pragma unroll
        for (int j = 0; j < 8; j++) {
            float v0 = sL[(c8*16 + 2*j)*128 + w];
            float v1 = sL[(c8*16 + 2*j + 1)*128 + w];
            pw[j] = (u32)hfb(v0) | ((u32)hfb(v1) << 16);
        }
        u32* dst = (u32*)(g_fLp + (((size_t)b*64 + h)*128 + w)*256 + c8*32);
        *(uint4*)dst       = make_uint4(pw[0], pw[1], pw[2], pw[3]);
        *(uint4*)(dst + 4) = make_uint4(pw[4], pw[5], pw[6], pw[7]);
    }

    for (int dl = 0; dl < 12; dl++) {
        int d = dh*12 + dl;
        u32 pw[4];
#pragma unroll
        for (int gp = 0; gp < 4; gp++) {
            float s0 = 0.f, s1 = 0.f;
            if (w >= d) {
                const float* pL = sL + gp*32*128 + w;
                const float* pR = sR + gp*32*128 + w - d;
#pragma unroll
                for (int c = 0; c < 16; c++) {
                    s0 += pL[c*128] * pR[c*128];
                    s1 += pL[(16 + c)*128] * pR[(16 + c)*128];
                }
                s0 *= 0.0625f; s1 *= 0.0625f;
            }
            pw[gp] = (u32)hfb(s0) | ((u32)hfb(s1) << 16);
        }
        char* vox = g_cvp + ((((size_t)(b*24 + d)*64 + h)*128 + w)*16);
        *(uint4*)vox = make_uint4(pw[0], pw[1], pw[2], pw[3]);
    }
}

// ================= tensor-core conv3d: fp16, d-pairs, 4h x 64w, packed output ======
#define ROW_B   48
#define NROWP   396
#define PLANE_B (NROWP*ROW_B)        // 19008
#define W_OFF   (4*PLANE_B)          // 76032
#define WROW_B  48
#define CONV_SMEM (W_OFF + 27*16*WROW_B)  // 96768 -> 2 CTAs/SM

template<int CIN>
__global__ void __launch_bounds__(256) k_conv_tc(const float* __restrict__ wts) {
    char* outu = (CIN == 8) ? g_x1u : g_x2u;
    double* stats = g_stats + ((CIN == 8) ? 0 : 1)*128;

    extern __shared__ char smem[];
    char* w_sm = smem + W_OFF;
    __shared__ float sred[16];

    u32 a_base = smem_u32(smem);
    u32 w_base = smem_u32(w_sm);
    int tid = threadIdx.x, lane = tid & 31, wrp = tid >> 5;
    int hl = wrp >> 1, wq = wrp & 1;
    if (tid < 16) sred[tid] = 0.f;

    int x = blockIdx.x;
    int wt = x & 1, dq = (x >> 1) & 3, hp = (x >> 3) & 15, b = x >> 7;
    int d0 = dq*6, h0 = hp*4, wg0 = wt*64;

    for (int i = tid; i < 4*PLANE_B/4; i += 256) ((u32*)smem)[i] = 0u;

    for (int i = tid; i < 27*256; i += 256) {
        int ic = i & 15, oc = (i >> 4) & 15, tap = i >> 8;
        float v = (ic < CIN) ? wts[(oc*CIN + ic)*27 + tap] : 0.f;
        *(u16*)(w_sm + (tap*16 + oc)*WROW_B + ic*2) = hfb(v);
    }
    __syncthreads();

    auto stage = [&](int zd) {
        int slot = (zd - d0 + 1) & 3;
        bool pv = ((unsigned)zd < 24u);
        for (int it = tid; it < 792; it += 256) {
            int ch = it & 1;
            int t2 = it >> 1;
            int zhl = t2 / 66;
            int wl = t2 - zhl*66;
            int zh = h0 - 1 + zhl;
            int wgl = wg0 + wl - 1;
            u32 dst = a_base + slot*PLANE_B + (u32)t2*ROW_B + ch*16;
            const void* src;
            bool iv = pv && (unsigned)zh < 64u && (unsigned)wgl < 128u;
            if (CIN == 8) {
                src = (iv && ch == 0)
                    ? (const void*)(g_cvp + ((((size_t)(b*24 + zd)*64 + zh)*128 + wgl)*16))
                    : (const void*)g_zerobuf;
            } else {
                src = iv
                    ? (const void*)(g_x1p + ((((size_t)(b*24 + zd)*64 + zh)*128 + wgl)*32 + ch*16))
                    : (const void*)g_zerobuf;
            }
            cp16(dst, src);
        }
    };

    float gsum[2] = {0.f, 0.f}, gss[2] = {0.f, 0.f};

    for (int pair = 0; pair < 3; pair++) {
        int d = d0 + 2*pair;
        if (pair == 0) {
            stage(d0 - 1); stage(d0); stage(d0 + 1); stage(d0 + 2);
        } else {
            stage(d + 1); stage(d + 2);
        }
        asm volatile("cp.async.commit_group;" ::: "memory");
        asm volatile("cp.async.wait_group 0;" ::: "memory");
        __syncthreads();

        float acc[2][2][2][4];
#pragma unroll
        for (int t = 0; t < 2; t++)
#pragma unroll
            for (int dd = 0; dd < 2; dd++)
#pragma unroll
                for (int oh = 0; oh < 2; oh++)
#pragma unroll
                    for (int r = 0; r < 4; r++) acc[t][dd][oh][r] = 0.f;

#pragma unroll
        for (int kh = 0; kh < 3; kh++) {
            int zhl = hl + kh;
#pragma unroll
            for (int kw = 0; kw < 3; kw++) {
                u32 bfr[3][4];
                int m = lane >> 3;
#pragma unroll
                for (int kd = 0; kd < 3; kd++) {
                    int tap = kd*9 + kh*3 + kw;
                    u32 ba = w_base + (u32)((tap*16 + (m >> 1)*8 + (lane & 7))*WROW_B + (m & 1)*16);
                    ldsm4(ba, bfr[kd][0], bfr[kd][1], bfr[kd][2], bfr[kd][3]);
                }
#pragma unroll
                for (int t = 0; t < 2; t++) {
                    int r = zhl*66 + wq*32 + t*16 + (lane & 15) + kw;
                    u32 rowoff = (u32)r*ROW_B + (lane >> 4)*16;
#pragma unroll
                    for (int q = 0; q < 4; q++) {
                        u32 pbase = a_base + (u32)((2*pair + q) & 3)*PLANE_B;
                        u32 a0, a1, a2, a3;
                        ldsm4(pbase + rowoff, a0, a1, a2, a3);
                        if (q <= 2) {
#pragma unroll
                            for (int oh = 0; oh < 2; oh++)
                                mma16816h(acc[t][0][oh], a0, a1, a2, a3, bfr[q][oh*2], bfr[q][oh*2+1]);
                        }
                        if (q >= 1) {
#pragma unroll
                            for (int oh = 0; oh < 2; oh++)
                                mma16816h(acc[t][1][oh], a0, a1, a2, a3, bfr[q-1][oh*2], bfr[q-1][oh*2+1]);
                        }
                    }
                }
            }
        }

        // stats
#pragma unroll
        for (int t = 0; t < 2; t++)
#pragma unroll
            for (int dd = 0; dd < 2; dd++)
#pragma unroll
                for (int oh = 0; oh < 2; oh++) {
                    float s = 0.f, s2 = 0.f;
#pragma unroll
                    for (int r = 0; r < 4; r++) { float v = acc[t][dd][oh][r]; s += v; s2 += v*v; }
                    gsum[oh] += s; gss[oh] += s2;
                }

        // bounce into the two retiring plane slots, then packed-voxel store
        __syncthreads();
#pragma unroll
        for (int dd = 0; dd < 2; dd++) {
            float* bounce = (float*)(smem + ((2*pair + dd) & 3)*PLANE_B);
#pragma unroll
            for (int t = 0; t < 2; t++)
#pragma unroll
                for (int oh = 0; oh < 2; oh++)
#pragma unroll
                    for (int r = 0; r < 4; r++) {
                        int oc = oh*8 + (lane & 3)*2 + (r & 1);
                        int px = wq*32 + t*16 + (lane >> 2) + (r >> 1)*8;
                        bounce[oc*264 + hl*64 + px] = acc[t][dd][oh][r];
                    }
        }
        __syncthreads();
        for (int i = tid; i < 512; i += 256) {
            int dd = i >> 8, rem = i & 255;
            int h2 = rem >> 6, wl = rem & 63;
            const float* bounce = (const float*)(smem + ((2*pair + dd) & 3)*PLANE_B);
            u32 pw[8];
#pragma unroll
            for (int j = 0; j < 8; j++) {
                float v0 = bounce[(2*j)*264 + h2*64 + wl];
                float v1 = bounce[(2*j + 1)*264 + h2*64 + wl];
                pw[j] = (u32)hfb(v0) | ((u32)hfb(v1) << 16);
            }
            u32* dst = (u32*)(outu + ((((size_t)(b*24 + d + dd)*64 + h0 + h2)*128 + wg0 + wl)*32));
            *(uint4*)dst       = make_uint4(pw[0], pw[1], pw[2], pw[3]);
            *(uint4*)(dst + 4) = make_uint4(pw[4], pw[5], pw[6], pw[7]);
        }
        __syncthreads();
    }

    int g0 = lane & 3;
    atomicAdd(&sred[g0*2],         gsum[0]); atomicAdd(&sred[g0*2 + 1],         gss[0]);
    atomicAdd(&sred[(4 + g0)*2],   gsum[1]); atomicAdd(&sred[(4 + g0)*2 + 1],   gss[1]);
    __syncthreads();
    if (tid < 16) atomicAdd(&stats[b*16 + tid], (double)sred[tid]);
}

// ---------------- GN1 finalize + SiLU: packed -> packed ----------------
__global__ void __launch_bounds__(256) k_norm_pack(const float* __restrict__ gw,
                                                   const float* __restrict__ gb) {
    __shared__ float sA[16], sB[16];
    int x = blockIdx.x;
    int hq = x & 31, d = (x >> 5) % 24, b = x / 768;
    int tid = threadIdx.x;
    if (tid < 16) {
        const double* p = g_stats + ((size_t)b*8 + (tid >> 1))*2;
        double mu = p[0] / 393216.0;
        double var = p[1] / 393216.0 - mu*mu;
        float rstd = rsqrtf((float)var + 1e-5f);
        float A = rstd * gw[tid];
        sA[tid] = A; sB[tid] = gb[tid] - (float)mu*A;
    }
    __syncthreads();
    int w = tid & 127, h = hq*2 + (tid >> 7);
    size_t vox = (((size_t)(b*24 + d)*64 + h)*128 + w)*32;
    const uint4* src = (const uint4*)(g_x1u + vox);
    uint4 lo = src[0], hi = src[1];
    u32 in[8] = {lo.x, lo.y, lo.z, lo.w, hi.x, hi.y, hi.z, hi.w};
    u32 pw[8];
#pragma unroll
    for (int j = 0; j < 8; j++) {
        float v0 = fbh((u16)(in[j] & 0xFFFF));
        float v1 = fbh((u16)(in[j] >> 16));
        float t0 = v0*sA[2*j] + sB[2*j];
        float t1 = v1*sA[2*j + 1] + sB[2*j + 1];
        t0 = t0 / (1.f + __expf(-t0));
        t1 = t1 / (1.f + __expf(-t1));
        pw[j] = (u32)hfb(t0) | ((u32)hfb(t1) << 16);
    }
    uint4* dst = (uint4*)(g_x1p + vox);
    dst[0] = make_uint4(pw[0], pw[1], pw[2], pw[3]);
    dst[1] = make_uint4(pw[4], pw[5], pw[6], pw[7]);
}

// ---------------- GN2 finalize + SiLU: packed -> planar fp32 ----------------
__global__ void __launch_bounds__(256) k_norm2pl(const float* __restrict__ gw,
                                                 const float* __restrict__ gb) {
    __shared__ float sA[16], sB[16];
    int x = blockIdx.x;
    int hq = x & 31, d = (x >> 5) % 24, b = x / 768;
    int tid = threadIdx.x;
    if (tid < 16) {
        const double* p = g_stats + 128 + ((size_t)b*8 + (tid >> 1))*2;
        double mu = p[0] / 393216.0;
        double var = p[1] / 393216.0 - mu*mu;
        float rstd = rsqrtf((float)var + 1e-5f);
        float A = rstd * gw[tid];
        sA[tid] = A; sB[tid] = gb[tid] - (float)mu*A;
    }
    __syncthreads();
    int w = tid & 127, h = hq*2 + (tid >> 7);
    const uint4* src = (const uint4*)(g_x2u + (((size_t)(b*24 + d)*64 + h)*128 + w)*32);
    uint4 lo = src[0], hi = src[1];
    u32 in[8] = {lo.x, lo.y, lo.z, lo.w, hi.x, hi.y, hi.z, hi.w};
    float* outb = g_x2n + ((size_t)b*16*DD + d)*HW + h*WW + w;
#pragma unroll
    for (int j = 0; j < 8; j++) {
        float v0 = fbh((u16)(in[j] & 0xFFFF));
        float v1 = fbh((u16)(in[j] >> 16));
        float t0 = v0*sA[2*j] + sB[2*j];
        float t1 = v1*sA[2*j + 1] + sB[2*j + 1];
        t0 = t0 / (1.f + __expf(-t0));
        t1 = t1 / (1.f + __expf(-t1));
        outb[(size_t)(2*j)*DD*HW]     = t0;
        outb[(size_t)(2*j + 1)*DD*HW] = t1;
    }
}

// ---------------- GN finalize + apply + SiLU (feat head only) ----------------
__global__ void __launch_bounds__(256) k_norm(float* outext,
                                              const float* __restrict__ gw,
                                              const float* __restrict__ gb) {
    const double* st = g_stats + 2*128;
    __shared__ float sA, sB;
    int x = blockIdx.x;
    int c = x & 15, b = x >> 4;
    if (threadIdx.x == 0) {
        const double* p = st + ((size_t)b*8 + (c >> 1))*2;
        double mu = p[0] / 16384.0;
        double var = p[1] / 16384.0 - mu*mu;
        float rstd = rsqrtf((float)var + 1e-5f);
        float A = rstd * gw[c];
        sA = A; sB = gb[c] - (float)mu * A;
    }
    __syncthreads();
    float A = sA, Bv = sB;
    size_t base = ((size_t)(b*16 + c))*8192;
    const float4* ip = (const float4*)(g_feat + base);
    float4* op = (float4*)(outext + base);
    for (int i = threadIdx.x; i < 2048; i += 256) {
        float4 v = ip[i];
        v.x = v.x*A + Bv; v.y = v.y*A + Bv; v.z = v.z*A + Bv; v.w = v.w*A + Bv;
        v.x = v.x / (1.f + __expf(-v.x));
        v.y = v.y / (1.f + __expf(-v.y));
        v.z = v.z / (1.f + __expf(-v.z));
        v.w = v.w / (1.f + __expf(-v.w));
        op[i] = v;
    }
}

// ---------------- conv3d oc=1 (FMA2, proven) ----------------
__global__ void __launch_bounds__(128) k_conv3d_oc1(const float* __restrict__ wts,
                                                    const float* __restrict__ bias) {
    __shared__ u64 swt[432];
    int tid = threadIdx.x;
    for (int i = tid; i < 432; i += 128) swt[i] = pk1(wts[i]);
    __syncthreads();
    int x = blockIdx.x;
    int ht = x & 7, d = (x >> 3) % 24, b = x / 192;
    int wt = tid & 15, hr = tid >> 4;
    int w0 = wt << 3, h = ht*8 + hr;
    u64 acc[4];
#pragma unroll
    for (int t = 0; t < 4; t++) acc[t] = 0ull;
    const float* inb = g_x2n + (size_t)b*16*DD*HW;
    for (int ic = 0; ic < 16; ic++) {
        const float* inc = inb + (size_t)ic*DD*HW;
#pragma unroll
        for (int kd = 0; kd < 3; kd++) {
            int zd = d + kd - 1;
            if ((unsigned)zd >= (unsigned)DD) continue;
#pragma unroll
            for (int kh = 0; kh < 3; kh++) {
                int zh = h + kh - 1;
                if ((unsigned)zh >= (unsigned)HH) continue;
                const float* row = inc + ((size_t)zd*HH + zh)*WW + w0;
                float r0 = (w0 == 0) ? 0.f : __ldg(row - 1);
                float4 va = *(const float4*)row;
                float4 vb = *(const float4*)(row + 4);
                float r9 = (w0 == 120) ? 0.f : __ldg(row + 8);
                u64 pe[5], po[4];
                pe[0] = pk(r0, va.x);  pe[1] = pk(va.y, va.z);
                pe[2] = pk(va.w, vb.x); pe[3] = pk(vb.y, vb.z);
                pe[4] = pk(vb.w, r9);
                po[0] = pk(va.x, va.y); po[1] = pk(va.z, va.w);
                po[2] = pk(vb.x, vb.y); po[3] = pk(vb.z, vb.w);
                int tb = (kd*3 + kh)*3;
                u64 wv0 = swt[ic*27 + tb + 0];
                u64 wv1 = swt[ic*27 + tb + 1];
                u64 wv2 = swt[ic*27 + tb + 2];
#pragma unroll
                for (int t = 0; t < 4; t++) {
                    fma2(acc[t], wv0, pe[t]);
                    fma2(acc[t], wv1, po[t]);
                    fma2(acc[t], wv2, pe[t + 1]);
                }
            }
        }
    }
    float bs = bias[0];
    float o[8];
#pragma unroll
    for (int t = 0; t < 4; t++) { float2 f = unpk(acc[t]); o[2*t] = f.x + bs; o[2*t+1] = f.y + bs; }
    float* orow = g_logits + (((size_t)b*DD + d)*HH + h)*WW + w0;
    *(float4*)orow       = make_float4(o[0], o[1], o[2], o[3]);
    *(float4*)(orow + 4) = make_float4(o[4], o[5], o[6], o[7]);
}

// ---------------- softmax (proven) ----------------
__global__ void __launch_bounds__(128) k_softmax(float* __restrict__ out) {
    int x = blockIdx.x;
    int h = x & 63, b = x >> 6;
    int w = threadIdx.x;
    const float* lp = g_logits + ((size_t)b*DD*HH + h)*WW + w;
    float l[DD];
    float m = -1e30f;
#pragma unroll
    for (int d = 0; d < DD; d++) { l[d] = lp[(size_t)d*HW]; m = fmaxf(m, l[d]); }
    float S = 0.f, E = 0.f;
#pragma unroll
    for (int d = 0; d < DD; d++) {
        float e = __expf(l[d] - m);
        S += e; E += e * (float)d;
    }
    float inv = 1.f / S;
    int oi = (b*HH + h)*WW + w;
    out[oi]           = E * inv;
    out[65536 + oi]   = 0.f;
    out[131072 + oi]  = 0.f;
    out[1245184 + oi] = inv;
}

// ================= feature head: fp16 mma conv2d (proven) =================
#define FROW_B  48
#define FPLANE  (264*FROW_B)
#define FW_OFF  FPLANE
#define FEAT_SMEM (FPLANE + 8*9*16*FROW_B)   // 67968 -> 3 CTAs/SM

__global__ void __launch_bounds__(256) k_feat_tc(const float* __restrict__ wts) {
    extern __shared__ char smem[];
    char* w_sm = smem + FW_OFF;
    __shared__ float sred[16];

    u32 a_base = smem_u32(smem);
    u32 w_base = smem_u32(w_sm);
    int tid = threadIdx.x, lane = tid & 31, wrp = tid >> 5;
    int hl = wrp >> 2, wq = wrp & 3, w0l = wq*16;
    if (tid < 16) sred[tid] = 0.f;

    int x = blockIdx.x;
    int wt = x & 1, hp = (x >> 1) & 31, b = x >> 6;
    int h0 = hp*2, wg0 = wt*64;

    for (int i = tid; i < 18432; i += 256) {
        int icl = i & 15;
        int rest = i >> 4;
        int oc = rest & 15;
        int tapc = rest >> 4;
        int c = tapc / 9, tap = tapc - c*9;
        float v = wts[((size_t)oc*128 + c*16 + icl)*9 + tap];
        *(u16*)(w_sm + (tapc*16 + oc)*FROW_B + icl*2) = hfb(v);
    }
    __syncthreads();

    float acc[2][4];
#pragma unroll
    for (int oh = 0; oh < 2; oh++)
#pragma unroll
        for (int r = 0; r < 4; r++) acc[oh][r] = 0.f;

    for (int c = 0; c < 8; c++) {
        for (int it = tid; it < 528; it += 256) {
            int ch = it & 1;
            int t2 = it >> 1;
            int zhl = t2 / 66;
            int wl = t2 - zhl*66;
            int zh = h0 - 1 + zhl;
            int wgl = wg0 + wl - 1;
            u32 dst = a_base + (u32)t2*FROW_B + ch*16;
            const void* src = ((unsigned)zh < 64u && (unsigned)wgl < 128u)
                ? (const void*)(g_fLp + (((size_t)b*64 + zh)*128 + wgl)*256 + c*32 + ch*16)
                : (const void*)g_zerobuf;
            cp16(dst, src);
        }
        asm volatile("cp.async.commit_group;" ::: "memory");
        asm volatile("cp.async.wait_group 0;" ::: "memory");
        __syncthreads();

#pragma unroll
        for (int kh = 0; kh < 3; kh++) {
            int zhl = hl + kh;
#pragma unroll
            for (int kw = 0; kw < 3; kw++) {
                int tapc = c*9 + kh*3 + kw;
                int m = lane >> 3;
                u32 bfr0, bfr1, bfr2, bfr3;
                u32 ba = w_base + (u32)((tapc*16 + (m >> 1)*8 + (lane & 7))*FROW_B + (m & 1)*16);
                ldsm4(ba, bfr0, bfr1, bfr2, bfr3);
                int r = zhl*66 + w0l + (lane & 15) + kw;
                u32 a0, a1, a2, a3;
                ldsm4(a_base + (u32)r*FROW_B + (lane >> 4)*16, a0, a1, a2, a3);
                mma16816h(acc[0], a0, a1, a2, a3, bfr0, bfr1);
                mma16816h(acc[1], a0, a1, a2, a3, bfr2, bfr3);
            }
        }
        __syncthreads();
    }

    float gsum[2], gss[2];
#pragma unroll
    for (int oh = 0; oh < 2; oh++) {
        float s = 0.f, s2 = 0.f;
#pragma unroll
        for (int r = 0; r < 4; r++) { float v = acc[oh][r]; s += v; s2 += v*v; }
        gsum[oh] = s; gss[oh] = s2;
    }

    float* bounce = (float*)smem;
#pragma unroll
    for (int oh = 0; oh < 2; oh++)
#pragma unroll
        for (int r = 0; r < 4; r++) {
            int oc = oh*8 + (lane & 3)*2 + (r & 1);
            int px = w0l + (lane >> 2) + (r >> 1)*8;
            bounce[oc*132 + hl*64 + px] = acc[oh][r];
        }
    __syncthreads();
    for (int i = tid; i < 512; i += 256) {
        int oc = i >> 5, rem = i & 31;
        int h2 = rem >> 4, w4 = rem & 15;
        float4 v = *(const float4*)&bounce[oc*132 + h2*64 + w4*4];
        *(float4*)&g_feat[((size_t)(b*16 + oc)*HH + h0 + h2)*WW + wg0 + w4*4] = v;
    }

    int g0 = lane & 3;
    atomicAdd(&sred[g0*2],         gsum[0]); atomicAdd(&sred[g0*2 + 1],         gss[0]);
    atomicAdd(&sred[(4 + g0)*2],   gsum[1]); atomicAdd(&sred[(4 + g0)*2 + 1],   gss[1]);
    __syncthreads();
    if (tid < 16) atomicAdd(&g_stats[2*128 + b*16 + tid], (double)sred[tid]);
}

// ---------------- launch ----------------
extern "C" void kernel_launch(void* const* d_in, const int* in_sizes, int n_in,
                              void* d_out, int out_size) {
    const float* fL    = (const float*)d_in[0];
    const float* fR    = (const float*)d_in[1];
    const float* w1    = (const float*)d_in[2];
    const float* gn1w  = (const float*)d_in[3];
    const float* gn1b  = (const float*)d_in[4];
    const float* w2    = (const float*)d_in[5];
    const float* gn2w  = (const float*)d_in[6];
    const float* gn2b  = (const float*)d_in[7];
    const float* w3    = (const float*)d_in[8];
    const float* b3    = (const float*)d_in[9];
    const float* fhw   = (const float*)d_in[10];
    const float* fhgnw = (const float*)d_in[11];
    const float* fhgnb = (const float*)d_in[12];
    float* out = (float*)d_out;

    cudaFuncSetAttribute(k_costvol,     cudaFuncAttributeMaxDynamicSharedMemorySize, 131072);
    cudaFuncSetAttribute(k_conv_tc<8>,  cudaFuncAttributeMaxDynamicSharedMemorySize, CONV_SMEM);
    cudaFuncSetAttribute(k_conv_tc<16>, cudaFuncAttributeMaxDynamicSharedMemorySize, CONV_SMEM);
    cudaFuncSetAttribute(k_feat_tc,     cudaFuncAttributeMaxDynamicSharedMemorySize, FEAT_SMEM);

    k_zero_stats<<<1, 384>>>();                                  // 0
    k_costvol<<<BATCH*HH, 256, 131072>>>(fL, fR);                // 1
    k_zero_stats<<<1, 384>>>();                                  // 2 (dummy)
    k_conv_tc<8><<<1024, 256, CONV_SMEM>>>(w1);                  // 3 <-- profiled
    k_norm_pack<<<BATCH*24*32, 256>>>(gn1w, gn1b);               // 4
    k_conv_tc<16><<<1024, 256, CONV_SMEM>>>(w2);                 // 5
    k_norm2pl<<<BATCH*24*32, 256>>>(gn2w, gn2b);                 // 6
    k_conv3d_oc1<<<BATCH*24*8, 128>>>(w3, b3);                   // 7
    k_softmax<<<BATCH*HH, 128>>>(out);                           // 8
    k_feat_tc<<<BATCH*32*2, 256, FEAT_SMEM>>>(fhw);              // 9
    k_norm<<<BATCH*16, 256>>>(out + 196608, fhgnw, fhgnb);       // 10
}

// round 17
// speedup vs baseline: 2.9422x; 1.0522x over previous
#include <cuda_runtime.h>
#include <cuda_fp16.h>
#include <math.h>

#define BATCH 8
#define DD 24
#define HH 64
#define WW 128
#define HW (HH*WW)

typedef unsigned long long u64;
typedef unsigned int u32;
typedef unsigned short u16;

// ---------------- packed fp32x2 helpers ----------------
__device__ __forceinline__ u64 pk(float lo, float hi) {
    u64 r; asm("mov.b64 %0, {%1,%2};" : "=l"(r) : "f"(lo), "f"(hi)); return r;
}
__device__ __forceinline__ u64 pk1(float v) { return pk(v, v); }
__device__ __forceinline__ void fma2(u64& d, u64 a, u64 b) {
    asm("fma.rn.f32x2 %0, %1, %2, %0;" : "+l"(d) : "l"(a), "l"(b));
}
__device__ __forceinline__ float2 unpk(u64 v) {
    float2 f; asm("mov.b64 {%0,%1}, %2;" : "=f"(f.x), "=f"(f.y) : "l"(v)); return f;
}

// ---------------- mma / ldmatrix helpers ----------------
__device__ __forceinline__ u32 smem_u32(const void* p) {
    u32 a; asm("{ .reg .u64 t; cvta.to.shared.u64 t, %1; cvt.u32.u64 %0, t; }" : "=r"(a) : "l"(p));
    return a;
}
__device__ __forceinline__ void ldsm4(u32 a, u32& r0, u32& r1, u32& r2, u32& r3) {
    asm volatile("ldmatrix.sync.aligned.m8n8.x4.shared.b16 {%0,%1,%2,%3}, [%4];"
                 : "=r"(r0), "=r"(r1), "=r"(r2), "=r"(r3) : "r"(a));
}
__device__ __forceinline__ void mma16816h(float* d, u32 a0, u32 a1, u32 a2, u32 a3, u32 b0, u32 b1) {
    asm volatile("mma.sync.aligned.m16n8k16.row.col.f32.f16.f16.f32 "
                 "{%0,%1,%2,%3}, {%4,%5,%6,%7}, {%8,%9}, {%0,%1,%2,%3};"
                 : "+f"(d[0]), "+f"(d[1]), "+f"(d[2]), "+f"(d[3])
                 : "r"(a0), "r"(a1), "r"(a2), "r"(a3), "r"(b0), "r"(b1));
}
__device__ __forceinline__ void cp16(u32 dst, const void* src) {
    asm volatile("cp.async.ca.shared.global [%0], [%1], 16;" :: "r"(dst), "l"(src));
}
__device__ __forceinline__ u16 hfb(float f) {
    return __half_as_ushort(__float2half(f));
}
__device__ __forceinline__ float fbh(u16 b) {
    return __half2float(__ushort_as_half(b));
}

// ---------------- scratch ----------------
__device__ __align__(16) char g_cvp[(size_t)BATCH*DD*HH*WW*16];  // packed cv, 16B/voxel
__device__ __align__(16) char g_x1u[(size_t)BATCH*DD*HH*WW*32];  // conv1 raw packed fp16
__device__ __align__(16) char g_x1p[(size_t)BATCH*DD*HH*WW*32];  // x1 normed packed fp16
__device__ __align__(16) char g_x2u[(size_t)BATCH*DD*HH*WW*32];  // conv2 raw packed fp16
__device__ float g_x2n[BATCH*16*DD*HH*WW];                       // x2 normed fp32 planar
__device__ float g_logits[BATCH*DD*HH*WW];
__device__ float g_feat[BATCH*16*HH*WW];
__device__ __align__(16) char g_fLp[(size_t)BATCH*HH*WW*256];    // packed fL, 256B/voxel
__device__ double g_stats[3*BATCH*8*2];
__device__ __align__(16) float g_zerobuf[4];   // zero-initialized

__global__ void k_zero_stats() {
    int i = threadIdx.x;
    if (i < 3*BATCH*8*2) g_stats[i] = 0.0;
}

// ---------------- cost volume -> packed fp16 + fused fL packing (proven) ----------------
__global__ void __launch_bounds__(256) k_costvol(const float* __restrict__ fL,
                                                 const float* __restrict__ fR) {
    extern __shared__ float scv[];
    float* sL = scv;
    float* sR = scv + 16384;
    int b = blockIdx.x >> 6, h = blockIdx.x & 63;
    int tid = threadIdx.x;
    for (int i = tid; i < 16384; i += 256) {
        size_t gidx = ((size_t)(b*128 + (i >> 7))*HH + h)*WW + (i & 127);
        sL[i] = fL[gidx];
        sR[i] = fR[gidx];
    }
    __syncthreads();
    int w = tid & 127, dh = tid >> 7;

#pragma unroll
    for (int q = 0; q < 4; q++) {
        int c8 = dh*4 + q;
        u32 pw[8];
#pragma unroll
        for (int j = 0; j < 8; j++) {
            float v0 = sL[(c8*16 + 2*j)*128 + w];
            float v1 = sL[(c8*16 + 2*j + 1)*128 + w];
            pw[j] = (u32)hfb(v0) | ((u32)hfb(v1) << 16);
        }
        u32* dst = (u32*)(g_fLp + (((size_t)b*64 + h)*128 + w)*256 + c8*32);
        *(uint4*)dst       = make_uint4(pw[0], pw[1], pw[2], pw[3]);
        *(uint4*)(dst + 4) = make_uint4(pw[4], pw[5], pw[6], pw[7]);
    }

    for (int dl = 0; dl < 12; dl++) {
        int d = dh*12 + dl;
        u32 pw[4];
#pragma unroll
        for (int gp = 0; gp < 4; gp++) {
            float s0 = 0.f, s1 = 0.f;
            if (w >= d) {
                const float* pL = sL + gp*32*128 + w;
                const float* pR = sR + gp*32*128 + w - d;
#pragma unroll
                for (int c = 0; c < 16; c++) {
                    s0 += pL[c*128] * pR[c*128];
                    s1 += pL[(16 + c)*128] * pR[(16 + c)*128];
                }
                s0 *= 0.0625f; s1 *= 0.0625f;
            }
            pw[gp] = (u32)hfb(s0) | ((u32)hfb(s1) << 16);
        }
        char* vox = g_cvp + ((((size_t)(b*24 + d)*64 + h)*128 + w)*16);
        *(uint4*)vox = make_uint4(pw[0], pw[1], pw[2], pw[3]);
    }
}

// ================= tensor-core conv3d: fp16, d-pairs, 4h x 64w, direct packed STG ===
#define ROW_B   48
#define NROWP   396
#define PLANE_B (NROWP*ROW_B)        // 19008
#define W_OFF   (4*PLANE_B)          // 76032
#define WROW_B  48
#define CONV_SMEM (W_OFF + 27*16*WROW_B)  // 96768 -> 2 CTAs/SM

template<int CIN>
__global__ void __launch_bounds__(256) k_conv_tc(const float* __restrict__ wts) {
    char* outu = (CIN == 8) ? g_x1u : g_x2u;
    double* stats = g_stats + ((CIN == 8) ? 0 : 1)*128;

    extern __shared__ char smem[];
    char* w_sm = smem + W_OFF;
    __shared__ float sred[16];

    u32 a_base = smem_u32(smem);
    u32 w_base = smem_u32(w_sm);
    int tid = threadIdx.x, lane = tid & 31, wrp = tid >> 5;
    int hl = wrp >> 1, wq = wrp & 1;
    if (tid < 16) sred[tid] = 0.f;

    int x = blockIdx.x;
    int wt = x & 1, dq = (x >> 1) & 3, hp = (x >> 3) & 15, b = x >> 7;
    int d0 = dq*6, h0 = hp*4, wg0 = wt*64;

    // zero all 4 plane slots once (halo rows + conv1's zero channels stay zero forever:
    // nothing dirties the planes anymore — no bounce)
    for (int i = tid; i < 4*PLANE_B/4; i += 256) ((u32*)smem)[i] = 0u;

    for (int i = tid; i < 27*256; i += 256) {
        int ic = i & 15, oc = (i >> 4) & 15, tap = i >> 8;
        float v = (ic < CIN) ? wts[(oc*CIN + ic)*27 + tap] : 0.f;
        *(u16*)(w_sm + (tap*16 + oc)*WROW_B + ic*2) = hfb(v);
    }
    __syncthreads();

    // stage: only writes data chunks of position-valid rows (others stay zero)
    auto stage = [&](int zd) {
        int slot = (zd - d0 + 1) & 3;
        bool pv = ((unsigned)zd < 24u);
        if (CIN == 8) {
            for (int it = tid; it < 396; it += 256) {
                int zhl = it / 66;
                int wl = it - zhl*66;
                int zh = h0 - 1 + zhl;
                int wgl = wg0 + wl - 1;
                if ((unsigned)zh >= 64u || (unsigned)wgl >= 128u) continue;
                u32 dst = a_base + slot*PLANE_B + (u32)it*ROW_B;
                const void* src = pv
                    ? (const void*)(g_cvp + ((((size_t)(b*24 + zd)*64 + zh)*128 + wgl)*16))
                    : (const void*)g_zerobuf;
                cp16(dst, src);
            }
        } else {
            for (int it = tid; it < 792; it += 256) {
                int ch = it & 1;
                int t2 = it >> 1;
                int zhl = t2 / 66;
                int wl = t2 - zhl*66;
                int zh = h0 - 1 + zhl;
                int wgl = wg0 + wl - 1;
                if ((unsigned)zh >= 64u || (unsigned)wgl >= 128u) continue;
                u32 dst = a_base + slot*PLANE_B + (u32)t2*ROW_B + ch*16;
                const void* src = pv
                    ? (const void*)(g_x1p + ((((size_t)(b*24 + zd)*64 + zh)*128 + wgl)*32 + ch*16))
                    : (const void*)g_zerobuf;
                cp16(dst, src);
            }
        }
    };

    float gsum[2] = {0.f, 0.f}, gss[2] = {0.f, 0.f};

    for (int pair = 0; pair < 3; pair++) {
        int d = d0 + 2*pair;
        if (pair == 0) {
            stage(d0 - 1); stage(d0); stage(d0 + 1); stage(d0 + 2);
        } else {
            stage(d + 1); stage(d + 2);
        }
        asm volatile("cp.async.commit_group;" ::: "memory");
        asm volatile("cp.async.wait_group 0;" ::: "memory");
        __syncthreads();

        float acc[2][2][2][4];
#pragma unroll
        for (int t = 0; t < 2; t++)
#pragma unroll
            for (int dd = 0; dd < 2; dd++)
#pragma unroll
                for (int oh = 0; oh < 2; oh++)
#pragma unroll
                    for (int r = 0; r < 4; r++) acc[t][dd][oh][r] = 0.f;

#pragma unroll
        for (int kh = 0; kh < 3; kh++) {
            int zhl = hl + kh;
#pragma unroll
            for (int kw = 0; kw < 3; kw++) {
                u32 bfr[3][4];
                int m = lane >> 3;
#pragma unroll
                for (int kd = 0; kd < 3; kd++) {
                    int tap = kd*9 + kh*3 + kw;
                    u32 ba = w_base + (u32)((tap*16 + (m >> 1)*8 + (lane & 7))*WROW_B + (m & 1)*16);
                    ldsm4(ba, bfr[kd][0], bfr[kd][1], bfr[kd][2], bfr[kd][3]);
                }
#pragma unroll
                for (int t = 0; t < 2; t++) {
                    int r = zhl*66 + wq*32 + t*16 + (lane & 15) + kw;
                    u32 rowoff = (u32)r*ROW_B + (lane >> 4)*16;
#pragma unroll
                    for (int q = 0; q < 4; q++) {
                        u32 pbase = a_base + (u32)((2*pair + q) & 3)*PLANE_B;
                        u32 a0, a1, a2, a3;
                        ldsm4(pbase + rowoff, a0, a1, a2, a3);
                        if (q <= 2) {
#pragma unroll
                            for (int oh = 0; oh < 2; oh++)
                                mma16816h(acc[t][0][oh], a0, a1, a2, a3, bfr[q][oh*2], bfr[q][oh*2+1]);
                        }
                        if (q >= 1) {
#pragma unroll
                            for (int oh = 0; oh < 2; oh++)
                                mma16816h(acc[t][1][oh], a0, a1, a2, a3, bfr[q-1][oh*2], bfr[q-1][oh*2+1]);
                        }
                    }
                }
            }
        }

        // stats + direct packed stores (no bounce, no extra syncs)
#pragma unroll
        for (int t = 0; t < 2; t++)
#pragma unroll
            for (int dd = 0; dd < 2; dd++) {
                size_t voxbase = ((((size_t)(b*24 + d + dd)*64 + h0 + hl)*128)
                                  + wg0 + wq*32 + t*16 + (lane >> 2))*32;
#pragma unroll
                for (int oh = 0; oh < 2; oh++) {
                    float s = 0.f, s2 = 0.f;
#pragma unroll
                    for (int r = 0; r < 4; r++) { float v = acc[t][dd][oh][r]; s += v; s2 += v*v; }
                    gsum[oh] += s; gss[oh] += s2;
                    u32 p0 = (u32)hfb(acc[t][dd][oh][0]) | ((u32)hfb(acc[t][dd][oh][1]) << 16);
                    u32 p1 = (u32)hfb(acc[t][dd][oh][2]) | ((u32)hfb(acc[t][dd][oh][3]) << 16);
                    u32 off = oh*16 + (lane & 3)*4;
                    *(u32*)(outu + voxbase + off)       = p0;
                    *(u32*)(outu + voxbase + 256 + off) = p1;   // px+8 -> +8 voxels
                }
            }
        __syncthreads();   // all warps done reading slots before next pair's staging
    }

    int g0 = lane & 3;
    atomicAdd(&sred[g0*2],         gsum[0]); atomicAdd(&sred[g0*2 + 1],         gss[0]);
    atomicAdd(&sred[(4 + g0)*2],   gsum[1]); atomicAdd(&sred[(4 + g0)*2 + 1],   gss[1]);
    __syncthreads();
    if (tid < 16) atomicAdd(&stats[b*16 + tid], (double)sred[tid]);
}

// ---------------- GN1 finalize + SiLU: packed -> packed (proven) ----------------
__global__ void __launch_bounds__(256) k_norm_pack(const float* __restrict__ gw,
                                                   const float* __restrict__ gb) {
    __shared__ float sA[16], sB[16];
    int x = blockIdx.x;
    int hq = x & 31, d = (x >> 5) % 24, b = x / 768;
    int tid = threadIdx.x;
    if (tid < 16) {
        const double* p = g_stats + ((size_t)b*8 + (tid >> 1))*2;
        double mu = p[0] / 393216.0;
        double var = p[1] / 393216.0 - mu*mu;
        float rstd = rsqrtf((float)var + 1e-5f);
        float A = rstd * gw[tid];
        sA[tid] = A; sB[tid] = gb[tid] - (float)mu*A;
    }
    __syncthreads();
    int w = tid & 127, h = hq*2 + (tid >> 7);
    size_t vox = (((size_t)(b*24 + d)*64 + h)*128 + w)*32;
    const uint4* src = (const uint4*)(g_x1u + vox);
    uint4 lo = src[0], hi = src[1];
    u32 in[8] = {lo.x, lo.y, lo.z, lo.w, hi.x, hi.y, hi.z, hi.w};
    u32 pw[8];
#pragma unroll
    for (int j = 0; j < 8; j++) {
        float v0 = fbh((u16)(in[j] & 0xFFFF));
        float v1 = fbh((u16)(in[j] >> 16));
        float t0 = v0*sA[2*j] + sB[2*j];
        float t1 = v1*sA[2*j + 1] + sB[2*j + 1];
        t0 = t0 / (1.f + __expf(-t0));
        t1 = t1 / (1.f + __expf(-t1));
        pw[j] = (u32)hfb(t0) | ((u32)hfb(t1) << 16);
    }
    uint4* dst = (uint4*)(g_x1p + vox);
    dst[0] = make_uint4(pw[0], pw[1], pw[2], pw[3]);
    dst[1] = make_uint4(pw[4], pw[5], pw[6], pw[7]);
}

// ---------------- GN2 finalize + SiLU: packed -> planar fp32 (proven) ----------------
__global__ void __launch_bounds__(256) k_norm2pl(const float* __restrict__ gw,
                                                 const float* __restrict__ gb) {
    __shared__ float sA[16], sB[16];
    int x = blockIdx.x;
    int hq = x & 31, d = (x >> 5) % 24, b = x / 768;
    int tid = threadIdx.x;
    if (tid < 16) {
        const double* p = g_stats + 128 + ((size_t)b*8 + (tid >> 1))*2;
        double mu = p[0] / 393216.0;
        double var = p[1] / 393216.0 - mu*mu;
        float rstd = rsqrtf((float)var + 1e-5f);
        float A = rstd * gw[tid];
        sA[tid] = A; sB[tid] = gb[tid] - (float)mu*A;
    }
    __syncthreads();
    int w = tid & 127, h = hq*2 + (tid >> 7);
    const uint4* src = (const uint4*)(g_x2u + (((size_t)(b*24 + d)*64 + h)*128 + w)*32);
    uint4 lo = src[0], hi = src[1];
    u32 in[8] = {lo.x, lo.y, lo.z, lo.w, hi.x, hi.y, hi.z, hi.w};
    float* outb = g_x2n + ((size_t)b*16*DD + d)*HW + h*WW + w;
#pragma unroll
    for (int j = 0; j < 8; j++) {
        float v0 = fbh((u16)(in[j] & 0xFFFF));
        float v1 = fbh((u16)(in[j] >> 16));
        float t0 = v0*sA[2*j] + sB[2*j];
        float t1 = v1*sA[2*j + 1] + sB[2*j + 1];
        t0 = t0 / (1.f + __expf(-t0));
        t1 = t1 / (1.f + __expf(-t1));
        outb[(size_t)(2*j)*DD*HW]     = t0;
        outb[(size_t)(2*j + 1)*DD*HW] = t1;
    }
}

// ---------------- GN finalize + apply + SiLU (feat head only, proven) ----------------
__global__ void __launch_bounds__(256) k_norm(float* outext,
                                              const float* __restrict__ gw,
                                              const float* __restrict__ gb) {
    const double* st = g_stats + 2*128;
    __shared__ float sA, sB;
    int x = blockIdx.x;
    int c = x & 15, b = x >> 4;
    if (threadIdx.x == 0) {
        const double* p = st + ((size_t)b*8 + (c >> 1))*2;
        double mu = p[0] / 16384.0;
        double var = p[1] / 16384.0 - mu*mu;
        float rstd = rsqrtf((float)var + 1e-5f);
        float A = rstd * gw[c];
        sA = A; sB = gb[c] - (float)mu * A;
    }
    __syncthreads();
    float A = sA, Bv = sB;
    size_t base = ((size_t)(b*16 + c))*8192;
    const float4* ip = (const float4*)(g_feat + base);
    float4* op = (float4*)(outext + base);
    for (int i = threadIdx.x; i < 2048; i += 256) {
        float4 v = ip[i];
        v.x = v.x*A + Bv; v.y = v.y*A + Bv; v.z = v.z*A + Bv; v.w = v.w*A + Bv;
        v.x = v.x / (1.f + __expf(-v.x));
        v.y = v.y / (1.f + __expf(-v.y));
        v.z = v.z / (1.f + __expf(-v.z));
        v.w = v.w / (1.f + __expf(-v.w));
        op[i] = v;
    }
}

// ---------------- conv3d oc=1 (FMA2, proven) ----------------
__global__ void __launch_bounds__(128) k_conv3d_oc1(const float* __restrict__ wts,
                                                    const float* __restrict__ bias) {
    __shared__ u64 swt[432];
    int tid = threadIdx.x;
    for (int i = tid; i < 432; i += 128) swt[i] = pk1(wts[i]);
    __syncthreads();
    int x = blockIdx.x;
    int ht = x & 7, d = (x >> 3) % 24, b = x / 192;
    int wt = tid & 15, hr = tid >> 4;
    int w0 = wt << 3, h = ht*8 + hr;
    u64 acc[4];
#pragma unroll
    for (int t = 0; t < 4; t++) acc[t] = 0ull;
    const float* inb = g_x2n + (size_t)b*16*DD*HW;
    for (int ic = 0; ic < 16; ic++) {
        const float* inc = inb + (size_t)ic*DD*HW;
#pragma unroll
        for (int kd = 0; kd < 3; kd++) {
            int zd = d + kd - 1;
            if ((unsigned)zd >= (unsigned)DD) continue;
#pragma unroll
            for (int kh = 0; kh < 3; kh++) {
                int zh = h + kh - 1;
                if ((unsigned)zh >= (unsigned)HH) continue;
                const float* row = inc + ((size_t)zd*HH + zh)*WW + w0;
                float r0 = (w0 == 0) ? 0.f : __ldg(row - 1);
                float4 va = *(const float4*)row;
                float4 vb = *(const float4*)(row + 4);
                float r9 = (w0 == 120) ? 0.f : __ldg(row + 8);
                u64 pe[5], po[4];
                pe[0] = pk(r0, va.x);  pe[1] = pk(va.y, va.z);
                pe[2] = pk(va.w, vb.x); pe[3] = pk(vb.y, vb.z);
                pe[4] = pk(vb.w, r9);
                po[0] = pk(va.x, va.y); po[1] = pk(va.z, va.w);
                po[2] = pk(vb.x, vb.y); po[3] = pk(vb.z, vb.w);
                int tb = (kd*3 + kh)*3;
                u64 wv0 = swt[ic*27 + tb + 0];
                u64 wv1 = swt[ic*27 + tb + 1];
                u64 wv2 = swt[ic*27 + tb + 2];
#pragma unroll
                for (int t = 0; t < 4; t++) {
                    fma2(acc[t], wv0, pe[t]);
                    fma2(acc[t], wv1, po[t]);
                    fma2(acc[t], wv2, pe[t + 1]);
                }
            }
        }
    }
    float bs = bias[0];
    float o[8];
#pragma unroll
    for (int t = 0; t < 4; t++) { float2 f = unpk(acc[t]); o[2*t] = f.x + bs; o[2*t+1] = f.y + bs; }
    float* orow = g_logits + (((size_t)b*DD + d)*HH + h)*WW + w0;
    *(float4*)orow       = make_float4(o[0], o[1], o[2], o[3]);
    *(float4*)(orow + 4) = make_float4(o[4], o[5], o[6], o[7]);
}

// ---------------- softmax (proven) ----------------
__global__ void __launch_bounds__(128) k_softmax(float* __restrict__ out) {
    int x = blockIdx.x;
    int h = x & 63, b = x >> 6;
    int w = threadIdx.x;
    const float* lp = g_logits + ((size_t)b*DD*HH + h)*WW + w;
    float l[DD];
    float m = -1e30f;
#pragma unroll
    for (int d = 0; d < DD; d++) { l[d] = lp[(size_t)d*HW]; m = fmaxf(m, l[d]); }
    float S = 0.f, E = 0.f;
#pragma unroll
    for (int d = 0; d < DD; d++) {
        float e = __expf(l[d] - m);
        S += e; E += e * (float)d;
    }
    float inv = 1.f / S;
    int oi = (b*HH + h)*WW + w;
    out[oi]           = E * inv;
    out[65536 + oi]   = 0.f;
    out[131072 + oi]  = 0.f;
    out[1245184 + oi] = inv;
}

// ================= feature head: fp16 mma conv2d (proven) =================
#define FROW_B  48
#define FPLANE  (264*FROW_B)
#define FW_OFF  FPLANE
#define FEAT_SMEM (FPLANE + 8*9*16*FROW_B)   // 67968 -> 3 CTAs/SM

__global__ void __launch_bounds__(256) k_feat_tc(const float* __restrict__ wts) {
    extern __shared__ char smem[];
    char* w_sm = smem + FW_OFF;
    __shared__ float sred[16];

    u32 a_base = smem_u32(smem);
    u32 w_base = smem_u32(w_sm);
    int tid = threadIdx.x, lane = tid & 31, wrp = tid >> 5;
    int hl = wrp >> 2, wq = wrp & 3, w0l = wq*16;
    if (tid < 16) sred[tid] = 0.f;

    int x = blockIdx.x;
    int wt = x & 1, hp = (x >> 1) & 31, b = x >> 6;
    int h0 = hp*2, wg0 = wt*64;

    for (int i = tid; i < 18432; i += 256) {
        int icl = i & 15;
        int rest = i >> 4;
        int oc = rest & 15;
        int tapc = rest >> 4;
        int c = tapc / 9, tap = tapc - c*9;
        float v = wts[((size_t)oc*128 + c*16 + icl)*9 + tap];
        *(u16*)(w_sm + (tapc*16 + oc)*FROW_B + icl*2) = hfb(v);
    }
    __syncthreads();

    float acc[2][4];
#pragma unroll
    for (int oh = 0; oh < 2; oh++)
#pragma unroll
        for (int r = 0; r < 4; r++) acc[oh][r] = 0.f;

    for (int c = 0; c < 8; c++) {
        for (int it = tid; it < 528; it += 256) {
            int ch = it & 1;
            int t2 = it >> 1;
            int zhl = t2 / 66;
            int wl = t2 - zhl*66;
            int zh = h0 - 1 + zhl;
            int wgl = wg0 + wl - 1;
            u32 dst = a_base + (u32)t2*FROW_B + ch*16;
            const void* src = ((unsigned)zh < 64u && (unsigned)wgl < 128u)
                ? (const void*)(g_fLp + (((size_t)b*64 + zh)*128 + wgl)*256 + c*32 + ch*16)
                : (const void*)g_zerobuf;
            cp16(dst, src);
        }
        asm volatile("cp.async.commit_group;" ::: "memory");
        asm volatile("cp.async.wait_group 0;" ::: "memory");
        __syncthreads();

#pragma unroll
        for (int kh = 0; kh < 3; kh++) {
            int zhl = hl + kh;
#pragma unroll
            for (int kw = 0; kw < 3; kw++) {
                int tapc = c*9 + kh*3 + kw;
                int m = lane >> 3;
                u32 bfr0, bfr1, bfr2, bfr3;
                u32 ba = w_base + (u32)((tapc*16 + (m >> 1)*8 + (lane & 7))*FROW_B + (m & 1)*16);
                ldsm4(ba, bfr0, bfr1, bfr2, bfr3);
                int r = zhl*66 + w0l + (lane & 15) + kw;
                u32 a0, a1, a2, a3;
                ldsm4(a_base + (u32)r*FROW_B + (lane >> 4)*16, a0, a1, a2, a3);
                mma16816h(acc[0], a0, a1, a2, a3, bfr0, bfr1);
                mma16816h(acc[1], a0, a1, a2, a3, bfr2, bfr3);
            }
        }
        __syncthreads();
    }

    float gsum[2], gss[2];
#pragma unroll
    for (int oh = 0; oh < 2; oh++) {
        float s = 0.f, s2 = 0.f;
#pragma unroll
        for (int r = 0; r < 4; r++) { float v = acc[oh][r]; s += v; s2 += v*v; }
        gsum[oh] = s; gss[oh] = s2;
    }

    float* bounce = (float*)smem;
#pragma unroll
    for (int oh = 0; oh < 2; oh++)
#pragma unroll
        for (int r = 0; r < 4; r++) {
            int oc = oh*8 + (lane & 3)*2 + (r & 1);
            int px = w0l + (lane >> 2) + (r >> 1)*8;
            bounce[oc*132 + hl*64 + px] = acc[oh][r];
        }
    __syncthreads();
    for (int i = tid; i < 512; i += 256) {
        int oc = i >> 5, rem = i & 31;
        int h2 = rem >> 4, w4 = rem & 15;
        float4 v = *(const float4*)&bounce[oc*132 + h2*64 + w4*4];
        *(float4*)&g_feat[((size_t)(b*16 + oc)*HH + h0 + h2)*WW + wg0 + w4*4] = v;
    }

    int g0 = lane & 3;
    atomicAdd(&sred[g0*2],         gsum[0]); atomicAdd(&sred[g0*2 + 1],         gss[0]);
    atomicAdd(&sred[(4 + g0)*2],   gsum[1]); atomicAdd(&sred[(4 + g0)*2 + 1],   gss[1]);
    __syncthreads();
    if (tid < 16) atomicAdd(&g_stats[2*128 + b*16 + tid], (double)sred[tid]);
}

// ---------------- launch ----------------
extern "C" void kernel_launch(void* const* d_in, const int* in_sizes, int n_in,
                              void* d_out, int out_size) {
    const float* fL    = (const float*)d_in[0];
    const float* fR    = (const float*)d_in[1];
    const float* w1    = (const float*)d_in[2];
    const float* gn1w  = (const float*)d_in[3];
    const float* gn1b  = (const float*)d_in[4];
    const float* w2    = (const float*)d_in[5];
    const float* gn2w  = (const float*)d_in[6];
    const float* gn2b  = (const float*)d_in[7];
    const float* w3    = (const float*)d_in[8];
    const float* b3    = (const float*)d_in[9];
    const float* fhw   = (const float*)d_in[10];
    const float* fhgnw = (const float*)d_in[11];
    const float* fhgnb = (const float*)d_in[12];
    float* out = (float*)d_out;

    cudaFuncSetAttribute(k_costvol,     cudaFuncAttributeMaxDynamicSharedMemorySize, 131072);
    cudaFuncSetAttribute(k_conv_tc<8>,  cudaFuncAttributeMaxDynamicSharedMemorySize, CONV_SMEM);
    cudaFuncSetAttribute(k_conv_tc<16>, cudaFuncAttributeMaxDynamicSharedMemorySize, CONV_SMEM);
    cudaFuncSetAttribute(k_feat_tc,     cudaFuncAttributeMaxDynamicSharedMemorySize, FEAT_SMEM);

    k_zero_stats<<<1, 384>>>();                                  // 0
    k_costvol<<<BATCH*HH, 256, 131072>>>(fL, fR);                // 1
    k_zero_stats<<<1, 384>>>();                                  // 2 (dummy)
    k_conv_tc<8><<<1024, 256, CONV_SMEM>>>(w1);                  // 3 <-- profiled
    k_norm_pack<<<BATCH*24*32, 256>>>(gn1w, gn1b);               // 4
    k_conv_tc<16><<<1024, 256, CONV_SMEM>>>(w2);                 // 5
    k_norm2pl<<<BATCH*24*32, 256>>>(gn2w, gn2b);                 // 6
    k_conv3d_oc1<<<BATCH*24*8, 128>>>(w3, b3);                   // 7
    k_softmax<<<BATCH*HH, 128>>>(out);                           // 8
    k_feat_tc<<<BATCH*32*2, 256, FEAT_SMEM>>>(fhw);              // 9
    k_norm<<<BATCH*16, 256>>>(out + 196608, fhgnw, fhgnb);       // 10
}